// round 1
// baseline (speedup 1.0000x reference)
#include <cuda_runtime.h>
#include <cuda_bf16.h>
#include <math.h>

// Problem constants
#define L   16384
#define E   131072
#define SP  20000
#define C   512
#define H   8
#define DH  64
#define HID 1024

// ---------------- scratch (device globals: allocation-free) ----------------
__device__ float g_z[(size_t)L * C];
__device__ float g_q[(size_t)L * C];
__device__ float g_k[(size_t)L * C];
__device__ float g_v[(size_t)L * C];
__device__ float g_score[(size_t)E * H];   // reused as pexp in-place
__device__ float g_m[(size_t)L * H];
__device__ float g_den[(size_t)L * H];
__device__ float g_agg[(size_t)L * C];
__device__ float g_x1[(size_t)L * C];
__device__ float g_z2[(size_t)L * C];
__device__ float g_hid[(size_t)L * HID];

// ---------------- helpers ----------------
__device__ __forceinline__ float gelu_tanh(float x) {
    const float k0 = 0.7978845608028654f;   // sqrt(2/pi)
    const float k1 = 0.044715f;
    float x3 = x * x * x;
    return 0.5f * x * (1.0f + tanhf(k0 * (x + k1 * x3)));
}

__device__ __forceinline__ void atomicMaxFloat(float* addr, float val) {
    int* ia = (int*)addr;
    int old = *ia;
    while (__int_as_float(old) < val) {
        int assumed = old;
        old = atomicCAS(ia, assumed, __float_as_int(val));
        if (old == assumed) break;
    }
}

// ---------------- LayerNorm: one block (128 thr) per row ----------------
__global__ void ln_kernel(const float* __restrict__ x,
                          const float* __restrict__ g,
                          const float* __restrict__ b,
                          float* __restrict__ z) {
    int row = blockIdx.x;
    int t = threadIdx.x;                 // 0..127
    const float* xr = x + (size_t)row * C;
    float4 v4 = *(const float4*)(xr + t * 4);
    float s  = v4.x + v4.y + v4.z + v4.w;
    float ss = v4.x * v4.x + v4.y * v4.y + v4.z * v4.z + v4.w * v4.w;
    #pragma unroll
    for (int o = 16; o > 0; o >>= 1) {
        s  += __shfl_xor_sync(0xffffffffu, s, o);
        ss += __shfl_xor_sync(0xffffffffu, ss, o);
    }
    __shared__ float sh[4], sh2[4];
    int w = t >> 5;
    if ((t & 31) == 0) { sh[w] = s; sh2[w] = ss; }
    __syncthreads();
    float sum  = sh[0] + sh[1] + sh[2] + sh[3];
    float sum2 = sh2[0] + sh2[1] + sh2[2] + sh2[3];
    float mean = sum * (1.0f / C);
    float var  = sum2 * (1.0f / C) - mean * mean;
    float inv  = rsqrtf(var + 1e-5f);
    float4 g4 = *(const float4*)(g + t * 4);
    float4 b4 = *(const float4*)(b + t * 4);
    float4 o4;
    o4.x = (v4.x - mean) * inv * g4.x + b4.x;
    o4.y = (v4.y - mean) * inv * g4.y + b4.y;
    o4.z = (v4.z - mean) * inv * g4.z + b4.z;
    o4.w = (v4.w - mean) * inv * g4.w + b4.w;
    *(float4*)(z + (size_t)row * C + t * 4) = o4;
}

// ---------------- SGEMM: C = A(MxK) @ B(KxN) + bias, epilogue variants ---
// EPI: 0 = bias only, 1 = bias+gelu, 2 = bias+residual
#define BM 128
#define BN 128
#define BK 16
#define TM 8
#define TN 8

template <int EPI>
__global__ __launch_bounds__(256, 2)
void sgemm_kernel(const float* __restrict__ A, const float* __restrict__ B,
                  const float* __restrict__ bias, const float* __restrict__ res,
                  float* __restrict__ Cmat, int M, int N, int K) {
    __shared__ float As[BK][BM];
    __shared__ float Bs[BK][BN];
    const int tid  = threadIdx.x;            // 256
    const int brow = blockIdx.y, bcol = blockIdx.x;
    const int tcol = tid & 15;               // 0..15
    const int trow = tid >> 4;                // 0..15

    float acc[TM][TN];
    #pragma unroll
    for (int i = 0; i < TM; i++)
        #pragma unroll
        for (int j = 0; j < TN; j++) acc[i][j] = 0.0f;

    const int aRow = tid >> 2;        // 0..63
    const int aCol = (tid & 3) * 4;   // 0,4,8,12
    const int bRow = tid >> 5;        // 0..7
    const int bCol = (tid & 31) * 4;  // 0..124

    const float* Ab = A + (size_t)(brow * BM) * K;
    const float* Bb = B + bcol * BN;

    for (int k0 = 0; k0 < K; k0 += BK) {
        #pragma unroll
        for (int p = 0; p < 2; p++) {
            int r = aRow + p * 64;
            float4 v4 = *(const float4*)(Ab + (size_t)r * K + k0 + aCol);
            As[aCol + 0][r] = v4.x;
            As[aCol + 1][r] = v4.y;
            As[aCol + 2][r] = v4.z;
            As[aCol + 3][r] = v4.w;
        }
        #pragma unroll
        for (int p = 0; p < 2; p++) {
            int r = bRow + p * 8;
            float4 v4 = *(const float4*)(Bb + (size_t)(k0 + r) * N + bCol);
            *(float4*)&Bs[r][bCol] = v4;
        }
        __syncthreads();
        #pragma unroll
        for (int kk = 0; kk < BK; kk++) {
            float regM[TM], regN[TN];
            *(float4*)&regM[0] = *(const float4*)&As[kk][trow * TM];
            *(float4*)&regM[4] = *(const float4*)&As[kk][trow * TM + 4];
            *(float4*)&regN[0] = *(const float4*)&Bs[kk][tcol * TN];
            *(float4*)&regN[4] = *(const float4*)&Bs[kk][tcol * TN + 4];
            #pragma unroll
            for (int i = 0; i < TM; i++)
                #pragma unroll
                for (int j = 0; j < TN; j++)
                    acc[i][j] += regM[i] * regN[j];
        }
        __syncthreads();
    }

    #pragma unroll
    for (int i = 0; i < TM; i++) {
        int row = brow * BM + trow * TM + i;
        #pragma unroll
        for (int j = 0; j < TN; j++) {
            int col = bcol * BN + tcol * TN + j;
            float v = acc[i][j] + bias[col];
            if (EPI == 1) v = gelu_tanh(v);
            if (EPI == 2) v += res[(size_t)row * N + col];
            Cmat[(size_t)row * N + col] = v;
        }
    }
}

// ---------------- init: agg=0, m=-inf, den=0 ----------------
__global__ void init_kernel(float* __restrict__ agg, float* __restrict__ m,
                            float* __restrict__ den) {
    int i = blockIdx.x * blockDim.x + threadIdx.x;
    if (i < L * C) agg[i] = 0.0f;
    if (i < L * H) { m[i] = -INFINITY; den[i] = 0.0f; }
}

// ---------------- edge score: one warp per edge ----------------
__global__ void edge_score_kernel(const float* __restrict__ q,
                                  const float* __restrict__ k,
                                  const int* __restrict__ row_index,
                                  const int* __restrict__ col_index,
                                  const float* __restrict__ pab,
                                  float* __restrict__ score) {
    int e = blockIdx.x * 8 + (threadIdx.x >> 5);
    int lane = threadIdx.x & 31;
    const float* qr = q + (size_t)row_index[e] * C;
    const float* kr = k + (size_t)col_index[e] * C;
    #pragma unroll
    for (int h = 0; h < H; h++) {
        float d0 = qr[h * DH + lane]      - kr[h * DH + lane];
        float d1 = qr[h * DH + 32 + lane] - kr[h * DH + 32 + lane];
        float s = d0 * d0 + d1 * d1;
        #pragma unroll
        for (int o = 16; o > 0; o >>= 1) s += __shfl_xor_sync(0xffffffffu, s, o);
        if (lane == 0)
            score[(size_t)e * H + h] = -s * 0.125f + pab[(size_t)e * H + h];
    }
}

// ---------------- segment max ----------------
__global__ void seg_max_kernel(const float* __restrict__ score,
                               const int* __restrict__ row_index,
                               float* __restrict__ m) {
    int idx = blockIdx.x * blockDim.x + threadIdx.x;   // E*H threads
    int e = idx >> 3, h = idx & 7;
    atomicMaxFloat(&m[(size_t)row_index[e] * H + h], score[idx]);
}

// ---------------- pexp + segment sum (in-place on score) ----------------
__global__ void pexp_kernel(float* __restrict__ score,
                            const int* __restrict__ row_index,
                            const float* __restrict__ m,
                            float* __restrict__ den) {
    int idx = blockIdx.x * blockDim.x + threadIdx.x;   // E*H
    int e = idx >> 3, h = idx & 7;
    int ri = row_index[e];
    float p = __expf(score[idx] - m[(size_t)ri * H + h]);
    score[idx] = p;
    atomicAdd(&den[(size_t)ri * H + h], p);
}

// ---------------- aggregate: one warp per edge, atomics into agg ----------
__global__ void edge_aggregate_kernel(const float* __restrict__ v,
                                      const float* __restrict__ pexp,
                                      const float* __restrict__ den,
                                      const int* __restrict__ row_index,
                                      const int* __restrict__ col_index,
                                      const int* __restrict__ to_col_index,
                                      const float* __restrict__ dist,
                                      const float* __restrict__ pos,
                                      const float* __restrict__ col_pos,
                                      const float* __restrict__ Wvec,
                                      const float* __restrict__ bvec,
                                      float* __restrict__ agg) {
    int e = blockIdx.x * 8 + (threadIdx.x >> 5);
    int lane = threadIdx.x & 31;
    int ri = row_index[e], ci = col_index[e], tci = to_col_index[e];
    float dinv = 1.0f / dist[e];
    float rx = (col_pos[tci * 3 + 0] - pos[ri * 3 + 0]) * dinv;
    float ry = (col_pos[tci * 3 + 1] - pos[ri * 3 + 1]) * dinv;
    float rz = (col_pos[tci * 3 + 2] - pos[ri * 3 + 2]) * dinv;
    float a = 0.0f;
    if (lane < H) {
        float d = den[(size_t)ri * H + lane];
        a = pexp[(size_t)e * H + lane] / (d == 0.0f ? 1.0f : d);
    }
    const float* vr = v + (size_t)ci * C;
    float* ar = agg + (size_t)ri * C;
    #pragma unroll
    for (int it = 0; it < C / 32; it++) {
        int c = it * 32 + lane;
        float alpha = __shfl_sync(0xffffffffu, a, it >> 1);  // h = c/64 = it/2
        float relw = rx * Wvec[c] + ry * Wvec[C + c] + rz * Wvec[2 * C + c] + bvec[c];
        atomicAdd(ar + c, alpha * (vr[c] + relw));
    }
}

// ---------------- launcher ----------------
extern "C" void kernel_launch(void* const* d_in, const int* in_sizes, int n_in,
                              void* d_out, int out_size) {
    const float* x        = (const float*)d_in[0];
    const int*   row_idx  = (const int*)  d_in[1];
    const int*   col_idx  = (const int*)  d_in[2];
    const int*   tcol_idx = (const int*)  d_in[3];
    // d_in[4] = att_bias (unused by reference)
    const float* pab      = (const float*)d_in[5];
    const float* dist     = (const float*)d_in[6];
    const float* pos      = (const float*)d_in[7];
    const float* col_pos  = (const float*)d_in[8];
    const float* ln1_g    = (const float*)d_in[9];
    const float* ln1_b    = (const float*)d_in[10];
    const float* ln2_g    = (const float*)d_in[11];
    const float* ln2_b    = (const float*)d_in[12];
    const float* Wq       = (const float*)d_in[13];
    const float* bq       = (const float*)d_in[14];
    const float* Wk       = (const float*)d_in[15];
    const float* bk       = (const float*)d_in[16];
    const float* Wv       = (const float*)d_in[17];
    const float* bv       = (const float*)d_in[18];
    const float* Wvec     = (const float*)d_in[19];
    const float* bvec     = (const float*)d_in[20];
    const float* Wo       = (const float*)d_in[21];
    const float* bo       = (const float*)d_in[22];
    const float* W1       = (const float*)d_in[23];
    const float* b1       = (const float*)d_in[24];
    const float* W2       = (const float*)d_in[25];
    const float* b2       = (const float*)d_in[26];
    float* out = (float*)d_out;

    static float *zp = nullptr, *qp, *kp, *vp, *scp, *mp, *denp, *aggp, *x1p, *z2p, *hidp;
    if (!zp) {
        cudaGetSymbolAddress((void**)&zp,   g_z);
        cudaGetSymbolAddress((void**)&qp,   g_q);
        cudaGetSymbolAddress((void**)&kp,   g_k);
        cudaGetSymbolAddress((void**)&vp,   g_v);
        cudaGetSymbolAddress((void**)&scp,  g_score);
        cudaGetSymbolAddress((void**)&mp,   g_m);
        cudaGetSymbolAddress((void**)&denp, g_den);
        cudaGetSymbolAddress((void**)&aggp, g_agg);
        cudaGetSymbolAddress((void**)&x1p,  g_x1);
        cudaGetSymbolAddress((void**)&z2p,  g_z2);
        cudaGetSymbolAddress((void**)&hidp, g_hid);
    }

    // 1. LN1
    ln_kernel<<<L, 128>>>(x, ln1_g, ln1_b, zp);

    // 2. q/k/v projections
    dim3 g512(C / BN, L / BM);      // (4,128)
    sgemm_kernel<0><<<g512, 256>>>(zp, Wq, bq, nullptr, qp, L, C, C);
    sgemm_kernel<0><<<g512, 256>>>(zp, Wk, bk, nullptr, kp, L, C, C);
    sgemm_kernel<0><<<g512, 256>>>(zp, Wv, bv, nullptr, vp, L, C, C);

    // 3. init softmax/agg buffers
    init_kernel<<<(L * C + 255) / 256, 256>>>(aggp, mp, denp);

    // 4. edge scores
    edge_score_kernel<<<E / 8, 256>>>(qp, kp, row_idx, col_idx, pab, scp);

    // 5. segment max
    seg_max_kernel<<<E * H / 256, 256>>>(scp, row_idx, mp);

    // 6. pexp + segment sum
    pexp_kernel<<<E * H / 256, 256>>>(scp, row_idx, mp, denp);

    // 7. weighted aggregation (incl. vec-feature add)
    edge_aggregate_kernel<<<E / 8, 256>>>(vp, scp, denp, row_idx, col_idx,
                                          tcol_idx, dist, pos, col_pos,
                                          Wvec, bvec, aggp);

    // 8. output projection + residual -> x1
    sgemm_kernel<2><<<g512, 256>>>(aggp, Wo, bo, x, x1p, L, C, C);

    // 9. LN2
    ln_kernel<<<L, 128>>>(x1p, ln2_g, ln2_b, z2p);

    // 10. FFN up + gelu
    dim3 g1024(HID / BN, L / BM);   // (8,128)
    sgemm_kernel<1><<<g1024, 256>>>(z2p, W1, b1, nullptr, hidp, L, HID, C);

    // 11. FFN down + residual -> out
    sgemm_kernel<2><<<g512, 256>>>(hidp, W2, b2, x1p, out, L, C, HID);
}

// round 2
// speedup vs baseline: 1.9562x; 1.9562x over previous
#include <cuda_runtime.h>
#include <cuda_bf16.h>
#include <math.h>
#include <stdint.h>

// Problem constants
#define L   16384
#define E   131072
#define SP  20000
#define C   512
#define H   8
#define DH  64
#define HID 1024

// ---------------- scratch (device globals: allocation-free) ----------------
__device__ float g_z[(size_t)L * C];
__device__ float g_q[(size_t)L * C];
__device__ float g_k[(size_t)L * C];
__device__ float g_v[(size_t)L * C];
__device__ float g_score[(size_t)E * H];   // reused as pexp in-place
__device__ float g_m[(size_t)L * H];
__device__ float g_den[(size_t)L * H];
__device__ float g_agg[(size_t)L * C];
__device__ float g_x1[(size_t)L * C];
__device__ float g_z2[(size_t)L * C];
__device__ float g_hid[(size_t)L * HID];

// ---------------- helpers ----------------
__device__ __forceinline__ float gelu_tanh(float x) {
    const float k0 = 0.7978845608028654f;   // sqrt(2/pi)
    const float k1 = 0.044715f;
    float x3 = x * x * x;
    return 0.5f * x * (1.0f + tanhf(k0 * (x + k1 * x3)));
}

__device__ __forceinline__ void atomicMaxFloat(float* addr, float val) {
    int* ia = (int*)addr;
    int old = *ia;
    while (__int_as_float(old) < val) {
        int assumed = old;
        old = atomicCAS(ia, assumed, __float_as_int(val));
        if (old == assumed) break;
    }
}

__device__ __forceinline__ uint32_t f2tf32(float f) {
    uint32_t r;
    asm("cvt.rna.tf32.f32 %0, %1;" : "=r"(r) : "f"(f));
    return r;
}

__device__ __forceinline__ void mma_tf32(float* d, const uint32_t* a,
                                         const uint32_t* b) {
    asm volatile(
        "mma.sync.aligned.m16n8k8.row.col.f32.tf32.tf32.f32 "
        "{%0,%1,%2,%3}, {%4,%5,%6,%7}, {%8,%9}, {%0,%1,%2,%3};\n"
        : "+f"(d[0]), "+f"(d[1]), "+f"(d[2]), "+f"(d[3])
        : "r"(a[0]), "r"(a[1]), "r"(a[2]), "r"(a[3]),
          "r"(b[0]), "r"(b[1]));
}

// ---------------- LayerNorm: one block (128 thr) per row ----------------
__global__ void ln_kernel(const float* __restrict__ x,
                          const float* __restrict__ g,
                          const float* __restrict__ b,
                          float* __restrict__ z) {
    int row = blockIdx.x;
    int t = threadIdx.x;                 // 0..127
    const float* xr = x + (size_t)row * C;
    float4 v4 = *(const float4*)(xr + t * 4);
    float s  = v4.x + v4.y + v4.z + v4.w;
    float ss = v4.x * v4.x + v4.y * v4.y + v4.z * v4.z + v4.w * v4.w;
    #pragma unroll
    for (int o = 16; o > 0; o >>= 1) {
        s  += __shfl_xor_sync(0xffffffffu, s, o);
        ss += __shfl_xor_sync(0xffffffffu, ss, o);
    }
    __shared__ float sh[4], sh2[4];
    int w = t >> 5;
    if ((t & 31) == 0) { sh[w] = s; sh2[w] = ss; }
    __syncthreads();
    float sum  = sh[0] + sh[1] + sh[2] + sh[3];
    float sum2 = sh2[0] + sh2[1] + sh2[2] + sh2[3];
    float mean = sum * (1.0f / C);
    float var  = sum2 * (1.0f / C) - mean * mean;
    float inv  = rsqrtf(var + 1e-5f);
    float4 g4 = *(const float4*)(g + t * 4);
    float4 b4 = *(const float4*)(b + t * 4);
    float4 o4;
    o4.x = (v4.x - mean) * inv * g4.x + b4.x;
    o4.y = (v4.y - mean) * inv * g4.y + b4.y;
    o4.z = (v4.z - mean) * inv * g4.z + b4.z;
    o4.w = (v4.w - mean) * inv * g4.w + b4.w;
    *(float4*)(z + (size_t)row * C + t * 4) = o4;
}

// ---------------- TF32 tensor-core GEMM ----------------
// C = A(MxK) @ B(KxN) + bias ; EPI: 0 bias, 1 bias+gelu, 2 bias+residual
#define BM  128
#define BN  128
#define BKK 16
#define PADW 20   // padded smem row width in words

template <int EPI>
__global__ __launch_bounds__(256, 1)
void tgemm_kernel(const float* __restrict__ A, const float* __restrict__ B,
                  const float* __restrict__ bias, const float* __restrict__ res,
                  float* __restrict__ Cmat, int M, int N, int K) {
    __shared__ uint32_t As[2][BM][PADW];   // [row][k]
    __shared__ uint32_t Bs[2][BN][PADW];   // [n][k] (transposed)

    const int tid    = threadIdx.x;
    const int lane   = tid & 31;
    const int wid    = tid >> 5;
    const int warp_m = wid & 3;            // 0..3 -> 32-row slice
    const int warp_n = wid >> 2;           // 0..1 -> 64-col slice
    const int grp    = lane >> 2;          // 0..7
    const int t4     = lane & 3;           // 0..3

    const int brow = blockIdx.y * BM;
    const int bcol = blockIdx.x * BN;

    float acc[2][8][4];
    #pragma unroll
    for (int i = 0; i < 2; i++)
        #pragma unroll
        for (int j = 0; j < 8; j++)
            #pragma unroll
            for (int c = 0; c < 4; c++) acc[i][j][c] = 0.0f;

    // A gmem mapping: thread covers rows arow0 and arow0+64, 4 cols at ac4
    const int arow0 = tid >> 2;            // 0..63
    const int ac4   = (tid & 3) * 4;       // 0,4,8,12
    const float* Ap0 = A + (size_t)(brow + arow0) * K + ac4;
    const float* Ap1 = A + (size_t)(brow + arow0 + 64) * K + ac4;
    // B gmem mapping: thread covers col bn, k rows bkh..bkh+7
    const int bn  = tid & 127;
    const int bkh = (tid >> 7) * 8;        // 0 or 8
    const float* Bp = B + (size_t)bkh * N + bcol + bn;

    const int nStages = K / BKK;

    float ar[8];
    float br[8];

    // ---- prologue: load stage 0 ----
    {
        float4 a0 = *(const float4*)(Ap0);
        float4 a1 = *(const float4*)(Ap1);
        ar[0] = a0.x; ar[1] = a0.y; ar[2] = a0.z; ar[3] = a0.w;
        ar[4] = a1.x; ar[5] = a1.y; ar[6] = a1.z; ar[7] = a1.w;
        #pragma unroll
        for (int j = 0; j < 8; j++) br[j] = Bp[(size_t)j * N];
    }
    {
        uint4 u0 = { f2tf32(ar[0]), f2tf32(ar[1]), f2tf32(ar[2]), f2tf32(ar[3]) };
        uint4 u1 = { f2tf32(ar[4]), f2tf32(ar[5]), f2tf32(ar[6]), f2tf32(ar[7]) };
        *(uint4*)&As[0][arow0][ac4]      = u0;
        *(uint4*)&As[0][arow0 + 64][ac4] = u1;
        uint4 v0 = { f2tf32(br[0]), f2tf32(br[1]), f2tf32(br[2]), f2tf32(br[3]) };
        uint4 v1 = { f2tf32(br[4]), f2tf32(br[5]), f2tf32(br[6]), f2tf32(br[7]) };
        *(uint4*)&Bs[0][bn][bkh]     = v0;
        *(uint4*)&Bs[0][bn][bkh + 4] = v1;
    }
    __syncthreads();

    for (int s = 0; s < nStages; s++) {
        const int buf = s & 1;
        const bool more = (s + 1 < nStages);
        if (more) {
            int k0 = (s + 1) * BKK;
            float4 a0 = *(const float4*)(Ap0 + k0);
            float4 a1 = *(const float4*)(Ap1 + k0);
            ar[0] = a0.x; ar[1] = a0.y; ar[2] = a0.z; ar[3] = a0.w;
            ar[4] = a1.x; ar[5] = a1.y; ar[6] = a1.z; ar[7] = a1.w;
            #pragma unroll
            for (int j = 0; j < 8; j++) br[j] = Bp[(size_t)(k0 + j) * N];
        }
        // ---- compute 2 k8 steps from smem[buf] ----
        #pragma unroll
        for (int ks = 0; ks < 2; ks++) {
            const int kb = ks * 8;
            uint32_t af[2][4];
            #pragma unroll
            for (int mt = 0; mt < 2; mt++) {
                int r = warp_m * 32 + mt * 16 + grp;
                af[mt][0] = As[buf][r][kb + t4];
                af[mt][1] = As[buf][r + 8][kb + t4];
                af[mt][2] = As[buf][r][kb + 4 + t4];
                af[mt][3] = As[buf][r + 8][kb + 4 + t4];
            }
            #pragma unroll
            for (int nt = 0; nt < 8; nt++) {
                int cidx = warp_n * 64 + nt * 8 + grp;
                uint32_t bf[2];
                bf[0] = Bs[buf][cidx][kb + t4];
                bf[1] = Bs[buf][cidx][kb + 4 + t4];
                mma_tf32(acc[0][nt], af[0], bf);
                mma_tf32(acc[1][nt], af[1], bf);
            }
        }
        if (more) {
            int nbuf = buf ^ 1;
            uint4 u0 = { f2tf32(ar[0]), f2tf32(ar[1]), f2tf32(ar[2]), f2tf32(ar[3]) };
            uint4 u1 = { f2tf32(ar[4]), f2tf32(ar[5]), f2tf32(ar[6]), f2tf32(ar[7]) };
            *(uint4*)&As[nbuf][arow0][ac4]      = u0;
            *(uint4*)&As[nbuf][arow0 + 64][ac4] = u1;
            uint4 v0 = { f2tf32(br[0]), f2tf32(br[1]), f2tf32(br[2]), f2tf32(br[3]) };
            uint4 v1 = { f2tf32(br[4]), f2tf32(br[5]), f2tf32(br[6]), f2tf32(br[7]) };
            *(uint4*)&Bs[nbuf][bn][bkh]     = v0;
            *(uint4*)&Bs[nbuf][bn][bkh + 4] = v1;
        }
        __syncthreads();
    }

    // ---- epilogue ----
    #pragma unroll
    for (int mt = 0; mt < 2; mt++) {
        int row = brow + warp_m * 32 + mt * 16 + grp;
        #pragma unroll
        for (int nt = 0; nt < 8; nt++) {
            int col = bcol + warp_n * 64 + nt * 8 + 2 * t4;
            float b0 = bias[col], b1 = bias[col + 1];
            float v0 = acc[mt][nt][0] + b0;
            float v1 = acc[mt][nt][1] + b1;
            float v2 = acc[mt][nt][2] + b0;
            float v3 = acc[mt][nt][3] + b1;
            if (EPI == 1) {
                v0 = gelu_tanh(v0); v1 = gelu_tanh(v1);
                v2 = gelu_tanh(v2); v3 = gelu_tanh(v3);
            }
            if (EPI == 2) {
                v0 += res[(size_t)row * N + col];
                v1 += res[(size_t)row * N + col + 1];
                v2 += res[(size_t)(row + 8) * N + col];
                v3 += res[(size_t)(row + 8) * N + col + 1];
            }
            float2 o0 = { v0, v1 };
            float2 o1 = { v2, v3 };
            *(float2*)&Cmat[(size_t)row * N + col]       = o0;
            *(float2*)&Cmat[(size_t)(row + 8) * N + col] = o1;
        }
    }
}

// ---------------- init: agg=0, m=-inf, den=0 ----------------
__global__ void init_kernel(float* __restrict__ agg, float* __restrict__ m,
                            float* __restrict__ den) {
    int i = blockIdx.x * blockDim.x + threadIdx.x;
    if (i < L * C) agg[i] = 0.0f;
    if (i < L * H) { m[i] = -INFINITY; den[i] = 0.0f; }
}

// ---------------- edge score: one warp per edge ----------------
__global__ void edge_score_kernel(const float* __restrict__ q,
                                  const float* __restrict__ k,
                                  const int* __restrict__ row_index,
                                  const int* __restrict__ col_index,
                                  const float* __restrict__ pab,
                                  float* __restrict__ score) {
    int e = blockIdx.x * 8 + (threadIdx.x >> 5);
    int lane = threadIdx.x & 31;
    const float* qr = q + (size_t)row_index[e] * C;
    const float* kr = k + (size_t)col_index[e] * C;
    #pragma unroll
    for (int h = 0; h < H; h++) {
        float d0 = qr[h * DH + lane]      - kr[h * DH + lane];
        float d1 = qr[h * DH + 32 + lane] - kr[h * DH + 32 + lane];
        float s = d0 * d0 + d1 * d1;
        #pragma unroll
        for (int o = 16; o > 0; o >>= 1) s += __shfl_xor_sync(0xffffffffu, s, o);
        if (lane == 0)
            score[(size_t)e * H + h] = -s * 0.125f + pab[(size_t)e * H + h];
    }
}

// ---------------- segment max ----------------
__global__ void seg_max_kernel(const float* __restrict__ score,
                               const int* __restrict__ row_index,
                               float* __restrict__ m) {
    int idx = blockIdx.x * blockDim.x + threadIdx.x;   // E*H threads
    int e = idx >> 3, h = idx & 7;
    atomicMaxFloat(&m[(size_t)row_index[e] * H + h], score[idx]);
}

// ---------------- pexp + segment sum (in-place on score) ----------------
__global__ void pexp_kernel(float* __restrict__ score,
                            const int* __restrict__ row_index,
                            const float* __restrict__ m,
                            float* __restrict__ den) {
    int idx = blockIdx.x * blockDim.x + threadIdx.x;   // E*H
    int e = idx >> 3, h = idx & 7;
    int ri = row_index[e];
    float p = __expf(score[idx] - m[(size_t)ri * H + h]);
    score[idx] = p;
    atomicAdd(&den[(size_t)ri * H + h], p);
}

// ---------------- aggregate: one warp per edge, atomics into agg ----------
__global__ void edge_aggregate_kernel(const float* __restrict__ v,
                                      const float* __restrict__ pexp,
                                      const float* __restrict__ den,
                                      const int* __restrict__ row_index,
                                      const int* __restrict__ col_index,
                                      const int* __restrict__ to_col_index,
                                      const float* __restrict__ dist,
                                      const float* __restrict__ pos,
                                      const float* __restrict__ col_pos,
                                      const float* __restrict__ Wvec,
                                      const float* __restrict__ bvec,
                                      float* __restrict__ agg) {
    int e = blockIdx.x * 8 + (threadIdx.x >> 5);
    int lane = threadIdx.x & 31;
    int ri = row_index[e], ci = col_index[e], tci = to_col_index[e];
    float dinv = 1.0f / dist[e];
    float rx = (col_pos[tci * 3 + 0] - pos[ri * 3 + 0]) * dinv;
    float ry = (col_pos[tci * 3 + 1] - pos[ri * 3 + 1]) * dinv;
    float rz = (col_pos[tci * 3 + 2] - pos[ri * 3 + 2]) * dinv;
    float a = 0.0f;
    if (lane < H) {
        float d = den[(size_t)ri * H + lane];
        a = pexp[(size_t)e * H + lane] / (d == 0.0f ? 1.0f : d);
    }
    const float* vr = v + (size_t)ci * C;
    float* ar = agg + (size_t)ri * C;
    #pragma unroll
    for (int it = 0; it < C / 32; it++) {
        int c = it * 32 + lane;
        float alpha = __shfl_sync(0xffffffffu, a, it >> 1);  // h = c/64 = it/2
        float relw = rx * Wvec[c] + ry * Wvec[C + c] + rz * Wvec[2 * C + c] + bvec[c];
        atomicAdd(ar + c, alpha * (vr[c] + relw));
    }
}

// ---------------- launcher ----------------
extern "C" void kernel_launch(void* const* d_in, const int* in_sizes, int n_in,
                              void* d_out, int out_size) {
    const float* x        = (const float*)d_in[0];
    const int*   row_idx  = (const int*)  d_in[1];
    const int*   col_idx  = (const int*)  d_in[2];
    const int*   tcol_idx = (const int*)  d_in[3];
    // d_in[4] = att_bias (unused by reference)
    const float* pab      = (const float*)d_in[5];
    const float* dist     = (const float*)d_in[6];
    const float* pos      = (const float*)d_in[7];
    const float* col_pos  = (const float*)d_in[8];
    const float* ln1_g    = (const float*)d_in[9];
    const float* ln1_b    = (const float*)d_in[10];
    const float* ln2_g    = (const float*)d_in[11];
    const float* ln2_b    = (const float*)d_in[12];
    const float* Wq       = (const float*)d_in[13];
    const float* bq       = (const float*)d_in[14];
    const float* Wk       = (const float*)d_in[15];
    const float* bk       = (const float*)d_in[16];
    const float* Wv       = (const float*)d_in[17];
    const float* bv       = (const float*)d_in[18];
    const float* Wvec     = (const float*)d_in[19];
    const float* bvec     = (const float*)d_in[20];
    const float* Wo       = (const float*)d_in[21];
    const float* bo       = (const float*)d_in[22];
    const float* W1       = (const float*)d_in[23];
    const float* b1       = (const float*)d_in[24];
    const float* W2       = (const float*)d_in[25];
    const float* b2       = (const float*)d_in[26];
    float* out = (float*)d_out;

    static float *zp = nullptr, *qp, *kp, *vp, *scp, *mp, *denp, *aggp, *x1p, *z2p, *hidp;
    if (!zp) {
        cudaGetSymbolAddress((void**)&zp,   g_z);
        cudaGetSymbolAddress((void**)&qp,   g_q);
        cudaGetSymbolAddress((void**)&kp,   g_k);
        cudaGetSymbolAddress((void**)&vp,   g_v);
        cudaGetSymbolAddress((void**)&scp,  g_score);
        cudaGetSymbolAddress((void**)&mp,   g_m);
        cudaGetSymbolAddress((void**)&denp, g_den);
        cudaGetSymbolAddress((void**)&aggp, g_agg);
        cudaGetSymbolAddress((void**)&x1p,  g_x1);
        cudaGetSymbolAddress((void**)&z2p,  g_z2);
        cudaGetSymbolAddress((void**)&hidp, g_hid);
    }

    // 1. LN1
    ln_kernel<<<L, 128>>>(x, ln1_g, ln1_b, zp);

    // 2. q/k/v projections (tf32 tensor cores)
    dim3 g512(C / BN, L / BM);      // (4,128)
    tgemm_kernel<0><<<g512, 256>>>(zp, Wq, bq, nullptr, qp, L, C, C);
    tgemm_kernel<0><<<g512, 256>>>(zp, Wk, bk, nullptr, kp, L, C, C);
    tgemm_kernel<0><<<g512, 256>>>(zp, Wv, bv, nullptr, vp, L, C, C);

    // 3. init softmax/agg buffers
    init_kernel<<<(L * C + 255) / 256, 256>>>(aggp, mp, denp);

    // 4. edge scores
    edge_score_kernel<<<E / 8, 256>>>(qp, kp, row_idx, col_idx, pab, scp);

    // 5. segment max
    seg_max_kernel<<<E * H / 256, 256>>>(scp, row_idx, mp);

    // 6. pexp + segment sum
    pexp_kernel<<<E * H / 256, 256>>>(scp, row_idx, mp, denp);

    // 7. weighted aggregation (incl. vec-feature add)
    edge_aggregate_kernel<<<E / 8, 256>>>(vp, scp, denp, row_idx, col_idx,
                                          tcol_idx, dist, pos, col_pos,
                                          Wvec, bvec, aggp);

    // 8. output projection + residual -> x1
    tgemm_kernel<2><<<g512, 256>>>(aggp, Wo, bo, x, x1p, L, C, C);

    // 9. LN2
    ln_kernel<<<L, 128>>>(x1p, ln2_g, ln2_b, z2p);

    // 10. FFN up + gelu
    dim3 g1024(HID / BN, L / BM);   // (8,128)
    tgemm_kernel<1><<<g1024, 256>>>(z2p, W1, b1, nullptr, hidp, L, HID, C);

    // 11. FFN down + residual -> out
    tgemm_kernel<2><<<g512, 256>>>(hidp, W2, b2, x1p, out, L, C, HID);
}

// round 3
// speedup vs baseline: 2.3299x; 1.1910x over previous
#include <cuda_runtime.h>
#include <cuda_bf16.h>
#include <math.h>
#include <stdint.h>

// Problem constants
#define L   16384
#define E   131072
#define SP  20000
#define C   512
#define H   8
#define DH  64
#define HID 1024

// ---------------- scratch (device globals: allocation-free) ----------------
__device__ float g_z[(size_t)L * C];
__device__ float g_q[(size_t)L * C];
__device__ float g_k[(size_t)L * C];
__device__ float g_v[(size_t)L * C];
__device__ float g_score[(size_t)E * H];   // reused as pexp in-place
__device__ float g_m[(size_t)L * H];
__device__ float g_den[(size_t)L * H];
__device__ float g_agg[(size_t)L * C];
__device__ float g_x1[(size_t)L * C];
__device__ float g_z2[(size_t)L * C];
__device__ float g_hid[(size_t)L * HID];
// rounded (tf32) weight copies
__device__ float g_wq[(size_t)C * C];
__device__ float g_wk[(size_t)C * C];
__device__ float g_wv[(size_t)C * C];
__device__ float g_wo[(size_t)C * C];
__device__ float g_w1[(size_t)C * HID];
__device__ float g_w2[(size_t)HID * C];

// ---------------- helpers ----------------
__device__ __forceinline__ float gelu_tanh(float x) {
    const float k0 = 0.7978845608028654f;
    const float k1 = 0.044715f;
    float x3 = x * x * x;
    return 0.5f * x * (1.0f + tanhf(k0 * (x + k1 * x3)));
}

__device__ __forceinline__ void atomicMaxFloat(float* addr, float val) {
    int* ia = (int*)addr;
    int old = *ia;
    while (__int_as_float(old) < val) {
        int assumed = old;
        old = atomicCAS(ia, assumed, __float_as_int(val));
        if (old == assumed) break;
    }
}

__device__ __forceinline__ float f2tf32f(float f) {
    uint32_t r;
    asm("cvt.rna.tf32.f32 %0, %1;" : "=r"(r) : "f"(f));
    return __uint_as_float(r);
}

__device__ __forceinline__ void mma_tf32(float* d, const uint32_t* a,
                                         const uint32_t* b) {
    asm volatile(
        "mma.sync.aligned.m16n8k8.row.col.f32.tf32.tf32.f32 "
        "{%0,%1,%2,%3}, {%4,%5,%6,%7}, {%8,%9}, {%0,%1,%2,%3};\n"
        : "+f"(d[0]), "+f"(d[1]), "+f"(d[2]), "+f"(d[3])
        : "r"(a[0]), "r"(a[1]), "r"(a[2]), "r"(a[3]),
          "r"(b[0]), "r"(b[1]));
}

__device__ __forceinline__ void cp16(uint32_t dst, const float* src) {
    asm volatile("cp.async.cg.shared.global [%0], [%1], 16;\n"
                 :: "r"(dst), "l"(src));
}
__device__ __forceinline__ void cp_commit() {
    asm volatile("cp.async.commit_group;\n");
}
template <int N>
__device__ __forceinline__ void cp_wait() {
    asm volatile("cp.async.wait_group %0;\n" :: "n"(N));
}
__device__ __forceinline__ uint32_t smem_u32(const void* p) {
    uint32_t a;
    asm("{ .reg .u64 t; cvta.to.shared.u64 t, %1; cvt.u32.u64 %0, t; }"
        : "=r"(a) : "l"(p));
    return a;
}

// ---------------- elementwise tf32 rounding ----------------
__global__ void round_copy_kernel(const float* __restrict__ src,
                                  float* __restrict__ dst, int n4) {
    int i = blockIdx.x * blockDim.x + threadIdx.x;
    if (i < n4) {
        float4 v = ((const float4*)src)[i];
        v.x = f2tf32f(v.x); v.y = f2tf32f(v.y);
        v.z = f2tf32f(v.z); v.w = f2tf32f(v.w);
        ((float4*)dst)[i] = v;
    }
}
__global__ void round_inplace_kernel(float* __restrict__ p, int n4) {
    int i = blockIdx.x * blockDim.x + threadIdx.x;
    if (i < n4) {
        float4 v = ((float4*)p)[i];
        v.x = f2tf32f(v.x); v.y = f2tf32f(v.y);
        v.z = f2tf32f(v.z); v.w = f2tf32f(v.w);
        ((float4*)p)[i] = v;
    }
}

// ---------------- LayerNorm (emits tf32-rounded output) ----------------
__global__ void ln_kernel(const float* __restrict__ x,
                          const float* __restrict__ g,
                          const float* __restrict__ b,
                          float* __restrict__ z) {
    int row = blockIdx.x;
    int t = threadIdx.x;                 // 0..127
    const float* xr = x + (size_t)row * C;
    float4 v4 = *(const float4*)(xr + t * 4);
    float s  = v4.x + v4.y + v4.z + v4.w;
    float ss = v4.x * v4.x + v4.y * v4.y + v4.z * v4.z + v4.w * v4.w;
    #pragma unroll
    for (int o = 16; o > 0; o >>= 1) {
        s  += __shfl_xor_sync(0xffffffffu, s, o);
        ss += __shfl_xor_sync(0xffffffffu, ss, o);
    }
    __shared__ float sh[4], sh2[4];
    int w = t >> 5;
    if ((t & 31) == 0) { sh[w] = s; sh2[w] = ss; }
    __syncthreads();
    float sum  = sh[0] + sh[1] + sh[2] + sh[3];
    float sum2 = sh2[0] + sh2[1] + sh2[2] + sh2[3];
    float mean = sum * (1.0f / C);
    float var  = sum2 * (1.0f / C) - mean * mean;
    float inv  = rsqrtf(var + 1e-5f);
    float4 g4 = *(const float4*)(g + t * 4);
    float4 b4 = *(const float4*)(b + t * 4);
    float4 o4;
    o4.x = f2tf32f((v4.x - mean) * inv * g4.x + b4.x);
    o4.y = f2tf32f((v4.y - mean) * inv * g4.y + b4.y);
    o4.z = f2tf32f((v4.z - mean) * inv * g4.z + b4.z);
    o4.w = f2tf32f((v4.w - mean) * inv * g4.w + b4.w);
    *(float4*)(z + (size_t)row * C + t * 4) = o4;
}

// ---------------- TF32 tensor-core GEMM, cp.async 3-stage pipeline -------
// C = A(MxK) @ B(KxN) + bias ; EPI: 0 bias, 1 bias+gelu(+tf32 round),
//                              2 bias+residual
#define BM  128
#define BN  128
#define BK  16
#define STAGES 3
#define AROW 20          // padded A row stride (words)
#define BROW 136         // padded B row stride (words)
#define AW  (BM * AROW)  // 2560 words per A stage
#define BW  (BK * BROW)  // 2176 words per B stage
#define SMEM_WORDS (STAGES * (AW + BW))   // 14208 words = 56832 B

template <int EPI>
__global__ __launch_bounds__(256, 1)
void tgemm_kernel(const float* __restrict__ A, const float* __restrict__ B,
                  const float* __restrict__ bias, const float* __restrict__ res,
                  float* __restrict__ Cmat, int M, int N, int K) {
    extern __shared__ float smemf[];
    float* As = smemf;
    float* Bs = smemf + STAGES * AW;

    const int tid    = threadIdx.x;
    const int lane   = tid & 31;
    const int wid    = tid >> 5;
    const int warp_m = wid & 3;
    const int warp_n = wid >> 2;
    const int grp    = lane >> 2;
    const int t4     = lane & 3;

    const int brow = blockIdx.y * BM;
    const int bcol = blockIdx.x * BN;

    float acc[2][8][4];
    #pragma unroll
    for (int i = 0; i < 2; i++)
        #pragma unroll
        for (int j = 0; j < 8; j++)
            #pragma unroll
            for (int c = 0; c < 4; c++) acc[i][j][c] = 0.0f;

    // loader mapping
    const int rA0 = tid >> 2;           // 0..63
    const int rA1 = rA0 + 64;
    const int chA = (tid & 3) * 4;      // 0,4,8,12
    const int kr0 = tid >> 5;           // 0..7
    const int kr1 = kr0 + 8;
    const int nch = (tid & 31) * 4;     // 0..124

    const float* Ap0 = A + (size_t)(brow + rA0) * K + chA;
    const float* Ap1 = A + (size_t)(brow + rA1) * K + chA;
    const float* Bp0 = B + (size_t)kr0 * N + bcol + nch;
    const float* Bp1 = B + (size_t)kr1 * N + bcol + nch;

    const uint32_t sA = smem_u32(As);
    const uint32_t sB = smem_u32(Bs);
    const uint32_t dA0 = sA + (uint32_t)(rA0 * AROW + chA) * 4;
    const uint32_t dA1 = sA + (uint32_t)(rA1 * AROW + chA) * 4;
    const uint32_t dB0 = sB + (uint32_t)(kr0 * BROW + nch) * 4;
    const uint32_t dB1 = sB + (uint32_t)(kr1 * BROW + nch) * 4;

    const int kIters = K / BK;

    // prologue: stages 0..STAGES-2
    #pragma unroll
    for (int s = 0; s < STAGES - 1; s++) {
        int k0 = s * BK;
        uint32_t so = (uint32_t)s;
        cp16(dA0 + so * AW * 4, Ap0 + k0);
        cp16(dA1 + so * AW * 4, Ap1 + k0);
        cp16(dB0 + so * BW * 4, Bp0 + (size_t)k0 * N);
        cp16(dB1 + so * BW * 4, Bp1 + (size_t)k0 * N);
        cp_commit();
    }

    int buf = 0;
    int nbuf = STAGES - 1;
    for (int s = 0; s < kIters; s++) {
        cp_wait<STAGES - 2>();
        __syncthreads();

        // issue stage s+STAGES-1
        if (s + STAGES - 1 < kIters) {
            int k0 = (s + STAGES - 1) * BK;
            uint32_t so = (uint32_t)nbuf;
            cp16(dA0 + so * AW * 4, Ap0 + k0);
            cp16(dA1 + so * AW * 4, Ap1 + k0);
            cp16(dB0 + so * BW * 4, Bp0 + (size_t)k0 * N);
            cp16(dB1 + so * BW * 4, Bp1 + (size_t)k0 * N);
        }
        cp_commit();

        // compute on buf
        const float* Ab = As + buf * AW;
        const float* Bb = Bs + buf * BW;
        #pragma unroll
        for (int ks = 0; ks < 2; ks++) {
            const int kb = ks * 8;
            uint32_t af[2][4];
            #pragma unroll
            for (int mt = 0; mt < 2; mt++) {
                int r = warp_m * 32 + mt * 16 + grp;
                af[mt][0] = __float_as_uint(Ab[r * AROW + kb + t4]);
                af[mt][1] = __float_as_uint(Ab[(r + 8) * AROW + kb + t4]);
                af[mt][2] = __float_as_uint(Ab[r * AROW + kb + 4 + t4]);
                af[mt][3] = __float_as_uint(Ab[(r + 8) * AROW + kb + 4 + t4]);
            }
            #pragma unroll
            for (int nt = 0; nt < 8; nt++) {
                int col = warp_n * 64 + nt * 8 + grp;
                uint32_t bf[2];
                bf[0] = __float_as_uint(Bb[(kb + t4) * BROW + col]);
                bf[1] = __float_as_uint(Bb[(kb + 4 + t4) * BROW + col]);
                mma_tf32(acc[0][nt], af[0], bf);
                mma_tf32(acc[1][nt], af[1], bf);
            }
        }
        buf = (buf + 1 == STAGES) ? 0 : buf + 1;
        nbuf = (nbuf + 1 == STAGES) ? 0 : nbuf + 1;
    }

    // ---- epilogue ----
    #pragma unroll
    for (int mt = 0; mt < 2; mt++) {
        int row = brow + warp_m * 32 + mt * 16 + grp;
        #pragma unroll
        for (int nt = 0; nt < 8; nt++) {
            int col = bcol + warp_n * 64 + nt * 8 + 2 * t4;
            float b0 = bias[col], b1 = bias[col + 1];
            float v0 = acc[mt][nt][0] + b0;
            float v1 = acc[mt][nt][1] + b1;
            float v2 = acc[mt][nt][2] + b0;
            float v3 = acc[mt][nt][3] + b1;
            if (EPI == 1) {
                v0 = f2tf32f(gelu_tanh(v0)); v1 = f2tf32f(gelu_tanh(v1));
                v2 = f2tf32f(gelu_tanh(v2)); v3 = f2tf32f(gelu_tanh(v3));
            }
            if (EPI == 2) {
                v0 += res[(size_t)row * N + col];
                v1 += res[(size_t)row * N + col + 1];
                v2 += res[(size_t)(row + 8) * N + col];
                v3 += res[(size_t)(row + 8) * N + col + 1];
            }
            float2 o0 = { v0, v1 };
            float2 o1 = { v2, v3 };
            *(float2*)&Cmat[(size_t)row * N + col]       = o0;
            *(float2*)&Cmat[(size_t)(row + 8) * N + col] = o1;
        }
    }
}

// ---------------- init: agg=0, m=-inf, den=0 ----------------
__global__ void init_kernel(float* __restrict__ agg, float* __restrict__ m,
                            float* __restrict__ den) {
    int i = blockIdx.x * blockDim.x + threadIdx.x;
    if (i < L * C) agg[i] = 0.0f;
    if (i < L * H) { m[i] = -INFINITY; den[i] = 0.0f; }
}

// ---------------- edge score: one warp per edge ----------------
__global__ void edge_score_kernel(const float* __restrict__ q,
                                  const float* __restrict__ k,
                                  const int* __restrict__ row_index,
                                  const int* __restrict__ col_index,
                                  const float* __restrict__ pab,
                                  float* __restrict__ score) {
    int e = blockIdx.x * 8 + (threadIdx.x >> 5);
    int lane = threadIdx.x & 31;
    const float* qr = q + (size_t)row_index[e] * C;
    const float* kr = k + (size_t)col_index[e] * C;
    #pragma unroll
    for (int h = 0; h < H; h++) {
        float d0 = qr[h * DH + lane]      - kr[h * DH + lane];
        float d1 = qr[h * DH + 32 + lane] - kr[h * DH + 32 + lane];
        float s = d0 * d0 + d1 * d1;
        #pragma unroll
        for (int o = 16; o > 0; o >>= 1) s += __shfl_xor_sync(0xffffffffu, s, o);
        if (lane == 0)
            score[(size_t)e * H + h] = -s * 0.125f + pab[(size_t)e * H + h];
    }
}

// ---------------- segment max ----------------
__global__ void seg_max_kernel(const float* __restrict__ score,
                               const int* __restrict__ row_index,
                               float* __restrict__ m) {
    int idx = blockIdx.x * blockDim.x + threadIdx.x;   // E*H threads
    int e = idx >> 3, h = idx & 7;
    atomicMaxFloat(&m[(size_t)row_index[e] * H + h], score[idx]);
}

// ---------------- pexp + segment sum (in-place on score) ----------------
__global__ void pexp_kernel(float* __restrict__ score,
                            const int* __restrict__ row_index,
                            const float* __restrict__ m,
                            float* __restrict__ den) {
    int idx = blockIdx.x * blockDim.x + threadIdx.x;   // E*H
    int e = idx >> 3, h = idx & 7;
    int ri = row_index[e];
    float p = __expf(score[idx] - m[(size_t)ri * H + h]);
    score[idx] = p;
    atomicAdd(&den[(size_t)ri * H + h], p);
}

// ---------------- aggregate: one warp per edge, atomics into agg ----------
__global__ void edge_aggregate_kernel(const float* __restrict__ v,
                                      const float* __restrict__ pexp,
                                      const float* __restrict__ den,
                                      const int* __restrict__ row_index,
                                      const int* __restrict__ col_index,
                                      const int* __restrict__ to_col_index,
                                      const float* __restrict__ dist,
                                      const float* __restrict__ pos,
                                      const float* __restrict__ col_pos,
                                      const float* __restrict__ Wvec,
                                      const float* __restrict__ bvec,
                                      float* __restrict__ agg) {
    int e = blockIdx.x * 8 + (threadIdx.x >> 5);
    int lane = threadIdx.x & 31;
    int ri = row_index[e], ci = col_index[e], tci = to_col_index[e];
    float dinv = 1.0f / dist[e];
    float rx = (col_pos[tci * 3 + 0] - pos[ri * 3 + 0]) * dinv;
    float ry = (col_pos[tci * 3 + 1] - pos[ri * 3 + 1]) * dinv;
    float rz = (col_pos[tci * 3 + 2] - pos[ri * 3 + 2]) * dinv;
    float a = 0.0f;
    if (lane < H) {
        float d = den[(size_t)ri * H + lane];
        a = pexp[(size_t)e * H + lane] / (d == 0.0f ? 1.0f : d);
    }
    const float* vr = v + (size_t)ci * C;
    float* ar = agg + (size_t)ri * C;
    #pragma unroll
    for (int it = 0; it < C / 32; it++) {
        int c = it * 32 + lane;
        float alpha = __shfl_sync(0xffffffffu, a, it >> 1);  // h = c/64 = it/2
        float relw = rx * Wvec[c] + ry * Wvec[C + c] + rz * Wvec[2 * C + c] + bvec[c];
        atomicAdd(ar + c, alpha * (vr[c] + relw));
    }
}

// ---------------- launcher ----------------
extern "C" void kernel_launch(void* const* d_in, const int* in_sizes, int n_in,
                              void* d_out, int out_size) {
    const float* x        = (const float*)d_in[0];
    const int*   row_idx  = (const int*)  d_in[1];
    const int*   col_idx  = (const int*)  d_in[2];
    const int*   tcol_idx = (const int*)  d_in[3];
    // d_in[4] = att_bias (unused by reference)
    const float* pab      = (const float*)d_in[5];
    const float* dist     = (const float*)d_in[6];
    const float* pos      = (const float*)d_in[7];
    const float* col_pos  = (const float*)d_in[8];
    const float* ln1_g    = (const float*)d_in[9];
    const float* ln1_b    = (const float*)d_in[10];
    const float* ln2_g    = (const float*)d_in[11];
    const float* ln2_b    = (const float*)d_in[12];
    const float* Wq       = (const float*)d_in[13];
    const float* bq       = (const float*)d_in[14];
    const float* Wk       = (const float*)d_in[15];
    const float* bk       = (const float*)d_in[16];
    const float* Wv       = (const float*)d_in[17];
    const float* bv       = (const float*)d_in[18];
    const float* Wvec     = (const float*)d_in[19];
    const float* bvec     = (const float*)d_in[20];
    const float* Wo       = (const float*)d_in[21];
    const float* bo       = (const float*)d_in[22];
    const float* W1       = (const float*)d_in[23];
    const float* b1       = (const float*)d_in[24];
    const float* W2       = (const float*)d_in[25];
    const float* b2       = (const float*)d_in[26];
    float* out = (float*)d_out;

    static float *zp = nullptr, *qp, *kp, *vp, *scp, *mp, *denp, *aggp,
                 *x1p, *z2p, *hidp, *wqp, *wkp, *wvp, *wop, *w1p, *w2p;
    if (!zp) {
        cudaGetSymbolAddress((void**)&zp,   g_z);
        cudaGetSymbolAddress((void**)&qp,   g_q);
        cudaGetSymbolAddress((void**)&kp,   g_k);
        cudaGetSymbolAddress((void**)&vp,   g_v);
        cudaGetSymbolAddress((void**)&scp,  g_score);
        cudaGetSymbolAddress((void**)&mp,   g_m);
        cudaGetSymbolAddress((void**)&denp, g_den);
        cudaGetSymbolAddress((void**)&aggp, g_agg);
        cudaGetSymbolAddress((void**)&x1p,  g_x1);
        cudaGetSymbolAddress((void**)&z2p,  g_z2);
        cudaGetSymbolAddress((void**)&hidp, g_hid);
        cudaGetSymbolAddress((void**)&wqp,  g_wq);
        cudaGetSymbolAddress((void**)&wkp,  g_wk);
        cudaGetSymbolAddress((void**)&wvp,  g_wv);
        cudaGetSymbolAddress((void**)&wop,  g_wo);
        cudaGetSymbolAddress((void**)&w1p,  g_w1);
        cudaGetSymbolAddress((void**)&w2p,  g_w2);
        const int smem_bytes = SMEM_WORDS * 4;
        cudaFuncSetAttribute(tgemm_kernel<0>,
            cudaFuncAttributeMaxDynamicSharedMemorySize, smem_bytes);
        cudaFuncSetAttribute(tgemm_kernel<1>,
            cudaFuncAttributeMaxDynamicSharedMemorySize, smem_bytes);
        cudaFuncSetAttribute(tgemm_kernel<2>,
            cudaFuncAttributeMaxDynamicSharedMemorySize, smem_bytes);
    }
    const int SMEM_B = SMEM_WORDS * 4;

    // 0. round weights to tf32 once per launch
    round_copy_kernel<<<(C * C / 4 + 255) / 256, 256>>>(Wq, wqp, C * C / 4);
    round_copy_kernel<<<(C * C / 4 + 255) / 256, 256>>>(Wk, wkp, C * C / 4);
    round_copy_kernel<<<(C * C / 4 + 255) / 256, 256>>>(Wv, wvp, C * C / 4);
    round_copy_kernel<<<(C * C / 4 + 255) / 256, 256>>>(Wo, wop, C * C / 4);
    round_copy_kernel<<<(C * HID / 4 + 255) / 256, 256>>>(W1, w1p, C * HID / 4);
    round_copy_kernel<<<(C * HID / 4 + 255) / 256, 256>>>(W2, w2p, C * HID / 4);

    // 1. LN1 (tf32-rounded output)
    ln_kernel<<<L, 128>>>(x, ln1_g, ln1_b, zp);

    // 2. q/k/v projections (tf32 tensor cores, cp.async pipeline)
    dim3 g512(C / BN, L / BM);      // (4,128)
    tgemm_kernel<0><<<g512, 256, SMEM_B>>>(zp, wqp, bq, nullptr, qp, L, C, C);
    tgemm_kernel<0><<<g512, 256, SMEM_B>>>(zp, wkp, bk, nullptr, kp, L, C, C);
    tgemm_kernel<0><<<g512, 256, SMEM_B>>>(zp, wvp, bv, nullptr, vp, L, C, C);

    // 3. init softmax/agg buffers
    init_kernel<<<(L * C + 255) / 256, 256>>>(aggp, mp, denp);

    // 4. edge scores
    edge_score_kernel<<<E / 8, 256>>>(qp, kp, row_idx, col_idx, pab, scp);

    // 5. segment max
    seg_max_kernel<<<E * H / 256, 256>>>(scp, row_idx, mp);

    // 6. pexp + segment sum
    pexp_kernel<<<E * H / 256, 256>>>(scp, row_idx, mp, denp);

    // 7. weighted aggregation (incl. vec-feature add)
    edge_aggregate_kernel<<<E / 8, 256>>>(vp, scp, denp, row_idx, col_idx,
                                          tcol_idx, dist, pos, col_pos,
                                          Wvec, bvec, aggp);

    // 7b. round agg to tf32 (it feeds the Wo GEMM only)
    round_inplace_kernel<<<(L * C / 4 + 255) / 256, 256>>>(aggp, L * C / 4);

    // 8. output projection + residual -> x1
    tgemm_kernel<2><<<g512, 256, SMEM_B>>>(aggp, wop, bo, x, x1p, L, C, C);

    // 9. LN2 (tf32-rounded output)
    ln_kernel<<<L, 128>>>(x1p, ln2_g, ln2_b, z2p);

    // 10. FFN up + gelu (output tf32-rounded in epilogue)
    dim3 g1024(HID / BN, L / BM);   // (8,128)
    tgemm_kernel<1><<<g1024, 256, SMEM_B>>>(z2p, w1p, b1, nullptr, hidp, L, HID, C);

    // 11. FFN down + residual -> out
    tgemm_kernel<2><<<g512, 256, SMEM_B>>>(hidp, w2p, b2, x1p, out, L, C, HID);
}

// round 4
// speedup vs baseline: 2.7334x; 1.1732x over previous
#include <cuda_runtime.h>
#include <cuda_bf16.h>
#include <math.h>
#include <stdint.h>

// Problem constants
#define L   16384
#define E   131072
#define SP  20000
#define C   512
#define H   8
#define DH  64
#define HID 1024
#define NQKV 1536

// ---------------- scratch (device globals: allocation-free) ----------------
__device__ float g_z[(size_t)L * C];
__device__ float g_qkv[(size_t)L * NQKV];   // [q|k|v] per row
__device__ float g_score[(size_t)E * H];
__device__ float g_agg[(size_t)L * C];
__device__ float g_x1[(size_t)L * C];
__device__ float g_z2[(size_t)L * C];
__device__ float g_hid[(size_t)L * HID];
// rounded (tf32) weights
__device__ float g_wqkv[(size_t)C * NQKV];
__device__ float g_bqkv[NQKV];
__device__ float g_wo[(size_t)C * C];
__device__ float g_w1[(size_t)C * HID];
__device__ float g_w2[(size_t)HID * C];
// CSR
__device__ int g_cnt[L];
__device__ int g_off[L + 1];
__device__ int g_cur[L];
__device__ int g_eid[E];

// ---------------- helpers ----------------
__device__ __forceinline__ float gelu_tanh(float x) {
    const float k0 = 0.7978845608028654f;
    const float k1 = 0.044715f;
    float x3 = x * x * x;
    return 0.5f * x * (1.0f + tanhf(k0 * (x + k1 * x3)));
}

__device__ __forceinline__ float f2tf32f(float f) {
    uint32_t r;
    asm("cvt.rna.tf32.f32 %0, %1;" : "=r"(r) : "f"(f));
    return __uint_as_float(r);
}

__device__ __forceinline__ void mma_tf32(float* d, const uint32_t* a,
                                         const uint32_t* b) {
    asm volatile(
        "mma.sync.aligned.m16n8k8.row.col.f32.tf32.tf32.f32 "
        "{%0,%1,%2,%3}, {%4,%5,%6,%7}, {%8,%9}, {%0,%1,%2,%3};\n"
        : "+f"(d[0]), "+f"(d[1]), "+f"(d[2]), "+f"(d[3])
        : "r"(a[0]), "r"(a[1]), "r"(a[2]), "r"(a[3]),
          "r"(b[0]), "r"(b[1]));
}

__device__ __forceinline__ void cp16(uint32_t dst, const float* src) {
    asm volatile("cp.async.cg.shared.global [%0], [%1], 16;\n"
                 :: "r"(dst), "l"(src));
}
__device__ __forceinline__ void cp_commit() {
    asm volatile("cp.async.commit_group;\n");
}
template <int N>
__device__ __forceinline__ void cp_wait() {
    asm volatile("cp.async.wait_group %0;\n" :: "n"(N));
}
__device__ __forceinline__ uint32_t smem_u32(const void* p) {
    uint32_t a;
    asm("{ .reg .u64 t; cvta.to.shared.u64 t, %1; cvt.u32.u64 %0, t; }"
        : "=r"(a) : "l"(p));
    return a;
}

// ---------------- weight prep ----------------
__global__ void pack_qkv_kernel(const float* __restrict__ Wq,
                                const float* __restrict__ Wk,
                                const float* __restrict__ Wv,
                                const float* __restrict__ bq,
                                const float* __restrict__ bk,
                                const float* __restrict__ bv,
                                float* __restrict__ W, float* __restrict__ b) {
    int idx = blockIdx.x * blockDim.x + threadIdx.x;   // C*C
    if (idx < C * C) {
        int k = idx / C, j = idx % C;
        W[(size_t)k * NQKV + j]            = f2tf32f(Wq[idx]);
        W[(size_t)k * NQKV + C + j]        = f2tf32f(Wk[idx]);
        W[(size_t)k * NQKV + 2 * C + j]    = f2tf32f(Wv[idx]);
    }
    if (idx < C) {
        b[idx]         = bq[idx];
        b[C + idx]     = bk[idx];
        b[2 * C + idx] = bv[idx];
    }
}

__global__ void round_copy_kernel(const float* __restrict__ src,
                                  float* __restrict__ dst, int n4) {
    int i = blockIdx.x * blockDim.x + threadIdx.x;
    if (i < n4) {
        float4 v = ((const float4*)src)[i];
        v.x = f2tf32f(v.x); v.y = f2tf32f(v.y);
        v.z = f2tf32f(v.z); v.w = f2tf32f(v.w);
        ((float4*)dst)[i] = v;
    }
}

// ---------------- LayerNorm (tf32-rounded output) ----------------
__global__ void ln_kernel(const float* __restrict__ x,
                          const float* __restrict__ g,
                          const float* __restrict__ b,
                          float* __restrict__ z) {
    int row = blockIdx.x;
    int t = threadIdx.x;                 // 0..127
    const float* xr = x + (size_t)row * C;
    float4 v4 = *(const float4*)(xr + t * 4);
    float s  = v4.x + v4.y + v4.z + v4.w;
    float ss = v4.x * v4.x + v4.y * v4.y + v4.z * v4.z + v4.w * v4.w;
    #pragma unroll
    for (int o = 16; o > 0; o >>= 1) {
        s  += __shfl_xor_sync(0xffffffffu, s, o);
        ss += __shfl_xor_sync(0xffffffffu, ss, o);
    }
    __shared__ float sh[4], sh2[4];
    int w = t >> 5;
    if ((t & 31) == 0) { sh[w] = s; sh2[w] = ss; }
    __syncthreads();
    float sum  = sh[0] + sh[1] + sh[2] + sh[3];
    float sum2 = sh2[0] + sh2[1] + sh2[2] + sh2[3];
    float mean = sum * (1.0f / C);
    float var  = sum2 * (1.0f / C) - mean * mean;
    float inv  = rsqrtf(var + 1e-5f);
    float4 g4 = *(const float4*)(g + t * 4);
    float4 b4 = *(const float4*)(b + t * 4);
    float4 o4;
    o4.x = f2tf32f((v4.x - mean) * inv * g4.x + b4.x);
    o4.y = f2tf32f((v4.y - mean) * inv * g4.y + b4.y);
    o4.z = f2tf32f((v4.z - mean) * inv * g4.z + b4.z);
    o4.w = f2tf32f((v4.w - mean) * inv * g4.w + b4.w);
    *(float4*)(z + (size_t)row * C + t * 4) = o4;
}

// ---------------- TF32 tensor-core GEMM, BK=32, 3-stage cp.async ----------
#define BM  128
#define BN  128
#define BK  32
#define STAGES 3
#define AROW 36
#define BROW 136
#define AW  (BM * AROW)   // 4608 words / stage
#define BW  (BK * BROW)   // 4352 words / stage
#define SMEM_WORDS (STAGES * (AW + BW))   // 26880 w = 107520 B

template <int EPI>
__global__ __launch_bounds__(256, 1)
void tgemm_kernel(const float* __restrict__ A, const float* __restrict__ B,
                  const float* __restrict__ bias, const float* __restrict__ res,
                  float* __restrict__ Cmat, int M, int N, int K) {
    extern __shared__ float smemf[];
    float* As = smemf;
    float* Bs = smemf + STAGES * AW;

    const int tid    = threadIdx.x;
    const int lane   = tid & 31;
    const int wid    = tid >> 5;
    const int warp_m = wid & 3;
    const int warp_n = wid >> 2;
    const int grp    = lane >> 2;
    const int t4     = lane & 3;

    const int brow = blockIdx.y * BM;
    const int bcol = blockIdx.x * BN;

    float acc[2][8][4];
    #pragma unroll
    for (int i = 0; i < 2; i++)
        #pragma unroll
        for (int j = 0; j < 8; j++)
            #pragma unroll
            for (int c = 0; c < 4; c++) acc[i][j][c] = 0.0f;

    // loader mapping: A 128x32/stage -> 4 cp16/thread; B 32x128 -> 4
    const int rA  = tid >> 3;            // 0..31
    const int chA = (tid & 7) * 4;       // 0..28
    const int kB  = tid >> 5;            // 0..7
    const int nch = (tid & 31) * 4;      // 0..124

    const float* A0 = A + (size_t)(brow + rA) * K + chA;
    const float* B0 = B + (size_t)kB * N + bcol + nch;

    const uint32_t sA = smem_u32(As);
    const uint32_t sB = smem_u32(Bs);
    const uint32_t dA = sA + (uint32_t)(rA * AROW + chA) * 4;
    const uint32_t dB = sB + (uint32_t)(kB * BROW + nch) * 4;

    const int kIters = K / BK;

    // prologue
    #pragma unroll
    for (int s = 0; s < STAGES - 1; s++) {
        int k0 = s * BK;
        #pragma unroll
        for (int p = 0; p < 4; p++)
            cp16(dA + (uint32_t)(s * AW + p * 32 * AROW) * 4,
                 A0 + (size_t)p * 32 * K + k0);
        #pragma unroll
        for (int p = 0; p < 4; p++)
            cp16(dB + (uint32_t)(s * BW + p * 8 * BROW) * 4,
                 B0 + (size_t)(k0 + p * 8) * N);
        cp_commit();
    }

    int buf = 0;
    int nbuf = STAGES - 1;
    for (int s = 0; s < kIters; s++) {
        cp_wait<STAGES - 2>();
        __syncthreads();

        if (s + STAGES - 1 < kIters) {
            int k0 = (s + STAGES - 1) * BK;
            #pragma unroll
            for (int p = 0; p < 4; p++)
                cp16(dA + (uint32_t)(nbuf * AW + p * 32 * AROW) * 4,
                     A0 + (size_t)p * 32 * K + k0);
            #pragma unroll
            for (int p = 0; p < 4; p++)
                cp16(dB + (uint32_t)(nbuf * BW + p * 8 * BROW) * 4,
                     B0 + (size_t)(k0 + p * 8) * N);
        }
        cp_commit();

        const float* Ab = As + buf * AW;
        const float* Bb = Bs + buf * BW;
        #pragma unroll
        for (int ks = 0; ks < 4; ks++) {
            const int kb = ks * 8;
            uint32_t af[2][4];
            #pragma unroll
            for (int mt = 0; mt < 2; mt++) {
                int r = warp_m * 32 + mt * 16 + grp;
                af[mt][0] = __float_as_uint(Ab[r * AROW + kb + t4]);
                af[mt][1] = __float_as_uint(Ab[(r + 8) * AROW + kb + t4]);
                af[mt][2] = __float_as_uint(Ab[r * AROW + kb + 4 + t4]);
                af[mt][3] = __float_as_uint(Ab[(r + 8) * AROW + kb + 4 + t4]);
            }
            #pragma unroll
            for (int nt = 0; nt < 8; nt++) {
                int col = warp_n * 64 + nt * 8 + grp;
                uint32_t bf[2];
                bf[0] = __float_as_uint(Bb[(kb + t4) * BROW + col]);
                bf[1] = __float_as_uint(Bb[(kb + 4 + t4) * BROW + col]);
                mma_tf32(acc[0][nt], af[0], bf);
                mma_tf32(acc[1][nt], af[1], bf);
            }
        }
        buf = (buf + 1 == STAGES) ? 0 : buf + 1;
        nbuf = (nbuf + 1 == STAGES) ? 0 : nbuf + 1;
    }

    // epilogue
    #pragma unroll
    for (int mt = 0; mt < 2; mt++) {
        int row = brow + warp_m * 32 + mt * 16 + grp;
        #pragma unroll
        for (int nt = 0; nt < 8; nt++) {
            int col = bcol + warp_n * 64 + nt * 8 + 2 * t4;
            float b0 = bias[col], b1 = bias[col + 1];
            float v0 = acc[mt][nt][0] + b0;
            float v1 = acc[mt][nt][1] + b1;
            float v2 = acc[mt][nt][2] + b0;
            float v3 = acc[mt][nt][3] + b1;
            if (EPI == 1) {
                v0 = f2tf32f(gelu_tanh(v0)); v1 = f2tf32f(gelu_tanh(v1));
                v2 = f2tf32f(gelu_tanh(v2)); v3 = f2tf32f(gelu_tanh(v3));
            }
            if (EPI == 2) {
                v0 += res[(size_t)row * N + col];
                v1 += res[(size_t)row * N + col + 1];
                v2 += res[(size_t)(row + 8) * N + col];
                v3 += res[(size_t)(row + 8) * N + col + 1];
            }
            float2 o0 = { v0, v1 };
            float2 o1 = { v2, v3 };
            *(float2*)&Cmat[(size_t)row * N + col]       = o0;
            *(float2*)&Cmat[(size_t)(row + 8) * N + col] = o1;
        }
    }
}

// ---------------- CSR build ----------------
__global__ void zero_cnt_kernel(int* __restrict__ cnt) {
    int i = blockIdx.x * blockDim.x + threadIdx.x;
    if (i < L) cnt[i] = 0;
}
__global__ void hist_kernel(const int* __restrict__ row, int* __restrict__ cnt) {
    int e = blockIdx.x * blockDim.x + threadIdx.x;
    if (e < E) atomicAdd(&cnt[row[e]], 1);
}
__global__ void scan_kernel(const int* __restrict__ cnt, int* __restrict__ off,
                            int* __restrict__ cur) {
    // one block, 1024 threads, 16 elems/thread
    __shared__ int ws[32];
    int tid = threadIdx.x;
    int base = tid * 16;
    int loc[16];
    int s = 0;
    #pragma unroll
    for (int i = 0; i < 16; i++) { loc[i] = s; s += cnt[base + i]; }
    int lane = tid & 31, w = tid >> 5;
    int v = s;
    #pragma unroll
    for (int o = 1; o < 32; o <<= 1) {
        int t = __shfl_up_sync(0xffffffffu, v, o);
        if (lane >= o) v += t;
    }
    if (lane == 31) ws[w] = v;
    __syncthreads();
    if (w == 0) {
        int t = ws[lane];
        #pragma unroll
        for (int o = 1; o < 32; o <<= 1) {
            int u = __shfl_up_sync(0xffffffffu, t, o);
            if (lane >= o) t += u;
        }
        ws[lane] = t;
    }
    __syncthreads();
    int excl = v - s + (w > 0 ? ws[w - 1] : 0);
    #pragma unroll
    for (int i = 0; i < 16; i++) {
        off[base + i] = excl + loc[i];
        cur[base + i] = excl + loc[i];
    }
    if (tid == 1023) off[L] = excl + s;
}
__global__ void scatter_kernel(const int* __restrict__ row,
                               int* __restrict__ cur, int* __restrict__ eid) {
    int e = blockIdx.x * blockDim.x + threadIdx.x;
    if (e < E) {
        int p = atomicAdd(&cur[row[e]], 1);
        eid[p] = e;
    }
}

// ---------------- edge score: one warp per edge ----------------
__global__ void edge_score_kernel(const float* __restrict__ qkv,
                                  const int* __restrict__ row_index,
                                  const int* __restrict__ col_index,
                                  const float* __restrict__ pab,
                                  float* __restrict__ score) {
    int e = blockIdx.x * 8 + (threadIdx.x >> 5);
    int lane = threadIdx.x & 31;
    const float* qr = qkv + (size_t)row_index[e] * NQKV;
    const float* kr = qkv + (size_t)col_index[e] * NQKV + C;
    #pragma unroll
    for (int h = 0; h < H; h++) {
        float d0 = qr[h * DH + lane]      - kr[h * DH + lane];
        float d1 = qr[h * DH + 32 + lane] - kr[h * DH + 32 + lane];
        float s = d0 * d0 + d1 * d1;
        #pragma unroll
        for (int o = 16; o > 0; o >>= 1) s += __shfl_xor_sync(0xffffffffu, s, o);
        if (lane == 0)
            score[(size_t)e * H + h] = -s * 0.125f + pab[(size_t)e * H + h];
    }
}

// ---------------- fused row softmax + aggregation (no global atomics) ----
#define MAXCH 16
__global__ __launch_bounds__(128)
void row_agg_kernel(const float* __restrict__ qkv,
                    const float* __restrict__ score,
                    const int* __restrict__ off,
                    const int* __restrict__ eid,
                    const int* __restrict__ col_index,
                    const int* __restrict__ to_col_index,
                    const float* __restrict__ dist,
                    const float* __restrict__ pos,
                    const float* __restrict__ col_pos,
                    const float* __restrict__ Wvec,
                    const float* __restrict__ bvec,
                    float* __restrict__ agg) {
    int r = blockIdx.x;
    int tid = threadIdx.x;          // 128
    int beg = off[r], end = off[r + 1];
    int deg = end - beg;
    int c0 = tid * 4;
    int hh = c0 >> 6;               // head for all 4 channels

    // per-thread Wvec slice
    float4 wv0 = *(const float4*)(Wvec + c0);
    float4 wv1 = *(const float4*)(Wvec + C + c0);
    float4 wv2 = *(const float4*)(Wvec + 2 * C + c0);
    float4 bv  = *(const float4*)(bvec + c0);

    __shared__ float s_den[H];
    __shared__ float s_meta[MAXCH][12];   // ci, rx, ry, rz, alpha[8]
    if (tid < H) s_den[tid] = 0.0f;
    __syncthreads();
    for (int idx = tid; idx < deg * H; idx += 128) {
        int e = eid[beg + (idx >> 3)];
        atomicAdd(&s_den[idx & 7], __expf(score[(size_t)e * H + (idx & 7)]));
    }
    __syncthreads();
    if (tid < H) s_den[tid] = 1.0f / s_den[tid];
    __syncthreads();

    float a0 = 0.0f, a1 = 0.0f, a2 = 0.0f, a3 = 0.0f;
    for (int chunk = 0; chunk < deg; chunk += MAXCH) {
        int n = min(MAXCH, deg - chunk);
        if (tid < n) {
            int e = eid[beg + chunk + tid];
            int ci = col_index[e], tci = to_col_index[e];
            float dinv = 1.0f / dist[e];
            s_meta[tid][0] = __int_as_float(ci);
            s_meta[tid][1] = (col_pos[tci * 3 + 0] - pos[ci == ci ? r * 3 + 0 : 0]) * dinv;
            s_meta[tid][2] = (col_pos[tci * 3 + 1] - pos[r * 3 + 1]) * dinv;
            s_meta[tid][3] = (col_pos[tci * 3 + 2] - pos[r * 3 + 2]) * dinv;
        }
        if (tid < n * H) {
            int i = tid >> 3, h = tid & 7;
            int e = eid[beg + chunk + i];
            s_meta[i][4 + h] = __expf(score[(size_t)e * H + h]) * s_den[h];
        }
        __syncthreads();
        for (int i = 0; i < n; i++) {
            int ci = __float_as_int(s_meta[i][0]);
            float rx = s_meta[i][1], ry = s_meta[i][2], rz = s_meta[i][3];
            float al = s_meta[i][4 + hh];
            float4 v4 = *(const float4*)(qkv + (size_t)ci * NQKV + 2 * C + c0);
            a0 += al * (v4.x + rx * wv0.x + ry * wv1.x + rz * wv2.x + bv.x);
            a1 += al * (v4.y + rx * wv0.y + ry * wv1.y + rz * wv2.y + bv.y);
            a2 += al * (v4.z + rx * wv0.z + ry * wv1.z + rz * wv2.z + bv.z);
            a3 += al * (v4.w + rx * wv0.w + ry * wv1.w + rz * wv2.w + bv.w);
        }
        __syncthreads();
    }
    float4 o;
    o.x = f2tf32f(a0); o.y = f2tf32f(a1);
    o.z = f2tf32f(a2); o.w = f2tf32f(a3);
    *(float4*)(agg + (size_t)r * C + c0) = o;
}

// ---------------- launcher ----------------
extern "C" void kernel_launch(void* const* d_in, const int* in_sizes, int n_in,
                              void* d_out, int out_size) {
    const float* x        = (const float*)d_in[0];
    const int*   row_idx  = (const int*)  d_in[1];
    const int*   col_idx  = (const int*)  d_in[2];
    const int*   tcol_idx = (const int*)  d_in[3];
    // d_in[4] = att_bias (unused by reference)
    const float* pab      = (const float*)d_in[5];
    const float* dist     = (const float*)d_in[6];
    const float* pos      = (const float*)d_in[7];
    const float* col_pos  = (const float*)d_in[8];
    const float* ln1_g    = (const float*)d_in[9];
    const float* ln1_b    = (const float*)d_in[10];
    const float* ln2_g    = (const float*)d_in[11];
    const float* ln2_b    = (const float*)d_in[12];
    const float* Wq       = (const float*)d_in[13];
    const float* bq       = (const float*)d_in[14];
    const float* Wk       = (const float*)d_in[15];
    const float* bk       = (const float*)d_in[16];
    const float* Wv       = (const float*)d_in[17];
    const float* bv       = (const float*)d_in[18];
    const float* Wvec     = (const float*)d_in[19];
    const float* bvec     = (const float*)d_in[20];
    const float* Wo       = (const float*)d_in[21];
    const float* bo       = (const float*)d_in[22];
    const float* W1       = (const float*)d_in[23];
    const float* b1       = (const float*)d_in[24];
    const float* W2       = (const float*)d_in[25];
    const float* b2       = (const float*)d_in[26];
    float* out = (float*)d_out;

    static float *zp = nullptr, *qkvp, *scp, *aggp, *x1p, *z2p, *hidp,
                 *wqkvp, *bqkvp, *wop, *w1p, *w2p;
    static int *cntp, *offp, *curp, *eidp;
    if (!zp) {
        cudaGetSymbolAddress((void**)&zp,    g_z);
        cudaGetSymbolAddress((void**)&qkvp,  g_qkv);
        cudaGetSymbolAddress((void**)&scp,   g_score);
        cudaGetSymbolAddress((void**)&aggp,  g_agg);
        cudaGetSymbolAddress((void**)&x1p,   g_x1);
        cudaGetSymbolAddress((void**)&z2p,   g_z2);
        cudaGetSymbolAddress((void**)&hidp,  g_hid);
        cudaGetSymbolAddress((void**)&wqkvp, g_wqkv);
        cudaGetSymbolAddress((void**)&bqkvp, g_bqkv);
        cudaGetSymbolAddress((void**)&wop,   g_wo);
        cudaGetSymbolAddress((void**)&w1p,   g_w1);
        cudaGetSymbolAddress((void**)&w2p,   g_w2);
        cudaGetSymbolAddress((void**)&cntp,  g_cnt);
        cudaGetSymbolAddress((void**)&offp,  g_off);
        cudaGetSymbolAddress((void**)&curp,  g_cur);
        cudaGetSymbolAddress((void**)&eidp,  g_eid);
        const int smem_bytes = SMEM_WORDS * 4;
        cudaFuncSetAttribute(tgemm_kernel<0>,
            cudaFuncAttributeMaxDynamicSharedMemorySize, smem_bytes);
        cudaFuncSetAttribute(tgemm_kernel<1>,
            cudaFuncAttributeMaxDynamicSharedMemorySize, smem_bytes);
        cudaFuncSetAttribute(tgemm_kernel<2>,
            cudaFuncAttributeMaxDynamicSharedMemorySize, smem_bytes);
    }
    const int SMEM_B = SMEM_WORDS * 4;

    // CSR build (only depends on row_idx)
    zero_cnt_kernel<<<(L + 255) / 256, 256>>>(cntp);
    hist_kernel<<<(E + 255) / 256, 256>>>(row_idx, cntp);
    scan_kernel<<<1, 1024>>>(cntp, offp, curp);
    scatter_kernel<<<(E + 255) / 256, 256>>>(row_idx, curp, eidp);

    // weight prep
    pack_qkv_kernel<<<(C * C + 255) / 256, 256>>>(Wq, Wk, Wv, bq, bk, bv,
                                                  wqkvp, bqkvp);
    round_copy_kernel<<<(C * C / 4 + 255) / 256, 256>>>(Wo, wop, C * C / 4);
    round_copy_kernel<<<(C * HID / 4 + 255) / 256, 256>>>(W1, w1p, C * HID / 4);
    round_copy_kernel<<<(C * HID / 4 + 255) / 256, 256>>>(W2, w2p, C * HID / 4);

    // LN1
    ln_kernel<<<L, 128>>>(x, ln1_g, ln1_b, zp);

    // fused QKV projection
    dim3 gqkv(NQKV / BN, L / BM);   // (12,128)
    tgemm_kernel<0><<<gqkv, 256, SMEM_B>>>(zp, wqkvp, bqkvp, nullptr, qkvp,
                                           L, NQKV, C);

    // edge scores
    edge_score_kernel<<<E / 8, 256>>>(qkvp, row_idx, col_idx, pab, scp);

    // fused softmax + aggregation
    row_agg_kernel<<<L, 128>>>(qkvp, scp, offp, eidp, col_idx, tcol_idx,
                               dist, pos, col_pos, Wvec, bvec, aggp);

    // output projection + residual
    dim3 g512(C / BN, L / BM);      // (4,128)
    tgemm_kernel<2><<<g512, 256, SMEM_B>>>(aggp, wop, bo, x, x1p, L, C, C);

    // LN2
    ln_kernel<<<L, 128>>>(x1p, ln2_g, ln2_b, z2p);

    // FFN up + gelu
    dim3 g1024(HID / BN, L / BM);   // (8,128)
    tgemm_kernel<1><<<g1024, 256, SMEM_B>>>(z2p, w1p, b1, nullptr, hidp,
                                            L, HID, C);

    // FFN down + residual
    tgemm_kernel<2><<<g512, 256, SMEM_B>>>(hidp, w2p, b2, x1p, out, L, C, HID);
}

// round 5
// speedup vs baseline: 2.9933x; 1.0951x over previous
#include <cuda_runtime.h>
#include <cuda_bf16.h>
#include <math.h>
#include <stdint.h>

// Problem constants
#define L   16384
#define E   131072
#define SP  20000
#define C   512
#define H   8
#define DH  64
#define HID 1024
#define NQKV 1536

// ---------------- scratch (device globals: allocation-free) ----------------
__device__ float g_z[(size_t)L * C];
__device__ float g_qkv[(size_t)L * NQKV];
__device__ float g_score[(size_t)E * H];
__device__ float g_agg[(size_t)L * C];
__device__ float g_x1[(size_t)L * C];
__device__ float g_z2[(size_t)L * C];
__device__ float g_hid[(size_t)L * HID];
// transposed + tf32-rounded weights: [N][K] row-major
__device__ float g_wqkv[(size_t)NQKV * C];
__device__ float g_bqkv[NQKV];
__device__ float g_wo[(size_t)C * C];
__device__ float g_w1[(size_t)HID * C];
__device__ float g_w2[(size_t)C * HID];
// CSR
__device__ int g_cnt[L];
__device__ int g_off[L + 1];
__device__ int g_cur[L];
__device__ int g_eid[E];

// ---------------- helpers ----------------
__device__ __forceinline__ float gelu_tanh(float x) {
    const float k0 = 0.7978845608028654f;
    const float k1 = 0.044715f;
    float x3 = x * x * x;
    return 0.5f * x * (1.0f + tanhf(k0 * (x + k1 * x3)));
}

__device__ __forceinline__ float f2tf32f(float f) {
    uint32_t r;
    asm("cvt.rna.tf32.f32 %0, %1;" : "=r"(r) : "f"(f));
    return __uint_as_float(r);
}

__device__ __forceinline__ void mma_tf32(float* d, const uint32_t* a,
                                         const uint32_t* b) {
    asm volatile(
        "mma.sync.aligned.m16n8k8.row.col.f32.tf32.tf32.f32 "
        "{%0,%1,%2,%3}, {%4,%5,%6,%7}, {%8,%9}, {%0,%1,%2,%3};\n"
        : "+f"(d[0]), "+f"(d[1]), "+f"(d[2]), "+f"(d[3])
        : "r"(a[0]), "r"(a[1]), "r"(a[2]), "r"(a[3]),
          "r"(b[0]), "r"(b[1]));
}

__device__ __forceinline__ void ldsm_x4(uint32_t* r, uint32_t addr) {
    asm volatile(
        "ldmatrix.sync.aligned.m8n8.x4.shared.b16 {%0,%1,%2,%3}, [%4];\n"
        : "=r"(r[0]), "=r"(r[1]), "=r"(r[2]), "=r"(r[3]) : "r"(addr));
}

__device__ __forceinline__ void cp16(uint32_t dst, const float* src) {
    asm volatile("cp.async.cg.shared.global [%0], [%1], 16;\n"
                 :: "r"(dst), "l"(src));
}
__device__ __forceinline__ void cp_commit() {
    asm volatile("cp.async.commit_group;\n");
}
template <int N>
__device__ __forceinline__ void cp_wait() {
    asm volatile("cp.async.wait_group %0;\n" :: "n"(N));
}
__device__ __forceinline__ uint32_t smem_u32(const void* p) {
    uint32_t a;
    asm("{ .reg .u64 t; cvta.to.shared.u64 t, %1; cvt.u32.u64 %0, t; }"
        : "=r"(a) : "l"(p));
    return a;
}

// ---------------- weight prep: transpose + tf32 round ----------------
// src [Kd][Nd] row-major -> dst [Nd][Kd] row-major (tf32-rounded)
__global__ void transpose_round_kernel(const float* __restrict__ src,
                                       float* __restrict__ dst,
                                       int Kd, int Nd) {
    __shared__ float tile[32][33];
    int kb = blockIdx.y * 32, nb = blockIdx.x * 32;
    int tx = threadIdx.x, ty = threadIdx.y;   // 32x8
    #pragma unroll
    for (int i = ty; i < 32; i += 8)
        tile[i][tx] = src[(size_t)(kb + i) * Nd + nb + tx];
    __syncthreads();
    #pragma unroll
    for (int i = ty; i < 32; i += 8)
        dst[(size_t)(nb + i) * Kd + kb + tx] = f2tf32f(tile[tx][i]);
}

__global__ void pack_bias_kernel(const float* __restrict__ bq,
                                 const float* __restrict__ bk,
                                 const float* __restrict__ bv,
                                 float* __restrict__ b) {
    int i = blockIdx.x * blockDim.x + threadIdx.x;
    if (i < C) { b[i] = bq[i]; b[C + i] = bk[i]; b[2 * C + i] = bv[i]; }
}

// ---------------- LayerNorm (tf32-rounded output) ----------------
__global__ void ln_kernel(const float* __restrict__ x,
                          const float* __restrict__ g,
                          const float* __restrict__ b,
                          float* __restrict__ z) {
    int row = blockIdx.x;
    int t = threadIdx.x;                 // 0..127
    const float* xr = x + (size_t)row * C;
    float4 v4 = *(const float4*)(xr + t * 4);
    float s  = v4.x + v4.y + v4.z + v4.w;
    float ss = v4.x * v4.x + v4.y * v4.y + v4.z * v4.z + v4.w * v4.w;
    #pragma unroll
    for (int o = 16; o > 0; o >>= 1) {
        s  += __shfl_xor_sync(0xffffffffu, s, o);
        ss += __shfl_xor_sync(0xffffffffu, ss, o);
    }
    __shared__ float sh[4], sh2[4];
    int w = t >> 5;
    if ((t & 31) == 0) { sh[w] = s; sh2[w] = ss; }
    __syncthreads();
    float sum  = sh[0] + sh[1] + sh[2] + sh[3];
    float sum2 = sh2[0] + sh2[1] + sh2[2] + sh2[3];
    float mean = sum * (1.0f / C);
    float var  = sum2 * (1.0f / C) - mean * mean;
    float inv  = rsqrtf(var + 1e-5f);
    float4 g4 = *(const float4*)(g + t * 4);
    float4 b4 = *(const float4*)(b + t * 4);
    float4 o4;
    o4.x = f2tf32f((v4.x - mean) * inv * g4.x + b4.x);
    o4.y = f2tf32f((v4.y - mean) * inv * g4.y + b4.y);
    o4.z = f2tf32f((v4.z - mean) * inv * g4.z + b4.z);
    o4.w = f2tf32f((v4.w - mean) * inv * g4.w + b4.w);
    *(float4*)(z + (size_t)row * C + t * 4) = o4;
}

// ---------------- TF32 GEMM: LDSM fragments, xor swizzle, cp.async --------
// C = A(MxK) @ B^T where B is stored [N][K]; both tiles 128x32 K-contiguous.
#define BM  128
#define BN  128
#define BK  32
#define STAGES 3
#define STAGE_BYTES 16384          // 128 rows * 32 words * 4B
#define SMEM_BYTES (STAGES * 2 * STAGE_BYTES)   // 98304

template <int EPI>
__global__ __launch_bounds__(256, 1)
void tgemm_kernel(const float* __restrict__ A, const float* __restrict__ B,
                  const float* __restrict__ bias, const float* __restrict__ res,
                  float* __restrict__ Cmat, int M, int N, int K) {
    extern __shared__ float smemf[];
    const uint32_t sA = smem_u32(smemf);
    const uint32_t sB = sA + STAGES * STAGE_BYTES;

    const int tid    = threadIdx.x;
    const int lane   = tid & 31;
    const int wid    = tid >> 5;
    const int warp_m = wid & 3;
    const int warp_n = wid >> 2;

    const int brow = blockIdx.y * BM;
    const int bcol = blockIdx.x * BN;

    float acc[2][8][4];
    #pragma unroll
    for (int i = 0; i < 2; i++)
        #pragma unroll
        for (int j = 0; j < 8; j++)
            #pragma unroll
            for (int c = 0; c < 4; c++) acc[i][j][c] = 0.0f;

    // ---- loader mapping (identical for A and B tiles) ----
    const int lr  = tid >> 3;              // 0..31 row in 32-row group
    const int lc  = tid & 7;               // 16B chunk 0..7
    const uint32_t lsw = (uint32_t)((lc ^ (lr & 7)) * 16);  // swizzled byte off
    const float* A0 = A + (size_t)(brow + lr) * K + lc * 4;
    const float* B0 = B + (size_t)(bcol + lr) * K + lc * 4;
    const uint32_t dA = sA + (uint32_t)lr * 128 + lsw;
    const uint32_t dB = sB + (uint32_t)lr * 128 + lsw;

    // ---- fragment (LDSM) mapping ----
    const int m8    = lane >> 3;           // matrix index 0..3
    const int rowin = lane & 7;
    // A: matrix m -> rows (m&1)*8, k-half (m>>1)
    const uint32_t aOff = (uint32_t)(warp_m * 32 + (m8 & 1) * 8 + rowin) * 128;
    const int aKh = m8 >> 1;
    // B: matrix m -> nt parity (m>>1), k-half (m&1)
    const uint32_t bOff = (uint32_t)(warp_n * 64 + (m8 >> 1) * 8 + rowin) * 128;
    const int bKh = m8 & 1;

    const int kIters = K / BK;

    // prologue: stages 0..STAGES-2
    #pragma unroll
    for (int s = 0; s < STAGES - 1; s++) {
        int k0 = s * BK;
        uint32_t so = (uint32_t)s * STAGE_BYTES;
        #pragma unroll
        for (int p = 0; p < 4; p++)
            cp16(dA + so + p * 4096, A0 + (size_t)p * 32 * K + k0);
        #pragma unroll
        for (int p = 0; p < 4; p++)
            cp16(dB + so + p * 4096, B0 + (size_t)p * 32 * K + k0);
        cp_commit();
    }

    int buf = 0;
    int nbuf = STAGES - 1;
    for (int s = 0; s < kIters; s++) {
        cp_wait<STAGES - 2>();
        __syncthreads();

        if (s + STAGES - 1 < kIters) {
            int k0 = (s + STAGES - 1) * BK;
            uint32_t so = (uint32_t)nbuf * STAGE_BYTES;
            #pragma unroll
            for (int p = 0; p < 4; p++)
                cp16(dA + so + p * 4096, A0 + (size_t)p * 32 * K + k0);
            #pragma unroll
            for (int p = 0; p < 4; p++)
                cp16(dB + so + p * 4096, B0 + (size_t)p * 32 * K + k0);
        }
        cp_commit();

        const uint32_t bufOff = (uint32_t)buf * STAGE_BYTES;
        #pragma unroll
        for (int ks = 0; ks < 4; ks++) {
            uint32_t af[2][4];
            uint32_t aSw = (uint32_t)(((ks * 2 + aKh) ^ rowin) << 4);
            ldsm_x4(af[0], sA + bufOff + aOff + aSw);
            ldsm_x4(af[1], sA + bufOff + aOff + 16 * 128 + aSw);
            uint32_t bSw = (uint32_t)(((ks * 2 + bKh) ^ rowin) << 4);
            #pragma unroll
            for (int np = 0; np < 4; np++) {
                uint32_t bf[4];
                ldsm_x4(bf, sB + bufOff + bOff + (uint32_t)np * (16 * 128) + bSw);
                mma_tf32(acc[0][2 * np],     af[0], bf);
                mma_tf32(acc[1][2 * np],     af[1], bf);
                mma_tf32(acc[0][2 * np + 1], af[0], bf + 2);
                mma_tf32(acc[1][2 * np + 1], af[1], bf + 2);
            }
        }
        buf = (buf + 1 == STAGES) ? 0 : buf + 1;
        nbuf = (nbuf + 1 == STAGES) ? 0 : nbuf + 1;
    }

    // ---- epilogue ----
    const int grp = lane >> 2;
    const int t4  = lane & 3;
    #pragma unroll
    for (int mt = 0; mt < 2; mt++) {
        int row = brow + warp_m * 32 + mt * 16 + grp;
        #pragma unroll
        for (int nt = 0; nt < 8; nt++) {
            int col = bcol + warp_n * 64 + nt * 8 + 2 * t4;
            float b0 = bias[col], b1 = bias[col + 1];
            float v0 = acc[mt][nt][0] + b0;
            float v1 = acc[mt][nt][1] + b1;
            float v2 = acc[mt][nt][2] + b0;
            float v3 = acc[mt][nt][3] + b1;
            if (EPI == 1) {
                v0 = f2tf32f(gelu_tanh(v0)); v1 = f2tf32f(gelu_tanh(v1));
                v2 = f2tf32f(gelu_tanh(v2)); v3 = f2tf32f(gelu_tanh(v3));
            }
            if (EPI == 2) {
                v0 += res[(size_t)row * N + col];
                v1 += res[(size_t)row * N + col + 1];
                v2 += res[(size_t)(row + 8) * N + col];
                v3 += res[(size_t)(row + 8) * N + col + 1];
            }
            float2 o0 = { v0, v1 };
            float2 o1 = { v2, v3 };
            *(float2*)&Cmat[(size_t)row * N + col]       = o0;
            *(float2*)&Cmat[(size_t)(row + 8) * N + col] = o1;
        }
    }
}

// ---------------- CSR build ----------------
__global__ void zero_cnt_kernel(int* __restrict__ cnt) {
    int i = blockIdx.x * blockDim.x + threadIdx.x;
    if (i < L) cnt[i] = 0;
}
__global__ void hist_kernel(const int* __restrict__ row, int* __restrict__ cnt) {
    int e = blockIdx.x * blockDim.x + threadIdx.x;
    if (e < E) atomicAdd(&cnt[row[e]], 1);
}
__global__ void scan_kernel(const int* __restrict__ cnt, int* __restrict__ off,
                            int* __restrict__ cur) {
    __shared__ int ws[32];
    int tid = threadIdx.x;
    int base = tid * 16;
    int loc[16];
    int s = 0;
    #pragma unroll
    for (int i = 0; i < 16; i++) { loc[i] = s; s += cnt[base + i]; }
    int lane = tid & 31, w = tid >> 5;
    int v = s;
    #pragma unroll
    for (int o = 1; o < 32; o <<= 1) {
        int t = __shfl_up_sync(0xffffffffu, v, o);
        if (lane >= o) v += t;
    }
    if (lane == 31) ws[w] = v;
    __syncthreads();
    if (w == 0) {
        int t = ws[lane];
        #pragma unroll
        for (int o = 1; o < 32; o <<= 1) {
            int u = __shfl_up_sync(0xffffffffu, t, o);
            if (lane >= o) t += u;
        }
        ws[lane] = t;
    }
    __syncthreads();
    int excl = v - s + (w > 0 ? ws[w - 1] : 0);
    #pragma unroll
    for (int i = 0; i < 16; i++) {
        off[base + i] = excl + loc[i];
        cur[base + i] = excl + loc[i];
    }
    if (tid == 1023) off[L] = excl + s;
}
__global__ void scatter_kernel(const int* __restrict__ row,
                               int* __restrict__ cur, int* __restrict__ eid) {
    int e = blockIdx.x * blockDim.x + threadIdx.x;
    if (e < E) {
        int p = atomicAdd(&cur[row[e]], 1);
        eid[p] = e;
    }
}

// ---------------- edge score: one warp per edge ----------------
__global__ void edge_score_kernel(const float* __restrict__ qkv,
                                  const int* __restrict__ row_index,
                                  const int* __restrict__ col_index,
                                  const float* __restrict__ pab,
                                  float* __restrict__ score) {
    int e = blockIdx.x * 8 + (threadIdx.x >> 5);
    int lane = threadIdx.x & 31;
    const float* qr = qkv + (size_t)row_index[e] * NQKV;
    const float* kr = qkv + (size_t)col_index[e] * NQKV + C;
    #pragma unroll
    for (int h = 0; h < H; h++) {
        float d0 = qr[h * DH + lane]      - kr[h * DH + lane];
        float d1 = qr[h * DH + 32 + lane] - kr[h * DH + 32 + lane];
        float s = d0 * d0 + d1 * d1;
        #pragma unroll
        for (int o = 16; o > 0; o >>= 1) s += __shfl_xor_sync(0xffffffffu, s, o);
        if (lane == 0)
            score[(size_t)e * H + h] = -s * 0.125f + pab[(size_t)e * H + h];
    }
}

// ---------------- fused row softmax + aggregation ----------------
#define MAXCH 16
__global__ __launch_bounds__(128)
void row_agg_kernel(const float* __restrict__ qkv,
                    const float* __restrict__ score,
                    const int* __restrict__ off,
                    const int* __restrict__ eid,
                    const int* __restrict__ col_index,
                    const int* __restrict__ to_col_index,
                    const float* __restrict__ dist,
                    const float* __restrict__ pos,
                    const float* __restrict__ col_pos,
                    const float* __restrict__ Wvec,
                    const float* __restrict__ bvec,
                    float* __restrict__ agg) {
    int r = blockIdx.x;
    int tid = threadIdx.x;          // 128
    int beg = off[r], end = off[r + 1];
    int deg = end - beg;
    int c0 = tid * 4;
    int hh = c0 >> 6;

    float4 wv0 = *(const float4*)(Wvec + c0);
    float4 wv1 = *(const float4*)(Wvec + C + c0);
    float4 wv2 = *(const float4*)(Wvec + 2 * C + c0);
    float4 bv  = *(const float4*)(bvec + c0);

    __shared__ float s_den[H];
    __shared__ float s_meta[MAXCH][12];
    if (tid < H) s_den[tid] = 0.0f;
    __syncthreads();
    for (int idx = tid; idx < deg * H; idx += 128) {
        int e = eid[beg + (idx >> 3)];
        atomicAdd(&s_den[idx & 7], __expf(score[(size_t)e * H + (idx & 7)]));
    }
    __syncthreads();
    if (tid < H) s_den[tid] = 1.0f / s_den[tid];
    __syncthreads();

    float a0 = 0.0f, a1 = 0.0f, a2 = 0.0f, a3 = 0.0f;
    for (int chunk = 0; chunk < deg; chunk += MAXCH) {
        int n = min(MAXCH, deg - chunk);
        if (tid < n) {
            int e = eid[beg + chunk + tid];
            int ci = col_index[e], tci = to_col_index[e];
            float dinv = 1.0f / dist[e];
            s_meta[tid][0] = __int_as_float(ci);
            s_meta[tid][1] = (col_pos[tci * 3 + 0] - pos[r * 3 + 0]) * dinv;
            s_meta[tid][2] = (col_pos[tci * 3 + 1] - pos[r * 3 + 1]) * dinv;
            s_meta[tid][3] = (col_pos[tci * 3 + 2] - pos[r * 3 + 2]) * dinv;
        }
        if (tid < n * H) {
            int i = tid >> 3, h = tid & 7;
            int e = eid[beg + chunk + i];
            s_meta[i][4 + h] = __expf(score[(size_t)e * H + h]) * s_den[h];
        }
        __syncthreads();
        for (int i = 0; i < n; i++) {
            int ci = __float_as_int(s_meta[i][0]);
            float rx = s_meta[i][1], ry = s_meta[i][2], rz = s_meta[i][3];
            float al = s_meta[i][4 + hh];
            float4 v4 = *(const float4*)(qkv + (size_t)ci * NQKV + 2 * C + c0);
            a0 += al * (v4.x + rx * wv0.x + ry * wv1.x + rz * wv2.x + bv.x);
            a1 += al * (v4.y + rx * wv0.y + ry * wv1.y + rz * wv2.y + bv.y);
            a2 += al * (v4.z + rx * wv0.z + ry * wv1.z + rz * wv2.z + bv.z);
            a3 += al * (v4.w + rx * wv0.w + ry * wv1.w + rz * wv2.w + bv.w);
        }
        __syncthreads();
    }
    float4 o;
    o.x = f2tf32f(a0); o.y = f2tf32f(a1);
    o.z = f2tf32f(a2); o.w = f2tf32f(a3);
    *(float4*)(agg + (size_t)r * C + c0) = o;
}

// ---------------- launcher ----------------
extern "C" void kernel_launch(void* const* d_in, const int* in_sizes, int n_in,
                              void* d_out, int out_size) {
    const float* x        = (const float*)d_in[0];
    const int*   row_idx  = (const int*)  d_in[1];
    const int*   col_idx  = (const int*)  d_in[2];
    const int*   tcol_idx = (const int*)  d_in[3];
    const float* pab      = (const float*)d_in[5];
    const float* dist     = (const float*)d_in[6];
    const float* pos      = (const float*)d_in[7];
    const float* col_pos  = (const float*)d_in[8];
    const float* ln1_g    = (const float*)d_in[9];
    const float* ln1_b    = (const float*)d_in[10];
    const float* ln2_g    = (const float*)d_in[11];
    const float* ln2_b    = (const float*)d_in[12];
    const float* Wq       = (const float*)d_in[13];
    const float* bq       = (const float*)d_in[14];
    const float* Wk       = (const float*)d_in[15];
    const float* bk       = (const float*)d_in[16];
    const float* Wv       = (const float*)d_in[17];
    const float* bv       = (const float*)d_in[18];
    const float* Wvec     = (const float*)d_in[19];
    const float* bvec     = (const float*)d_in[20];
    const float* Wo       = (const float*)d_in[21];
    const float* bo       = (const float*)d_in[22];
    const float* W1       = (const float*)d_in[23];
    const float* b1       = (const float*)d_in[24];
    const float* W2       = (const float*)d_in[25];
    const float* b2       = (const float*)d_in[26];
    float* out = (float*)d_out;

    static float *zp = nullptr, *qkvp, *scp, *aggp, *x1p, *z2p, *hidp,
                 *wqkvp, *bqkvp, *wop, *w1p, *w2p;
    static int *cntp, *offp, *curp, *eidp;
    if (!zp) {
        cudaGetSymbolAddress((void**)&zp,    g_z);
        cudaGetSymbolAddress((void**)&qkvp,  g_qkv);
        cudaGetSymbolAddress((void**)&scp,   g_score);
        cudaGetSymbolAddress((void**)&aggp,  g_agg);
        cudaGetSymbolAddress((void**)&x1p,   g_x1);
        cudaGetSymbolAddress((void**)&z2p,   g_z2);
        cudaGetSymbolAddress((void**)&hidp,  g_hid);
        cudaGetSymbolAddress((void**)&wqkvp, g_wqkv);
        cudaGetSymbolAddress((void**)&bqkvp, g_bqkv);
        cudaGetSymbolAddress((void**)&wop,   g_wo);
        cudaGetSymbolAddress((void**)&w1p,   g_w1);
        cudaGetSymbolAddress((void**)&w2p,   g_w2);
        cudaGetSymbolAddress((void**)&cntp,  g_cnt);
        cudaGetSymbolAddress((void**)&offp,  g_off);
        cudaGetSymbolAddress((void**)&curp,  g_cur);
        cudaGetSymbolAddress((void**)&eidp,  g_eid);
        cudaFuncSetAttribute(tgemm_kernel<0>,
            cudaFuncAttributeMaxDynamicSharedMemorySize, SMEM_BYTES);
        cudaFuncSetAttribute(tgemm_kernel<1>,
            cudaFuncAttributeMaxDynamicSharedMemorySize, SMEM_BYTES);
        cudaFuncSetAttribute(tgemm_kernel<2>,
            cudaFuncAttributeMaxDynamicSharedMemorySize, SMEM_BYTES);
    }

    // CSR build
    zero_cnt_kernel<<<(L + 255) / 256, 256>>>(cntp);
    hist_kernel<<<(E + 255) / 256, 256>>>(row_idx, cntp);
    scan_kernel<<<1, 1024>>>(cntp, offp, curp);
    scatter_kernel<<<(E + 255) / 256, 256>>>(row_idx, curp, eidp);

    // weight prep: transpose + round to [N][K]
    dim3 tb(32, 8);
    transpose_round_kernel<<<dim3(C / 32, C / 32), tb>>>(Wq, wqkvp,           C, C);
    transpose_round_kernel<<<dim3(C / 32, C / 32), tb>>>(Wk, wqkvp + (size_t)C * C,     C, C);
    transpose_round_kernel<<<dim3(C / 32, C / 32), tb>>>(Wv, wqkvp + (size_t)2 * C * C, C, C);
    transpose_round_kernel<<<dim3(C / 32, C / 32), tb>>>(Wo, wop, C, C);
    transpose_round_kernel<<<dim3(HID / 32, C / 32), tb>>>(W1, w1p, C, HID);
    transpose_round_kernel<<<dim3(C / 32, HID / 32), tb>>>(W2, w2p, HID, C);
    pack_bias_kernel<<<(C + 255) / 256, 256>>>(bq, bk, bv, bqkvp);

    // LN1
    ln_kernel<<<L, 128>>>(x, ln1_g, ln1_b, zp);

    // fused QKV projection
    dim3 gqkv(NQKV / BN, L / BM);
    tgemm_kernel<0><<<gqkv, 256, SMEM_BYTES>>>(zp, wqkvp, bqkvp, nullptr, qkvp,
                                               L, NQKV, C);

    // edge scores
    edge_score_kernel<<<E / 8, 256>>>(qkvp, row_idx, col_idx, pab, scp);

    // fused softmax + aggregation
    row_agg_kernel<<<L, 128>>>(qkvp, scp, offp, eidp, col_idx, tcol_idx,
                               dist, pos, col_pos, Wvec, bvec, aggp);

    // output projection + residual
    dim3 g512(C / BN, L / BM);
    tgemm_kernel<2><<<g512, 256, SMEM_BYTES>>>(aggp, wop, bo, x, x1p, L, C, C);

    // LN2
    ln_kernel<<<L, 128>>>(x1p, ln2_g, ln2_b, z2p);

    // FFN up + gelu
    dim3 g1024(HID / BN, L / BM);
    tgemm_kernel<1><<<g1024, 256, SMEM_BYTES>>>(z2p, w1p, b1, nullptr, hidp,
                                                L, HID, C);

    // FFN down + residual
    tgemm_kernel<2><<<g512, 256, SMEM_BYTES>>>(hidp, w2p, b2, x1p, out, L, C, HID);
}

// round 6
// speedup vs baseline: 4.2252x; 1.4115x over previous
#include <cuda_runtime.h>
#include <cuda_bf16.h>
#include <math.h>
#include <stdint.h>

// Problem constants
#define L   16384
#define E   131072
#define SP  20000
#define C   512
#define H   8
#define DH  64
#define HID 1024
#define NQKV 1536

// ---------------- scratch (device globals: allocation-free) ----------------
__device__ __nv_bfloat16 g_z[(size_t)L * C];
__device__ float         g_qkv[(size_t)L * NQKV];
__device__ float         g_score[(size_t)E * H];
__device__ __nv_bfloat16 g_agg[(size_t)L * C];
__device__ float         g_x1[(size_t)L * C];
__device__ __nv_bfloat16 g_z2[(size_t)L * C];
__device__ __nv_bfloat16 g_hid[(size_t)L * HID];
// transposed bf16 weights: [N][K]
__device__ __nv_bfloat16 g_wqkv[(size_t)NQKV * C];
__device__ float         g_bqkv[NQKV];
__device__ __nv_bfloat16 g_wo[(size_t)C * C];
__device__ __nv_bfloat16 g_w1[(size_t)HID * C];
__device__ __nv_bfloat16 g_w2[(size_t)C * HID];
// CSR
__device__ int g_cnt[L];
__device__ int g_off[L + 1];
__device__ int g_cur[L];
__device__ int g_eid[E];

// ---------------- helpers ----------------
__device__ __forceinline__ float gelu_tanh(float x) {
    const float k0 = 0.7978845608028654f;
    const float k1 = 0.044715f;
    float x3 = x * x * x;
    return 0.5f * x * (1.0f + tanhf(k0 * (x + k1 * x3)));
}

__device__ __forceinline__ void mma_bf16(float* d, const uint32_t* a,
                                         const uint32_t* b) {
    asm volatile(
        "mma.sync.aligned.m16n8k16.row.col.f32.bf16.bf16.f32 "
        "{%0,%1,%2,%3}, {%4,%5,%6,%7}, {%8,%9}, {%0,%1,%2,%3};\n"
        : "+f"(d[0]), "+f"(d[1]), "+f"(d[2]), "+f"(d[3])
        : "r"(a[0]), "r"(a[1]), "r"(a[2]), "r"(a[3]),
          "r"(b[0]), "r"(b[1]));
}

__device__ __forceinline__ void ldsm_x4(uint32_t* r, uint32_t addr) {
    asm volatile(
        "ldmatrix.sync.aligned.m8n8.x4.shared.b16 {%0,%1,%2,%3}, [%4];\n"
        : "=r"(r[0]), "=r"(r[1]), "=r"(r[2]), "=r"(r[3]) : "r"(addr));
}

__device__ __forceinline__ void cp16(uint32_t dst, const void* src) {
    asm volatile("cp.async.cg.shared.global [%0], [%1], 16;\n"
                 :: "r"(dst), "l"(src));
}
__device__ __forceinline__ void cp_commit() {
    asm volatile("cp.async.commit_group;\n");
}
template <int N>
__device__ __forceinline__ void cp_wait() {
    asm volatile("cp.async.wait_group %0;\n" :: "n"(N));
}
__device__ __forceinline__ uint32_t smem_u32(const void* p) {
    uint32_t a;
    asm("{ .reg .u64 t; cvta.to.shared.u64 t, %1; cvt.u32.u64 %0, t; }"
        : "=r"(a) : "l"(p));
    return a;
}

// swizzled byte offset of 16B chunk c (0..3) in logical row r (64B rows,
// packed 2 per 128B physical row)
__device__ __forceinline__ uint32_t sw_off(int r, int c) {
    return (uint32_t)((r >> 1) * 128 + ((((c + 4 * (r & 1))) ^ ((r >> 1) & 7)) << 4));
}

// ---------------- weight prep: transpose fp32 -> bf16 [N][K] ----------------
__global__ void transpose_bf16_kernel(const float* __restrict__ src,
                                      __nv_bfloat16* __restrict__ dst,
                                      int Kd, int Nd) {
    __shared__ float tile[32][33];
    int kb = blockIdx.y * 32, nb = blockIdx.x * 32;
    int tx = threadIdx.x, ty = threadIdx.y;   // 32x8
    #pragma unroll
    for (int i = ty; i < 32; i += 8)
        tile[i][tx] = src[(size_t)(kb + i) * Nd + nb + tx];
    __syncthreads();
    #pragma unroll
    for (int i = ty; i < 32; i += 8)
        dst[(size_t)(nb + i) * Kd + kb + tx] = __float2bfloat16_rn(tile[tx][i]);
}

__global__ void pack_bias_kernel(const float* __restrict__ bq,
                                 const float* __restrict__ bk,
                                 const float* __restrict__ bv,
                                 float* __restrict__ b) {
    int i = blockIdx.x * blockDim.x + threadIdx.x;
    if (i < C) { b[i] = bq[i]; b[C + i] = bk[i]; b[2 * C + i] = bv[i]; }
}

// ---------------- LayerNorm (bf16 output) ----------------
__global__ void ln_kernel(const float* __restrict__ x,
                          const float* __restrict__ g,
                          const float* __restrict__ b,
                          __nv_bfloat16* __restrict__ z) {
    int row = blockIdx.x;
    int t = threadIdx.x;                 // 0..127
    const float* xr = x + (size_t)row * C;
    float4 v4 = *(const float4*)(xr + t * 4);
    float s  = v4.x + v4.y + v4.z + v4.w;
    float ss = v4.x * v4.x + v4.y * v4.y + v4.z * v4.z + v4.w * v4.w;
    #pragma unroll
    for (int o = 16; o > 0; o >>= 1) {
        s  += __shfl_xor_sync(0xffffffffu, s, o);
        ss += __shfl_xor_sync(0xffffffffu, ss, o);
    }
    __shared__ float sh[4], sh2[4];
    int w = t >> 5;
    if ((t & 31) == 0) { sh[w] = s; sh2[w] = ss; }
    __syncthreads();
    float sum  = sh[0] + sh[1] + sh[2] + sh[3];
    float sum2 = sh2[0] + sh2[1] + sh2[2] + sh2[3];
    float mean = sum * (1.0f / C);
    float var  = sum2 * (1.0f / C) - mean * mean;
    float inv  = rsqrtf(var + 1e-5f);
    float4 g4 = *(const float4*)(g + t * 4);
    float4 b4 = *(const float4*)(b + t * 4);
    __nv_bfloat162 p0 = __floats2bfloat162_rn(
        (v4.x - mean) * inv * g4.x + b4.x, (v4.y - mean) * inv * g4.y + b4.y);
    __nv_bfloat162 p1 = __floats2bfloat162_rn(
        (v4.z - mean) * inv * g4.z + b4.z, (v4.w - mean) * inv * g4.w + b4.w);
    __nv_bfloat162* zr = (__nv_bfloat162*)(z + (size_t)row * C);
    zr[t * 2]     = p0;
    zr[t * 2 + 1] = p1;
}

// ---------------- bf16 tensor-core GEMM ----------------
// C = A(MxK,bf16) @ B^T (B stored [N][K] bf16)
// EPI: 0 bias->fp32, 1 bias+gelu->bf16, 2 bias+residual->fp32
#define BM  128
#define BN  128
#define BK  32
#define STAGES 4
#define STAGE_BYTES 8192            // 128 rows * 64B
#define SMEM_BYTES (STAGES * 2 * STAGE_BYTES)   // 65536

template <int EPI>
__global__ __launch_bounds__(256, 2)
void tgemm_kernel(const __nv_bfloat16* __restrict__ A,
                  const __nv_bfloat16* __restrict__ B,
                  const float* __restrict__ bias, const float* __restrict__ res,
                  float* __restrict__ Cmat, int M, int N, int K) {
    extern __shared__ float smemf[];
    const uint32_t sA = smem_u32(smemf);
    const uint32_t sB = sA + STAGES * STAGE_BYTES;

    const int tid    = threadIdx.x;
    const int lane   = tid & 31;
    const int wid    = tid >> 5;
    const int warp_m = wid & 3;
    const int warp_n = wid >> 2;

    const int brow = blockIdx.y * BM;
    const int bcol = blockIdx.x * BN;

    float acc[2][8][4];
    #pragma unroll
    for (int i = 0; i < 2; i++)
        #pragma unroll
        for (int j = 0; j < 8; j++)
            #pragma unroll
            for (int c = 0; c < 4; c++) acc[i][j][c] = 0.0f;

    // ---- loader mapping: 2 chunks of 16B per thread per tile ----
    const int lr = tid >> 1;              // logical row 0..127
    const int c0 = (tid & 1) * 2;         // chunk 0 or 2
    const __nv_bfloat16* A0 = A + (size_t)(brow + lr) * K + c0 * 8;
    const __nv_bfloat16* B0 = B + (size_t)(bcol + lr) * K + c0 * 8;
    const uint32_t dA0 = sA + sw_off(lr, c0);
    const uint32_t dA1 = sA + sw_off(lr, c0 + 1);
    const uint32_t dB0 = sB + sw_off(lr, c0);
    const uint32_t dB1 = sB + sw_off(lr, c0 + 1);

    // ---- fragment (LDSM) mapping ----
    const int m8    = lane >> 3;
    const int rowin = lane & 7;
    // A: m8&1 -> row half, m8>>1 -> k-chunk half
    int rA[2], cAh = m8 >> 1;
    rA[0] = warp_m * 32 + (m8 & 1) * 8 + rowin;
    rA[1] = rA[0] + 16;
    // B: m8>>1 -> n-subgroup, m8&1 -> k-chunk half
    int rB[4], cBh = m8 & 1;
    #pragma unroll
    for (int np = 0; np < 4; np++)
        rB[np] = warp_n * 64 + np * 16 + (m8 >> 1) * 8 + rowin;

    const int kIters = K / BK;

    // prologue
    #pragma unroll
    for (int s = 0; s < STAGES - 1; s++) {
        int k0 = s * BK;
        uint32_t so = (uint32_t)s * STAGE_BYTES;
        cp16(dA0 + so, A0 + k0);
        cp16(dA1 + so, A0 + k0 + 8);
        cp16(dB0 + so, B0 + k0);
        cp16(dB1 + so, B0 + k0 + 8);
        cp_commit();
    }

    int buf = 0;
    int nbuf = STAGES - 1;
    for (int s = 0; s < kIters; s++) {
        cp_wait<STAGES - 2>();
        __syncthreads();

        if (s + STAGES - 1 < kIters) {
            int k0 = (s + STAGES - 1) * BK;
            uint32_t so = (uint32_t)nbuf * STAGE_BYTES;
            cp16(dA0 + so, A0 + k0);
            cp16(dA1 + so, A0 + k0 + 8);
            cp16(dB0 + so, B0 + k0);
            cp16(dB1 + so, B0 + k0 + 8);
        }
        cp_commit();

        const uint32_t aBuf = sA + (uint32_t)buf * STAGE_BYTES;
        const uint32_t bBuf = sB + (uint32_t)buf * STAGE_BYTES;
        #pragma unroll
        for (int ks = 0; ks < 2; ks++) {
            uint32_t af[2][4];
            #pragma unroll
            for (int mt = 0; mt < 2; mt++)
                ldsm_x4(af[mt], aBuf + sw_off(rA[mt], 2 * ks + cAh));
            #pragma unroll
            for (int np = 0; np < 4; np++) {
                uint32_t bf[4];
                ldsm_x4(bf, bBuf + sw_off(rB[np], 2 * ks + cBh));
                mma_bf16(acc[0][2 * np],     af[0], bf);
                mma_bf16(acc[1][2 * np],     af[1], bf);
                mma_bf16(acc[0][2 * np + 1], af[0], bf + 2);
                mma_bf16(acc[1][2 * np + 1], af[1], bf + 2);
            }
        }
        buf = (buf + 1 == STAGES) ? 0 : buf + 1;
        nbuf = (nbuf + 1 == STAGES) ? 0 : nbuf + 1;
    }

    // ---- epilogue ----
    const int grp = lane >> 2;
    const int t4  = lane & 3;
    #pragma unroll
    for (int mt = 0; mt < 2; mt++) {
        int row = brow + warp_m * 32 + mt * 16 + grp;
        #pragma unroll
        for (int nt = 0; nt < 8; nt++) {
            int col = bcol + warp_n * 64 + nt * 8 + 2 * t4;
            float b0 = bias[col], b1 = bias[col + 1];
            float v0 = acc[mt][nt][0] + b0;
            float v1 = acc[mt][nt][1] + b1;
            float v2 = acc[mt][nt][2] + b0;
            float v3 = acc[mt][nt][3] + b1;
            if (EPI == 1) {
                __nv_bfloat16* O = (__nv_bfloat16*)Cmat;
                __nv_bfloat162 o0 = __floats2bfloat162_rn(gelu_tanh(v0),
                                                          gelu_tanh(v1));
                __nv_bfloat162 o1 = __floats2bfloat162_rn(gelu_tanh(v2),
                                                          gelu_tanh(v3));
                *(__nv_bfloat162*)&O[(size_t)row * N + col]       = o0;
                *(__nv_bfloat162*)&O[(size_t)(row + 8) * N + col] = o1;
            } else {
                if (EPI == 2) {
                    v0 += res[(size_t)row * N + col];
                    v1 += res[(size_t)row * N + col + 1];
                    v2 += res[(size_t)(row + 8) * N + col];
                    v3 += res[(size_t)(row + 8) * N + col + 1];
                }
                float2 o0 = { v0, v1 };
                float2 o1 = { v2, v3 };
                *(float2*)&Cmat[(size_t)row * N + col]       = o0;
                *(float2*)&Cmat[(size_t)(row + 8) * N + col] = o1;
            }
        }
    }
}

// ---------------- CSR build ----------------
__global__ void zero_cnt_kernel(int* __restrict__ cnt) {
    int i = blockIdx.x * blockDim.x + threadIdx.x;
    if (i < L) cnt[i] = 0;
}
__global__ void hist_kernel(const int* __restrict__ row, int* __restrict__ cnt) {
    int e = blockIdx.x * blockDim.x + threadIdx.x;
    if (e < E) atomicAdd(&cnt[row[e]], 1);
}
__global__ void scan_kernel(const int* __restrict__ cnt, int* __restrict__ off,
                            int* __restrict__ cur) {
    __shared__ int ws[32];
    int tid = threadIdx.x;
    int base = tid * 16;
    int loc[16];
    int s = 0;
    #pragma unroll
    for (int i = 0; i < 16; i++) { loc[i] = s; s += cnt[base + i]; }
    int lane = tid & 31, w = tid >> 5;
    int v = s;
    #pragma unroll
    for (int o = 1; o < 32; o <<= 1) {
        int t = __shfl_up_sync(0xffffffffu, v, o);
        if (lane >= o) v += t;
    }
    if (lane == 31) ws[w] = v;
    __syncthreads();
    if (w == 0) {
        int t = ws[lane];
        #pragma unroll
        for (int o = 1; o < 32; o <<= 1) {
            int u = __shfl_up_sync(0xffffffffu, t, o);
            if (lane >= o) t += u;
        }
        ws[lane] = t;
    }
    __syncthreads();
    int excl = v - s + (w > 0 ? ws[w - 1] : 0);
    #pragma unroll
    for (int i = 0; i < 16; i++) {
        off[base + i] = excl + loc[i];
        cur[base + i] = excl + loc[i];
    }
    if (tid == 1023) off[L] = excl + s;
}
__global__ void scatter_kernel(const int* __restrict__ row,
                               int* __restrict__ cur, int* __restrict__ eid) {
    int e = blockIdx.x * blockDim.x + threadIdx.x;
    if (e < E) {
        int p = atomicAdd(&cur[row[e]], 1);
        eid[p] = e;
    }
}

// ---------------- edge score: one warp per edge ----------------
__global__ void edge_score_kernel(const float* __restrict__ qkv,
                                  const int* __restrict__ row_index,
                                  const int* __restrict__ col_index,
                                  const float* __restrict__ pab,
                                  float* __restrict__ score) {
    int e = blockIdx.x * 8 + (threadIdx.x >> 5);
    int lane = threadIdx.x & 31;
    const float* qr = qkv + (size_t)row_index[e] * NQKV;
    const float* kr = qkv + (size_t)col_index[e] * NQKV + C;
    #pragma unroll
    for (int h = 0; h < H; h++) {
        float d0 = qr[h * DH + lane]      - kr[h * DH + lane];
        float d1 = qr[h * DH + 32 + lane] - kr[h * DH + 32 + lane];
        float s = d0 * d0 + d1 * d1;
        #pragma unroll
        for (int o = 16; o > 0; o >>= 1) s += __shfl_xor_sync(0xffffffffu, s, o);
        if (lane == 0)
            score[(size_t)e * H + h] = -s * 0.125f + pab[(size_t)e * H + h];
    }
}

// ---------------- fused row softmax + aggregation (bf16 agg out) ---------
#define MAXCH 16
__global__ __launch_bounds__(128)
void row_agg_kernel(const float* __restrict__ qkv,
                    const float* __restrict__ score,
                    const int* __restrict__ off,
                    const int* __restrict__ eid,
                    const int* __restrict__ col_index,
                    const int* __restrict__ to_col_index,
                    const float* __restrict__ dist,
                    const float* __restrict__ pos,
                    const float* __restrict__ col_pos,
                    const float* __restrict__ Wvec,
                    const float* __restrict__ bvec,
                    __nv_bfloat16* __restrict__ agg) {
    int r = blockIdx.x;
    int tid = threadIdx.x;          // 128
    int beg = off[r], end = off[r + 1];
    int deg = end - beg;
    int c0 = tid * 4;
    int hh = c0 >> 6;

    float4 wv0 = *(const float4*)(Wvec + c0);
    float4 wv1 = *(const float4*)(Wvec + C + c0);
    float4 wv2 = *(const float4*)(Wvec + 2 * C + c0);
    float4 bv  = *(const float4*)(bvec + c0);

    __shared__ float s_den[H];
    __shared__ float s_meta[MAXCH][12];
    if (tid < H) s_den[tid] = 0.0f;
    __syncthreads();
    for (int idx = tid; idx < deg * H; idx += 128) {
        int e = eid[beg + (idx >> 3)];
        atomicAdd(&s_den[idx & 7], __expf(score[(size_t)e * H + (idx & 7)]));
    }
    __syncthreads();
    if (tid < H) s_den[tid] = 1.0f / s_den[tid];
    __syncthreads();

    float a0 = 0.0f, a1 = 0.0f, a2 = 0.0f, a3 = 0.0f;
    for (int chunk = 0; chunk < deg; chunk += MAXCH) {
        int n = min(MAXCH, deg - chunk);
        if (tid < n) {
            int e = eid[beg + chunk + tid];
            int ci = col_index[e], tci = to_col_index[e];
            float dinv = 1.0f / dist[e];
            s_meta[tid][0] = __int_as_float(ci);
            s_meta[tid][1] = (col_pos[tci * 3 + 0] - pos[r * 3 + 0]) * dinv;
            s_meta[tid][2] = (col_pos[tci * 3 + 1] - pos[r * 3 + 1]) * dinv;
            s_meta[tid][3] = (col_pos[tci * 3 + 2] - pos[r * 3 + 2]) * dinv;
        }
        if (tid < n * H) {
            int i = tid >> 3, h = tid & 7;
            int e = eid[beg + chunk + i];
            s_meta[i][4 + h] = __expf(score[(size_t)e * H + h]) * s_den[h];
        }
        __syncthreads();
        for (int i = 0; i < n; i++) {
            int ci = __float_as_int(s_meta[i][0]);
            float rx = s_meta[i][1], ry = s_meta[i][2], rz = s_meta[i][3];
            float al = s_meta[i][4 + hh];
            float4 v4 = *(const float4*)(qkv + (size_t)ci * NQKV + 2 * C + c0);
            a0 += al * (v4.x + rx * wv0.x + ry * wv1.x + rz * wv2.x + bv.x);
            a1 += al * (v4.y + rx * wv0.y + ry * wv1.y + rz * wv2.y + bv.y);
            a2 += al * (v4.z + rx * wv0.z + ry * wv1.z + rz * wv2.z + bv.z);
            a3 += al * (v4.w + rx * wv0.w + ry * wv1.w + rz * wv2.w + bv.w);
        }
        __syncthreads();
    }
    __nv_bfloat162 o0 = __floats2bfloat162_rn(a0, a1);
    __nv_bfloat162 o1 = __floats2bfloat162_rn(a2, a3);
    __nv_bfloat162* ar = (__nv_bfloat162*)(agg + (size_t)r * C);
    ar[tid * 2]     = o0;
    ar[tid * 2 + 1] = o1;
}

// ---------------- launcher ----------------
extern "C" void kernel_launch(void* const* d_in, const int* in_sizes, int n_in,
                              void* d_out, int out_size) {
    const float* x        = (const float*)d_in[0];
    const int*   row_idx  = (const int*)  d_in[1];
    const int*   col_idx  = (const int*)  d_in[2];
    const int*   tcol_idx = (const int*)  d_in[3];
    const float* pab      = (const float*)d_in[5];
    const float* dist     = (const float*)d_in[6];
    const float* pos      = (const float*)d_in[7];
    const float* col_pos  = (const float*)d_in[8];
    const float* ln1_g    = (const float*)d_in[9];
    const float* ln1_b    = (const float*)d_in[10];
    const float* ln2_g    = (const float*)d_in[11];
    const float* ln2_b    = (const float*)d_in[12];
    const float* Wq       = (const float*)d_in[13];
    const float* bq       = (const float*)d_in[14];
    const float* Wk       = (const float*)d_in[15];
    const float* bk       = (const float*)d_in[16];
    const float* Wv       = (const float*)d_in[17];
    const float* bv       = (const float*)d_in[18];
    const float* Wvec     = (const float*)d_in[19];
    const float* bvec     = (const float*)d_in[20];
    const float* Wo       = (const float*)d_in[21];
    const float* bo       = (const float*)d_in[22];
    const float* W1       = (const float*)d_in[23];
    const float* b1       = (const float*)d_in[24];
    const float* W2       = (const float*)d_in[25];
    const float* b2       = (const float*)d_in[26];
    float* out = (float*)d_out;

    static __nv_bfloat16 *zp = nullptr, *aggp, *z2p, *hidp,
                         *wqkvp, *wop, *w1p, *w2p;
    static float *qkvp, *scp, *x1p, *bqkvp;
    static int *cntp, *offp, *curp, *eidp;
    if (!zp) {
        cudaGetSymbolAddress((void**)&zp,    g_z);
        cudaGetSymbolAddress((void**)&qkvp,  g_qkv);
        cudaGetSymbolAddress((void**)&scp,   g_score);
        cudaGetSymbolAddress((void**)&aggp,  g_agg);
        cudaGetSymbolAddress((void**)&x1p,   g_x1);
        cudaGetSymbolAddress((void**)&z2p,   g_z2);
        cudaGetSymbolAddress((void**)&hidp,  g_hid);
        cudaGetSymbolAddress((void**)&wqkvp, g_wqkv);
        cudaGetSymbolAddress((void**)&bqkvp, g_bqkv);
        cudaGetSymbolAddress((void**)&wop,   g_wo);
        cudaGetSymbolAddress((void**)&w1p,   g_w1);
        cudaGetSymbolAddress((void**)&w2p,   g_w2);
        cudaGetSymbolAddress((void**)&cntp,  g_cnt);
        cudaGetSymbolAddress((void**)&offp,  g_off);
        cudaGetSymbolAddress((void**)&curp,  g_cur);
        cudaGetSymbolAddress((void**)&eidp,  g_eid);
        cudaFuncSetAttribute(tgemm_kernel<0>,
            cudaFuncAttributeMaxDynamicSharedMemorySize, SMEM_BYTES);
        cudaFuncSetAttribute(tgemm_kernel<1>,
            cudaFuncAttributeMaxDynamicSharedMemorySize, SMEM_BYTES);
        cudaFuncSetAttribute(tgemm_kernel<2>,
            cudaFuncAttributeMaxDynamicSharedMemorySize, SMEM_BYTES);
    }

    // CSR build
    zero_cnt_kernel<<<(L + 255) / 256, 256>>>(cntp);
    hist_kernel<<<(E + 255) / 256, 256>>>(row_idx, cntp);
    scan_kernel<<<1, 1024>>>(cntp, offp, curp);
    scatter_kernel<<<(E + 255) / 256, 256>>>(row_idx, curp, eidp);

    // weight prep: transpose + bf16 convert to [N][K]
    dim3 tb(32, 8);
    transpose_bf16_kernel<<<dim3(C / 32, C / 32), tb>>>(Wq, wqkvp, C, C);
    transpose_bf16_kernel<<<dim3(C / 32, C / 32), tb>>>(Wk, wqkvp + (size_t)C * C, C, C);
    transpose_bf16_kernel<<<dim3(C / 32, C / 32), tb>>>(Wv, wqkvp + (size_t)2 * C * C, C, C);
    transpose_bf16_kernel<<<dim3(C / 32, C / 32), tb>>>(Wo, wop, C, C);
    transpose_bf16_kernel<<<dim3(HID / 32, C / 32), tb>>>(W1, w1p, C, HID);
    transpose_bf16_kernel<<<dim3(C / 32, HID / 32), tb>>>(W2, w2p, HID, C);
    pack_bias_kernel<<<(C + 255) / 256, 256>>>(bq, bk, bv, bqkvp);

    // LN1 -> bf16
    ln_kernel<<<L, 128>>>(x, ln1_g, ln1_b, zp);

    // fused QKV projection (bf16 MMA, fp32 out)
    dim3 gqkv(NQKV / BN, L / BM);
    tgemm_kernel<0><<<gqkv, 256, SMEM_BYTES>>>(zp, wqkvp, bqkvp, nullptr, qkvp,
                                               L, NQKV, C);

    // edge scores
    edge_score_kernel<<<E / 8, 256>>>(qkvp, row_idx, col_idx, pab, scp);

    // fused softmax + aggregation -> bf16 agg
    row_agg_kernel<<<L, 128>>>(qkvp, scp, offp, eidp, col_idx, tcol_idx,
                               dist, pos, col_pos, Wvec, bvec, aggp);

    // output projection + residual -> fp32 x1
    dim3 g512(C / BN, L / BM);
    tgemm_kernel<2><<<g512, 256, SMEM_BYTES>>>(aggp, wop, bo, x, x1p, L, C, C);

    // LN2 -> bf16
    ln_kernel<<<L, 128>>>(x1p, ln2_g, ln2_b, z2p);

    // FFN up + gelu -> bf16 hid
    dim3 g1024(HID / BN, L / BM);
    tgemm_kernel<1><<<g1024, 256, SMEM_BYTES>>>(z2p, w1p, b1, nullptr,
                                                (float*)hidp, L, HID, C);

    // FFN down + residual -> fp32 out
    tgemm_kernel<2><<<g512, 256, SMEM_BYTES>>>(hidp, w2p, b2, x1p, out,
                                               L, C, HID);
}

// round 7
// speedup vs baseline: 4.2605x; 1.0084x over previous
#include <cuda_runtime.h>
#include <cuda_bf16.h>
#include <math.h>
#include <stdint.h>

// Problem constants
#define L   16384
#define E   131072
#define SP  20000
#define C   512
#define H   8
#define DH  64
#define HID 1024
#define NQKV 1536

// ---------------- scratch (device globals: allocation-free) ----------------
__device__ __nv_bfloat16 g_z[(size_t)L * C];
__device__ float         g_qkv[(size_t)L * NQKV];
__device__ __nv_bfloat16 g_agg[(size_t)L * C];
__device__ float         g_x1[(size_t)L * C];
__device__ __nv_bfloat16 g_z2[(size_t)L * C];
__device__ __nv_bfloat16 g_hid[(size_t)L * HID];
// transposed bf16 weights: [N][K]
__device__ __nv_bfloat16 g_wqkv[(size_t)NQKV * C];
__device__ float         g_bqkv[NQKV];
__device__ __nv_bfloat16 g_wo[(size_t)C * C];
__device__ __nv_bfloat16 g_w1[(size_t)HID * C];
__device__ __nv_bfloat16 g_w2[(size_t)C * HID];
// CSR
__device__ int g_cnt[L];
__device__ int g_off[L + 1];
__device__ int g_cur[L];
__device__ int g_eid[E];

// ---------------- helpers ----------------
__device__ __forceinline__ float gelu_tanh(float x) {
    const float k0 = 0.7978845608028654f;
    const float k1 = 0.044715f;
    float x3 = x * x * x;
    return 0.5f * x * (1.0f + tanhf(k0 * (x + k1 * x3)));
}

__device__ __forceinline__ void mma_bf16(float* d, const uint32_t* a,
                                         const uint32_t* b) {
    asm volatile(
        "mma.sync.aligned.m16n8k16.row.col.f32.bf16.bf16.f32 "
        "{%0,%1,%2,%3}, {%4,%5,%6,%7}, {%8,%9}, {%0,%1,%2,%3};\n"
        : "+f"(d[0]), "+f"(d[1]), "+f"(d[2]), "+f"(d[3])
        : "r"(a[0]), "r"(a[1]), "r"(a[2]), "r"(a[3]),
          "r"(b[0]), "r"(b[1]));
}

__device__ __forceinline__ void ldsm_x4(uint32_t* r, uint32_t addr) {
    asm volatile(
        "ldmatrix.sync.aligned.m8n8.x4.shared.b16 {%0,%1,%2,%3}, [%4];\n"
        : "=r"(r[0]), "=r"(r[1]), "=r"(r[2]), "=r"(r[3]) : "r"(addr));
}

__device__ __forceinline__ void cp16(uint32_t dst, const void* src) {
    asm volatile("cp.async.cg.shared.global [%0], [%1], 16;\n"
                 :: "r"(dst), "l"(src));
}
__device__ __forceinline__ void cp_commit() {
    asm volatile("cp.async.commit_group;\n");
}
template <int N>
__device__ __forceinline__ void cp_wait() {
    asm volatile("cp.async.wait_group %0;\n" :: "n"(N));
}
__device__ __forceinline__ uint32_t smem_u32(const void* p) {
    uint32_t a;
    asm("{ .reg .u64 t; cvta.to.shared.u64 t, %1; cvt.u32.u64 %0, t; }"
        : "=r"(a) : "l"(p));
    return a;
}

// swizzled byte offset of 16B chunk c (0..3) in logical row r (64B rows,
// packed 2 per 128B physical row)
__device__ __forceinline__ uint32_t sw_off(int r, int c) {
    return (uint32_t)((r >> 1) * 128 + ((((c + 4 * (r & 1))) ^ ((r >> 1) & 7)) << 4));
}

// ---------------- weight prep: all 6 transposes in one launch -------------
// z: 0..2 -> Wq/Wk/Wv into g_wqkv, 3 -> Wo, 4 -> W1, 5 -> W2
__global__ void transpose_all_kernel(const float* __restrict__ Wq,
                                     const float* __restrict__ Wk,
                                     const float* __restrict__ Wv,
                                     const float* __restrict__ Wo,
                                     const float* __restrict__ W1,
                                     const float* __restrict__ W2,
                                     __nv_bfloat16* __restrict__ wqkv,
                                     __nv_bfloat16* __restrict__ wo,
                                     __nv_bfloat16* __restrict__ w1,
                                     __nv_bfloat16* __restrict__ w2) {
    int z = blockIdx.z;
    const float* src;
    __nv_bfloat16* dst;
    int Kd, Nd;
    if (z == 0)      { src = Wq; dst = wqkv;                     Kd = C;   Nd = C; }
    else if (z == 1) { src = Wk; dst = wqkv + (size_t)C * C;     Kd = C;   Nd = C; }
    else if (z == 2) { src = Wv; dst = wqkv + (size_t)2 * C * C; Kd = C;   Nd = C; }
    else if (z == 3) { src = Wo; dst = wo;                       Kd = C;   Nd = C; }
    else if (z == 4) { src = W1; dst = w1;                       Kd = C;   Nd = HID; }
    else             { src = W2; dst = w2;                       Kd = HID; Nd = C; }
    int kb = blockIdx.y * 32, nb = blockIdx.x * 32;
    if (kb >= Kd || nb >= Nd) return;
    __shared__ float tile[32][33];
    int tx = threadIdx.x, ty = threadIdx.y;   // 32x8
    #pragma unroll
    for (int i = ty; i < 32; i += 8)
        tile[i][tx] = src[(size_t)(kb + i) * Nd + nb + tx];
    __syncthreads();
    #pragma unroll
    for (int i = ty; i < 32; i += 8)
        dst[(size_t)(nb + i) * Kd + kb + tx] = __float2bfloat16_rn(tile[tx][i]);
}

__global__ void pack_bias_kernel(const float* __restrict__ bq,
                                 const float* __restrict__ bk,
                                 const float* __restrict__ bv,
                                 float* __restrict__ b) {
    int i = blockIdx.x * blockDim.x + threadIdx.x;
    if (i < C) { b[i] = bq[i]; b[C + i] = bk[i]; b[2 * C + i] = bv[i]; }
}

// ---------------- LayerNorm (bf16 output) ----------------
__global__ void ln_kernel(const float* __restrict__ x,
                          const float* __restrict__ g,
                          const float* __restrict__ b,
                          __nv_bfloat16* __restrict__ z) {
    int row = blockIdx.x;
    int t = threadIdx.x;                 // 0..127
    const float* xr = x + (size_t)row * C;
    float4 v4 = *(const float4*)(xr + t * 4);
    float s  = v4.x + v4.y + v4.z + v4.w;
    float ss = v4.x * v4.x + v4.y * v4.y + v4.z * v4.z + v4.w * v4.w;
    #pragma unroll
    for (int o = 16; o > 0; o >>= 1) {
        s  += __shfl_xor_sync(0xffffffffu, s, o);
        ss += __shfl_xor_sync(0xffffffffu, ss, o);
    }
    __shared__ float sh[4], sh2[4];
    int w = t >> 5;
    if ((t & 31) == 0) { sh[w] = s; sh2[w] = ss; }
    __syncthreads();
    float sum  = sh[0] + sh[1] + sh[2] + sh[3];
    float sum2 = sh2[0] + sh2[1] + sh2[2] + sh2[3];
    float mean = sum * (1.0f / C);
    float var  = sum2 * (1.0f / C) - mean * mean;
    float inv  = rsqrtf(var + 1e-5f);
    float4 g4 = *(const float4*)(g + t * 4);
    float4 b4 = *(const float4*)(b + t * 4);
    __nv_bfloat162 p0 = __floats2bfloat162_rn(
        (v4.x - mean) * inv * g4.x + b4.x, (v4.y - mean) * inv * g4.y + b4.y);
    __nv_bfloat162 p1 = __floats2bfloat162_rn(
        (v4.z - mean) * inv * g4.z + b4.z, (v4.w - mean) * inv * g4.w + b4.w);
    __nv_bfloat162* zr = (__nv_bfloat162*)(z + (size_t)row * C);
    zr[t * 2]     = p0;
    zr[t * 2 + 1] = p1;
}

// ---------------- bf16 tensor-core GEMM (unchanged from R6) ---------------
#define BM  128
#define BN  128
#define BK  32
#define STAGES 4
#define STAGE_BYTES 8192
#define SMEM_BYTES (STAGES * 2 * STAGE_BYTES)   // 65536

template <int EPI>
__global__ __launch_bounds__(256, 2)
void tgemm_kernel(const __nv_bfloat16* __restrict__ A,
                  const __nv_bfloat16* __restrict__ B,
                  const float* __restrict__ bias, const float* __restrict__ res,
                  float* __restrict__ Cmat, int M, int N, int K) {
    extern __shared__ float smemf[];
    const uint32_t sA = smem_u32(smemf);
    const uint32_t sB = sA + STAGES * STAGE_BYTES;

    const int tid    = threadIdx.x;
    const int lane   = tid & 31;
    const int wid    = tid >> 5;
    const int warp_m = wid & 3;
    const int warp_n = wid >> 2;

    const int brow = blockIdx.y * BM;
    const int bcol = blockIdx.x * BN;

    float acc[2][8][4];
    #pragma unroll
    for (int i = 0; i < 2; i++)
        #pragma unroll
        for (int j = 0; j < 8; j++)
            #pragma unroll
            for (int c = 0; c < 4; c++) acc[i][j][c] = 0.0f;

    const int lr = tid >> 1;
    const int c0 = (tid & 1) * 2;
    const __nv_bfloat16* A0 = A + (size_t)(brow + lr) * K + c0 * 8;
    const __nv_bfloat16* B0 = B + (size_t)(bcol + lr) * K + c0 * 8;
    const uint32_t dA0 = sA + sw_off(lr, c0);
    const uint32_t dA1 = sA + sw_off(lr, c0 + 1);
    const uint32_t dB0 = sB + sw_off(lr, c0);
    const uint32_t dB1 = sB + sw_off(lr, c0 + 1);

    const int m8    = lane >> 3;
    const int rowin = lane & 7;
    int rA[2], cAh = m8 >> 1;
    rA[0] = warp_m * 32 + (m8 & 1) * 8 + rowin;
    rA[1] = rA[0] + 16;
    int rB[4], cBh = m8 & 1;
    #pragma unroll
    for (int np = 0; np < 4; np++)
        rB[np] = warp_n * 64 + np * 16 + (m8 >> 1) * 8 + rowin;

    const int kIters = K / BK;

    #pragma unroll
    for (int s = 0; s < STAGES - 1; s++) {
        int k0 = s * BK;
        uint32_t so = (uint32_t)s * STAGE_BYTES;
        cp16(dA0 + so, A0 + k0);
        cp16(dA1 + so, A0 + k0 + 8);
        cp16(dB0 + so, B0 + k0);
        cp16(dB1 + so, B0 + k0 + 8);
        cp_commit();
    }

    int buf = 0;
    int nbuf = STAGES - 1;
    for (int s = 0; s < kIters; s++) {
        cp_wait<STAGES - 2>();
        __syncthreads();

        if (s + STAGES - 1 < kIters) {
            int k0 = (s + STAGES - 1) * BK;
            uint32_t so = (uint32_t)nbuf * STAGE_BYTES;
            cp16(dA0 + so, A0 + k0);
            cp16(dA1 + so, A0 + k0 + 8);
            cp16(dB0 + so, B0 + k0);
            cp16(dB1 + so, B0 + k0 + 8);
        }
        cp_commit();

        const uint32_t aBuf = sA + (uint32_t)buf * STAGE_BYTES;
        const uint32_t bBuf = sB + (uint32_t)buf * STAGE_BYTES;
        #pragma unroll
        for (int ks = 0; ks < 2; ks++) {
            uint32_t af[2][4];
            #pragma unroll
            for (int mt = 0; mt < 2; mt++)
                ldsm_x4(af[mt], aBuf + sw_off(rA[mt], 2 * ks + cAh));
            #pragma unroll
            for (int np = 0; np < 4; np++) {
                uint32_t bf[4];
                ldsm_x4(bf, bBuf + sw_off(rB[np], 2 * ks + cBh));
                mma_bf16(acc[0][2 * np],     af[0], bf);
                mma_bf16(acc[1][2 * np],     af[1], bf);
                mma_bf16(acc[0][2 * np + 1], af[0], bf + 2);
                mma_bf16(acc[1][2 * np + 1], af[1], bf + 2);
            }
        }
        buf = (buf + 1 == STAGES) ? 0 : buf + 1;
        nbuf = (nbuf + 1 == STAGES) ? 0 : nbuf + 1;
    }

    const int grp = lane >> 2;
    const int t4  = lane & 3;
    #pragma unroll
    for (int mt = 0; mt < 2; mt++) {
        int row = brow + warp_m * 32 + mt * 16 + grp;
        #pragma unroll
        for (int nt = 0; nt < 8; nt++) {
            int col = bcol + warp_n * 64 + nt * 8 + 2 * t4;
            float b0 = bias[col], b1 = bias[col + 1];
            float v0 = acc[mt][nt][0] + b0;
            float v1 = acc[mt][nt][1] + b1;
            float v2 = acc[mt][nt][2] + b0;
            float v3 = acc[mt][nt][3] + b1;
            if (EPI == 1) {
                __nv_bfloat16* O = (__nv_bfloat16*)Cmat;
                __nv_bfloat162 o0 = __floats2bfloat162_rn(gelu_tanh(v0),
                                                          gelu_tanh(v1));
                __nv_bfloat162 o1 = __floats2bfloat162_rn(gelu_tanh(v2),
                                                          gelu_tanh(v3));
                *(__nv_bfloat162*)&O[(size_t)row * N + col]       = o0;
                *(__nv_bfloat162*)&O[(size_t)(row + 8) * N + col] = o1;
            } else {
                if (EPI == 2) {
                    v0 += res[(size_t)row * N + col];
                    v1 += res[(size_t)row * N + col + 1];
                    v2 += res[(size_t)(row + 8) * N + col];
                    v3 += res[(size_t)(row + 8) * N + col + 1];
                }
                float2 o0 = { v0, v1 };
                float2 o1 = { v2, v3 };
                *(float2*)&Cmat[(size_t)row * N + col]       = o0;
                *(float2*)&Cmat[(size_t)(row + 8) * N + col] = o1;
            }
        }
    }
}

// ---------------- CSR build ----------------
__global__ void zero_cnt_kernel(int* __restrict__ cnt) {
    int i = blockIdx.x * blockDim.x + threadIdx.x;
    if (i < L) cnt[i] = 0;
}
__global__ void hist_kernel(const int* __restrict__ row, int* __restrict__ cnt) {
    int e = blockIdx.x * blockDim.x + threadIdx.x;
    if (e < E) atomicAdd(&cnt[row[e]], 1);
}
__global__ void scan_kernel(const int* __restrict__ cnt, int* __restrict__ off,
                            int* __restrict__ cur) {
    __shared__ int ws[32];
    int tid = threadIdx.x;
    int base = tid * 16;
    int loc[16];
    int s = 0;
    #pragma unroll
    for (int i = 0; i < 16; i++) { loc[i] = s; s += cnt[base + i]; }
    int lane = tid & 31, w = tid >> 5;
    int v = s;
    #pragma unroll
    for (int o = 1; o < 32; o <<= 1) {
        int t = __shfl_up_sync(0xffffffffu, v, o);
        if (lane >= o) v += t;
    }
    if (lane == 31) ws[w] = v;
    __syncthreads();
    if (w == 0) {
        int t = ws[lane];
        #pragma unroll
        for (int o = 1; o < 32; o <<= 1) {
            int u = __shfl_up_sync(0xffffffffu, t, o);
            if (lane >= o) t += u;
        }
        ws[lane] = t;
    }
    __syncthreads();
    int excl = v - s + (w > 0 ? ws[w - 1] : 0);
    #pragma unroll
    for (int i = 0; i < 16; i++) {
        off[base + i] = excl + loc[i];
        cur[base + i] = excl + loc[i];
    }
    if (tid == 1023) off[L] = excl + s;
}
__global__ void scatter_kernel(const int* __restrict__ row,
                               int* __restrict__ cur, int* __restrict__ eid) {
    int e = blockIdx.x * blockDim.x + threadIdx.x;
    if (e < E) {
        int p = atomicAdd(&cur[row[e]], 1);
        eid[p] = e;
    }
}

// ---------------- fused edge score + softmax + aggregation ----------------
// One block (128 thr) per row. Scores computed in-kernel; pexp cached in smem.
#define DMAX 384
__global__ __launch_bounds__(128)
void row_attn_kernel(const float* __restrict__ qkv,
                     const int* __restrict__ off,
                     const int* __restrict__ eid,
                     const int* __restrict__ col_index,
                     const int* __restrict__ to_col_index,
                     const float* __restrict__ pab,
                     const float* __restrict__ dist,
                     const float* __restrict__ pos,
                     const float* __restrict__ col_pos,
                     const float* __restrict__ Wvec,
                     const float* __restrict__ bvec,
                     __nv_bfloat16* __restrict__ agg) {
    int r = blockIdx.x;
    int tid = threadIdx.x;          // 128
    int lane = tid & 31;
    int w = tid >> 5;               // warp 0..3
    int beg = off[r];
    int deg = off[r + 1] - beg;

    __shared__ float s_q[C];              // 2KB
    __shared__ float s_den[H];
    __shared__ float s_px[DMAX][H];       // pexp cache (12KB)
    __shared__ float s_mt[DMAX][4];       // ci(bits), rx, ry, rz (6KB)

    // load q[r] and row position
    for (int i = tid; i < C / 4; i += 128)
        ((float4*)s_q)[i] = ((const float4*)(qkv + (size_t)r * NQKV))[i];
    if (tid < H) s_den[tid] = 0.0f;
    __syncthreads();

    float px0 = pos[r * 3 + 0], px1 = pos[r * 3 + 1], px2 = pos[r * 3 + 2];

    // ---- pass 1: scores for all edges; accumulate den; cache <DMAX ----
    for (int i0 = w; i0 < deg; i0 += 4) {
        int e = eid[beg + i0];
        int ci = col_index[e];
        const float* kr = qkv + (size_t)ci * NQKV + C;
        float sc[H];
        #pragma unroll
        for (int h = 0; h < H; h++) {
            float d0 = s_q[h * DH + lane]      - kr[h * DH + lane];
            float d1 = s_q[h * DH + 32 + lane] - kr[h * DH + 32 + lane];
            float s = d0 * d0 + d1 * d1;
            #pragma unroll
            for (int o = 16; o > 0; o >>= 1)
                s += __shfl_xor_sync(0xffffffffu, s, o);
            sc[h] = s;
        }
        if (lane < H) {
            float val = __expf(-sc[lane] * 0.125f + pab[(size_t)e * H + lane]);
            atomicAdd(&s_den[lane], val);
            if (i0 < DMAX) s_px[i0][lane] = val;
        }
        if (lane == 8 && i0 < DMAX) {
            int tci = to_col_index[e];
            float dinv = 1.0f / dist[e];
            s_mt[i0][0] = __int_as_float(ci);
            s_mt[i0][1] = (col_pos[tci * 3 + 0] - px0) * dinv;
            s_mt[i0][2] = (col_pos[tci * 3 + 1] - px1) * dinv;
            s_mt[i0][3] = (col_pos[tci * 3 + 2] - px2) * dinv;
        }
    }
    __syncthreads();
    if (tid < H) {
        float d = s_den[tid];
        s_den[tid] = (d == 0.0f) ? 1.0f : 1.0f / d;
    }
    __syncthreads();

    // ---- pass 2: channel-parallel aggregation ----
    int c0 = tid * 4;
    int hh = c0 >> 6;
    float4 wv0 = *(const float4*)(Wvec + c0);
    float4 wv1 = *(const float4*)(Wvec + C + c0);
    float4 wv2 = *(const float4*)(Wvec + 2 * C + c0);
    float4 bv  = *(const float4*)(bvec + c0);
    float dinvh = s_den[hh];

    float a0 = 0.0f, a1 = 0.0f, a2 = 0.0f, a3 = 0.0f;
    int ncache = deg < DMAX ? deg : DMAX;
    for (int i = 0; i < ncache; i++) {
        int ci = __float_as_int(s_mt[i][0]);
        float rx = s_mt[i][1], ry = s_mt[i][2], rz = s_mt[i][3];
        float al = s_px[i][hh] * dinvh;
        float4 v4 = *(const float4*)(qkv + (size_t)ci * NQKV + 2 * C + c0);
        a0 += al * (v4.x + rx * wv0.x + ry * wv1.x + rz * wv2.x + bv.x);
        a1 += al * (v4.y + rx * wv0.y + ry * wv1.y + rz * wv2.y + bv.y);
        a2 += al * (v4.z + rx * wv0.z + ry * wv1.z + rz * wv2.z + bv.z);
        a3 += al * (v4.w + rx * wv0.w + ry * wv1.w + rz * wv2.w + bv.w);
    }
    // overflow fallback (deg > DMAX): recompute scores in chunks of 16
    for (int base = DMAX; base < deg; base += 16) {
        int n = min(16, deg - base);
        __syncthreads();
        for (int j = w; j < n; j += 4) {
            int e = eid[beg + base + j];
            int ci = col_index[e];
            const float* kr = qkv + (size_t)ci * NQKV + C;
            float sc[H];
            #pragma unroll
            for (int h = 0; h < H; h++) {
                float d0 = s_q[h * DH + lane]      - kr[h * DH + lane];
                float d1 = s_q[h * DH + 32 + lane] - kr[h * DH + 32 + lane];
                float s = d0 * d0 + d1 * d1;
                #pragma unroll
                for (int o = 16; o > 0; o >>= 1)
                    s += __shfl_xor_sync(0xffffffffu, s, o);
                sc[h] = s;
            }
            if (lane < H)
                s_px[j][lane] = __expf(-sc[lane] * 0.125f + pab[(size_t)e * H + lane]);
            if (lane == 8) {
                int tci = to_col_index[e];
                float dinv = 1.0f / dist[e];
                s_mt[j][0] = __int_as_float(ci);
                s_mt[j][1] = (col_pos[tci * 3 + 0] - px0) * dinv;
                s_mt[j][2] = (col_pos[tci * 3 + 1] - px1) * dinv;
                s_mt[j][3] = (col_pos[tci * 3 + 2] - px2) * dinv;
            }
        }
        __syncthreads();
        for (int i = 0; i < n; i++) {
            int ci = __float_as_int(s_mt[i][0]);
            float rx = s_mt[i][1], ry = s_mt[i][2], rz = s_mt[i][3];
            float al = s_px[i][hh] * dinvh;
            float4 v4 = *(const float4*)(qkv + (size_t)ci * NQKV + 2 * C + c0);
            a0 += al * (v4.x + rx * wv0.x + ry * wv1.x + rz * wv2.x + bv.x);
            a1 += al * (v4.y + rx * wv0.y + ry * wv1.y + rz * wv2.y + bv.y);
            a2 += al * (v4.z + rx * wv0.z + ry * wv1.z + rz * wv2.z + bv.z);
            a3 += al * (v4.w + rx * wv0.w + ry * wv1.w + rz * wv2.w + bv.w);
        }
    }

    __nv_bfloat162 o0 = __floats2bfloat162_rn(a0, a1);
    __nv_bfloat162 o1 = __floats2bfloat162_rn(a2, a3);
    __nv_bfloat162* ar = (__nv_bfloat162*)(agg + (size_t)r * C);
    ar[tid * 2]     = o0;
    ar[tid * 2 + 1] = o1;
}

// ---------------- launcher ----------------
extern "C" void kernel_launch(void* const* d_in, const int* in_sizes, int n_in,
                              void* d_out, int out_size) {
    const float* x        = (const float*)d_in[0];
    const int*   row_idx  = (const int*)  d_in[1];
    const int*   col_idx  = (const int*)  d_in[2];
    const int*   tcol_idx = (const int*)  d_in[3];
    const float* pab      = (const float*)d_in[5];
    const float* dist     = (const float*)d_in[6];
    const float* pos      = (const float*)d_in[7];
    const float* col_pos  = (const float*)d_in[8];
    const float* ln1_g    = (const float*)d_in[9];
    const float* ln1_b    = (const float*)d_in[10];
    const float* ln2_g    = (const float*)d_in[11];
    const float* ln2_b    = (const float*)d_in[12];
    const float* Wq       = (const float*)d_in[13];
    const float* bq       = (const float*)d_in[14];
    const float* Wk       = (const float*)d_in[15];
    const float* bk       = (const float*)d_in[16];
    const float* Wv       = (const float*)d_in[17];
    const float* bv       = (const float*)d_in[18];
    const float* Wvec     = (const float*)d_in[19];
    const float* bvec     = (const float*)d_in[20];
    const float* Wo       = (const float*)d_in[21];
    const float* bo       = (const float*)d_in[22];
    const float* W1       = (const float*)d_in[23];
    const float* b1       = (const float*)d_in[24];
    const float* W2       = (const float*)d_in[25];
    const float* b2       = (const float*)d_in[26];
    float* out = (float*)d_out;

    static __nv_bfloat16 *zp = nullptr, *aggp, *z2p, *hidp,
                         *wqkvp, *wop, *w1p, *w2p;
    static float *qkvp, *x1p, *bqkvp;
    static int *cntp, *offp, *curp, *eidp;
    if (!zp) {
        cudaGetSymbolAddress((void**)&zp,    g_z);
        cudaGetSymbolAddress((void**)&qkvp,  g_qkv);
        cudaGetSymbolAddress((void**)&aggp,  g_agg);
        cudaGetSymbolAddress((void**)&x1p,   g_x1);
        cudaGetSymbolAddress((void**)&z2p,   g_z2);
        cudaGetSymbolAddress((void**)&hidp,  g_hid);
        cudaGetSymbolAddress((void**)&wqkvp, g_wqkv);
        cudaGetSymbolAddress((void**)&bqkvp, g_bqkv);
        cudaGetSymbolAddress((void**)&wop,   g_wo);
        cudaGetSymbolAddress((void**)&w1p,   g_w1);
        cudaGetSymbolAddress((void**)&w2p,   g_w2);
        cudaGetSymbolAddress((void**)&cntp,  g_cnt);
        cudaGetSymbolAddress((void**)&offp,  g_off);
        cudaGetSymbolAddress((void**)&curp,  g_cur);
        cudaGetSymbolAddress((void**)&eidp,  g_eid);
        cudaFuncSetAttribute(tgemm_kernel<0>,
            cudaFuncAttributeMaxDynamicSharedMemorySize, SMEM_BYTES);
        cudaFuncSetAttribute(tgemm_kernel<1>,
            cudaFuncAttributeMaxDynamicSharedMemorySize, SMEM_BYTES);
        cudaFuncSetAttribute(tgemm_kernel<2>,
            cudaFuncAttributeMaxDynamicSharedMemorySize, SMEM_BYTES);
    }

    // CSR build
    zero_cnt_kernel<<<(L + 255) / 256, 256>>>(cntp);
    hist_kernel<<<(E + 255) / 256, 256>>>(row_idx, cntp);
    scan_kernel<<<1, 1024>>>(cntp, offp, curp);
    scatter_kernel<<<(E + 255) / 256, 256>>>(row_idx, curp, eidp);

    // weight prep: all transposes in one launch
    transpose_all_kernel<<<dim3(32, 32, 6), dim3(32, 8)>>>(
        Wq, Wk, Wv, Wo, W1, W2, wqkvp, wop, w1p, w2p);
    pack_bias_kernel<<<(C + 255) / 256, 256>>>(bq, bk, bv, bqkvp);

    // LN1 -> bf16
    ln_kernel<<<L, 128>>>(x, ln1_g, ln1_b, zp);

    // fused QKV projection (bf16 MMA, fp32 out)
    dim3 gqkv(NQKV / BN, L / BM);
    tgemm_kernel<0><<<gqkv, 256, SMEM_BYTES>>>(zp, wqkvp, bqkvp, nullptr, qkvp,
                                               L, NQKV, C);

    // fused edge score + softmax + aggregation -> bf16 agg
    row_attn_kernel<<<L, 128>>>(qkvp, offp, eidp, col_idx, tcol_idx,
                                pab, dist, pos, col_pos, Wvec, bvec, aggp);

    // output projection + residual -> fp32 x1
    dim3 g512(C / BN, L / BM);
    tgemm_kernel<2><<<g512, 256, SMEM_BYTES>>>(aggp, wop, bo, x, x1p, L, C, C);

    // LN2 -> bf16
    ln_kernel<<<L, 128>>>(x1p, ln2_g, ln2_b, z2p);

    // FFN up + gelu -> bf16 hid
    dim3 g1024(HID / BN, L / BM);
    tgemm_kernel<1><<<g1024, 256, SMEM_BYTES>>>(z2p, w1p, b1, nullptr,
                                                (float*)hidp, L, HID, C);

    // FFN down + residual -> fp32 out
    tgemm_kernel<2><<<g512, 256, SMEM_BYTES>>>(hidp, w2p, b2, x1p, out,
                                               L, C, HID);
}

// round 9
// speedup vs baseline: 4.2977x; 1.0087x over previous
#include <cuda_runtime.h>
#include <cuda_bf16.h>
#include <math.h>
#include <stdint.h>

// Problem constants
#define L   16384
#define E   131072
#define SP  20000
#define C   512
#define H   8
#define DH  64
#define HID 1024
#define NQKV 1536

// ---------------- scratch (device globals: allocation-free) ----------------
__device__ __nv_bfloat16 g_z[(size_t)L * C];
__device__ float         g_qkv[(size_t)L * NQKV];
__device__ __nv_bfloat16 g_agg[(size_t)L * C];
__device__ float         g_x1[(size_t)L * C];
__device__ __nv_bfloat16 g_z2[(size_t)L * C];
__device__ __nv_bfloat16 g_hid[(size_t)L * HID];
// transposed bf16 weights: [N][K]
__device__ __nv_bfloat16 g_wqkv[(size_t)NQKV * C];
__device__ float         g_bqkv[NQKV];
__device__ __nv_bfloat16 g_wo[(size_t)C * C];
__device__ __nv_bfloat16 g_w1[(size_t)HID * C];
__device__ __nv_bfloat16 g_w2[(size_t)C * HID];
// CSR
__device__ int g_cnt[L];
__device__ int g_off[L + 1];
__device__ int g_cur[L];
__device__ int g_eid[E];

// ---------------- helpers ----------------
__device__ __forceinline__ float gelu_tanh(float x) {
    const float k0 = 0.7978845608028654f;
    const float k1 = 0.044715f;
    float x3 = x * x * x;
    return 0.5f * x * (1.0f + tanhf(k0 * (x + k1 * x3)));
}

__device__ __forceinline__ void mma_bf16(float* d, const uint32_t* a,
                                         const uint32_t* b) {
    asm volatile(
        "mma.sync.aligned.m16n8k16.row.col.f32.bf16.bf16.f32 "
        "{%0,%1,%2,%3}, {%4,%5,%6,%7}, {%8,%9}, {%0,%1,%2,%3};\n"
        : "+f"(d[0]), "+f"(d[1]), "+f"(d[2]), "+f"(d[3])
        : "r"(a[0]), "r"(a[1]), "r"(a[2]), "r"(a[3]),
          "r"(b[0]), "r"(b[1]));
}

__device__ __forceinline__ void ldsm_x4(uint32_t* r, uint32_t addr) {
    asm volatile(
        "ldmatrix.sync.aligned.m8n8.x4.shared.b16 {%0,%1,%2,%3}, [%4];\n"
        : "=r"(r[0]), "=r"(r[1]), "=r"(r[2]), "=r"(r[3]) : "r"(addr));
}

__device__ __forceinline__ void cp16(uint32_t dst, const void* src) {
    asm volatile("cp.async.cg.shared.global [%0], [%1], 16;\n"
                 :: "r"(dst), "l"(src));
}
__device__ __forceinline__ void cp_commit() {
    asm volatile("cp.async.commit_group;\n");
}
template <int N>
__device__ __forceinline__ void cp_wait() {
    asm volatile("cp.async.wait_group %0;\n" :: "n"(N));
}
__device__ __forceinline__ uint32_t smem_u32(const void* p) {
    uint32_t a;
    asm("{ .reg .u64 t; cvta.to.shared.u64 t, %1; cvt.u32.u64 %0, t; }"
        : "=r"(a) : "l"(p));
    return a;
}

// swizzled byte offset of 16B chunk c (0..3) in logical row r (64B rows,
// packed 2 per 128B physical row)
__device__ __forceinline__ uint32_t sw_off(int r, int c) {
    return (uint32_t)((r >> 1) * 128 + ((((c + 4 * (r & 1))) ^ ((r >> 1) & 7)) << 4));
}

// ---------------- weight prep: all 6 transposes + bias pack ---------------
__global__ void transpose_all_kernel(const float* __restrict__ Wq,
                                     const float* __restrict__ Wk,
                                     const float* __restrict__ Wv,
                                     const float* __restrict__ Wo,
                                     const float* __restrict__ W1,
                                     const float* __restrict__ W2,
                                     const float* __restrict__ bq,
                                     const float* __restrict__ bk,
                                     const float* __restrict__ bv,
                                     __nv_bfloat16* __restrict__ wqkv,
                                     __nv_bfloat16* __restrict__ wo,
                                     __nv_bfloat16* __restrict__ w1,
                                     __nv_bfloat16* __restrict__ w2,
                                     float* __restrict__ bqkv) {
    int z = blockIdx.z;
    // bias pack piggybacks on z==0 plane (16 blocks of 256 lanes cover C=512)
    if (z == 0) {
        int bid = blockIdx.y * gridDim.x + blockIdx.x;
        int i = bid * 256 + threadIdx.y * 32 + threadIdx.x;
        if (i < C) {
            bqkv[i]         = bq[i];
            bqkv[C + i]     = bk[i];
            bqkv[2 * C + i] = bv[i];
        }
    }
    const float* src;
    __nv_bfloat16* dst;
    int Kd, Nd;
    if (z == 0)      { src = Wq; dst = wqkv;                     Kd = C;   Nd = C; }
    else if (z == 1) { src = Wk; dst = wqkv + (size_t)C * C;     Kd = C;   Nd = C; }
    else if (z == 2) { src = Wv; dst = wqkv + (size_t)2 * C * C; Kd = C;   Nd = C; }
    else if (z == 3) { src = Wo; dst = wo;                       Kd = C;   Nd = C; }
    else if (z == 4) { src = W1; dst = w1;                       Kd = C;   Nd = HID; }
    else             { src = W2; dst = w2;                       Kd = HID; Nd = C; }
    int kb = blockIdx.y * 32, nb = blockIdx.x * 32;
    if (kb >= Kd || nb >= Nd) return;
    __shared__ float tile[32][33];
    int tx = threadIdx.x, ty = threadIdx.y;   // 32x8
    #pragma unroll
    for (int i = ty; i < 32; i += 8)
        tile[i][tx] = src[(size_t)(kb + i) * Nd + nb + tx];
    __syncthreads();
    #pragma unroll
    for (int i = ty; i < 32; i += 8)
        dst[(size_t)(nb + i) * Kd + kb + tx] = __float2bfloat16_rn(tile[tx][i]);
}

// ---------------- LayerNorm (bf16 output) ----------------
__global__ void ln_kernel(const float* __restrict__ x,
                          const float* __restrict__ g,
                          const float* __restrict__ b,
                          __nv_bfloat16* __restrict__ z) {
    int row = blockIdx.x;
    int t = threadIdx.x;                 // 0..127
    const float* xr = x + (size_t)row * C;
    float4 v4 = *(const float4*)(xr + t * 4);
    float s  = v4.x + v4.y + v4.z + v4.w;
    float ss = v4.x * v4.x + v4.y * v4.y + v4.z * v4.z + v4.w * v4.w;
    #pragma unroll
    for (int o = 16; o > 0; o >>= 1) {
        s  += __shfl_xor_sync(0xffffffffu, s, o);
        ss += __shfl_xor_sync(0xffffffffu, ss, o);
    }
    __shared__ float sh[4], sh2[4];
    int w = t >> 5;
    if ((t & 31) == 0) { sh[w] = s; sh2[w] = ss; }
    __syncthreads();
    float sum  = sh[0] + sh[1] + sh[2] + sh[3];
    float sum2 = sh2[0] + sh2[1] + sh2[2] + sh2[3];
    float mean = sum * (1.0f / C);
    float var  = sum2 * (1.0f / C) - mean * mean;
    float inv  = rsqrtf(var + 1e-5f);
    float4 g4 = *(const float4*)(g + t * 4);
    float4 b4 = *(const float4*)(b + t * 4);
    __nv_bfloat162 p0 = __floats2bfloat162_rn(
        (v4.x - mean) * inv * g4.x + b4.x, (v4.y - mean) * inv * g4.y + b4.y);
    __nv_bfloat162 p1 = __floats2bfloat162_rn(
        (v4.z - mean) * inv * g4.z + b4.z, (v4.w - mean) * inv * g4.w + b4.w);
    __nv_bfloat162* zr = (__nv_bfloat162*)(z + (size_t)row * C);
    zr[t * 2]     = p0;
    zr[t * 2 + 1] = p1;
}

// ---------------- bf16 tensor-core GEMM (validated R6 design) -------------
#define BM  128
#define BN  128
#define BK  32
#define STAGES 4
#define STAGE_BYTES 8192
#define SMEM_BYTES (STAGES * 2 * STAGE_BYTES)   // 65536

template <int EPI>
__global__ __launch_bounds__(256, 2)
void tgemm_kernel(const __nv_bfloat16* __restrict__ A,
                  const __nv_bfloat16* __restrict__ B,
                  const float* __restrict__ bias, const float* __restrict__ res,
                  float* __restrict__ Cmat, int M, int N, int K) {
    extern __shared__ float smemf[];
    const uint32_t sA = smem_u32(smemf);
    const uint32_t sB = sA + STAGES * STAGE_BYTES;

    const int tid    = threadIdx.x;
    const int lane   = tid & 31;
    const int wid    = tid >> 5;
    const int warp_m = wid & 3;
    const int warp_n = wid >> 2;

    const int brow = blockIdx.y * BM;
    const int bcol = blockIdx.x * BN;

    float acc[2][8][4];
    #pragma unroll
    for (int i = 0; i < 2; i++)
        #pragma unroll
        for (int j = 0; j < 8; j++)
            #pragma unroll
            for (int c = 0; c < 4; c++) acc[i][j][c] = 0.0f;

    const int lr = tid >> 1;
    const int c0 = (tid & 1) * 2;
    const __nv_bfloat16* A0 = A + (size_t)(brow + lr) * K + c0 * 8;
    const __nv_bfloat16* B0 = B + (size_t)(bcol + lr) * K + c0 * 8;
    const uint32_t dA0 = sA + sw_off(lr, c0);
    const uint32_t dA1 = sA + sw_off(lr, c0 + 1);
    const uint32_t dB0 = sB + sw_off(lr, c0);
    const uint32_t dB1 = sB + sw_off(lr, c0 + 1);

    const int m8    = lane >> 3;
    const int rowin = lane & 7;
    int rA[2], cAh = m8 >> 1;
    rA[0] = warp_m * 32 + (m8 & 1) * 8 + rowin;
    rA[1] = rA[0] + 16;
    int rB[4], cBh = m8 & 1;
    #pragma unroll
    for (int np = 0; np < 4; np++)
        rB[np] = warp_n * 64 + np * 16 + (m8 >> 1) * 8 + rowin;

    const int kIters = K / BK;

    #pragma unroll
    for (int s = 0; s < STAGES - 1; s++) {
        int k0 = s * BK;
        uint32_t so = (uint32_t)s * STAGE_BYTES;
        cp16(dA0 + so, A0 + k0);
        cp16(dA1 + so, A0 + k0 + 8);
        cp16(dB0 + so, B0 + k0);
        cp16(dB1 + so, B0 + k0 + 8);
        cp_commit();
    }

    int buf = 0;
    int nbuf = STAGES - 1;
    for (int s = 0; s < kIters; s++) {
        cp_wait<STAGES - 2>();
        __syncthreads();

        if (s + STAGES - 1 < kIters) {
            int k0 = (s + STAGES - 1) * BK;
            uint32_t so = (uint32_t)nbuf * STAGE_BYTES;
            cp16(dA0 + so, A0 + k0);
            cp16(dA1 + so, A0 + k0 + 8);
            cp16(dB0 + so, B0 + k0);
            cp16(dB1 + so, B0 + k0 + 8);
        }
        cp_commit();

        const uint32_t aBuf = sA + (uint32_t)buf * STAGE_BYTES;
        const uint32_t bBuf = sB + (uint32_t)buf * STAGE_BYTES;
        #pragma unroll
        for (int ks = 0; ks < 2; ks++) {
            uint32_t af[2][4];
            #pragma unroll
            for (int mt = 0; mt < 2; mt++)
                ldsm_x4(af[mt], aBuf + sw_off(rA[mt], 2 * ks + cAh));
            #pragma unroll
            for (int np = 0; np < 4; np++) {
                uint32_t bf[4];
                ldsm_x4(bf, bBuf + sw_off(rB[np], 2 * ks + cBh));
                mma_bf16(acc[0][2 * np],     af[0], bf);
                mma_bf16(acc[1][2 * np],     af[1], bf);
                mma_bf16(acc[0][2 * np + 1], af[0], bf + 2);
                mma_bf16(acc[1][2 * np + 1], af[1], bf + 2);
            }
        }
        buf = (buf + 1 == STAGES) ? 0 : buf + 1;
        nbuf = (nbuf + 1 == STAGES) ? 0 : nbuf + 1;
    }

    const int grp = lane >> 2;
    const int t4  = lane & 3;
    #pragma unroll
    for (int mt = 0; mt < 2; mt++) {
        int row = brow + warp_m * 32 + mt * 16 + grp;
        #pragma unroll
        for (int nt = 0; nt < 8; nt++) {
            int col = bcol + warp_n * 64 + nt * 8 + 2 * t4;
            float b0 = bias[col], b1 = bias[col + 1];
            float v0 = acc[mt][nt][0] + b0;
            float v1 = acc[mt][nt][1] + b1;
            float v2 = acc[mt][nt][2] + b0;
            float v3 = acc[mt][nt][3] + b1;
            if (EPI == 1) {
                __nv_bfloat16* O = (__nv_bfloat16*)Cmat;
                __nv_bfloat162 o0 = __floats2bfloat162_rn(gelu_tanh(v0),
                                                          gelu_tanh(v1));
                __nv_bfloat162 o1 = __floats2bfloat162_rn(gelu_tanh(v2),
                                                          gelu_tanh(v3));
                *(__nv_bfloat162*)&O[(size_t)row * N + col]       = o0;
                *(__nv_bfloat162*)&O[(size_t)(row + 8) * N + col] = o1;
            } else {
                if (EPI == 2) {
                    v0 += res[(size_t)row * N + col];
                    v1 += res[(size_t)row * N + col + 1];
                    v2 += res[(size_t)(row + 8) * N + col];
                    v3 += res[(size_t)(row + 8) * N + col + 1];
                }
                float2 o0 = { v0, v1 };
                float2 o1 = { v2, v3 };
                *(float2*)&Cmat[(size_t)row * N + col]       = o0;
                *(float2*)&Cmat[(size_t)(row + 8) * N + col] = o1;
            }
        }
    }
}

// ---------------- CSR build ----------------
__global__ void zero_cnt_kernel(int* __restrict__ cnt) {
    int i = blockIdx.x * blockDim.x + threadIdx.x;
    if (i < L) cnt[i] = 0;
}
__global__ void hist_kernel(const int* __restrict__ row, int* __restrict__ cnt) {
    int e = blockIdx.x * blockDim.x + threadIdx.x;
    if (e < E) atomicAdd(&cnt[row[e]], 1);
}
__global__ void scan_kernel(const int* __restrict__ cnt, int* __restrict__ off,
                            int* __restrict__ cur) {
    __shared__ int ws[32];
    int tid = threadIdx.x;
    int base = tid * 16;
    int loc[16];
    int s = 0;
    #pragma unroll
    for (int i = 0; i < 16; i++) { loc[i] = s; s += cnt[base + i]; }
    int lane = tid & 31, w = tid >> 5;
    int v = s;
    #pragma unroll
    for (int o = 1; o < 32; o <<= 1) {
        int t = __shfl_up_sync(0xffffffffu, v, o);
        if (lane >= o) v += t;
    }
    if (lane == 31) ws[w] = v;
    __syncthreads();
    if (w == 0) {
        int t = ws[lane];
        #pragma unroll
        for (int o = 1; o < 32; o <<= 1) {
            int u = __shfl_up_sync(0xffffffffu, t, o);
            if (lane >= o) t += u;
        }
        ws[lane] = t;
    }
    __syncthreads();
    int excl = v - s + (w > 0 ? ws[w - 1] : 0);
    #pragma unroll
    for (int i = 0; i < 16; i++) {
        off[base + i] = excl + loc[i];
        cur[base + i] = excl + loc[i];
    }
    if (tid == 1023) off[L] = excl + s;
}
__global__ void scatter_kernel(const int* __restrict__ row,
                               int* __restrict__ cur, int* __restrict__ eid) {
    int e = blockIdx.x * blockDim.x + threadIdx.x;
    if (e < E) {
        int p = atomicAdd(&cur[row[e]], 1);
        eid[p] = e;
    }
}

// ---------------- fused edge score + softmax + aggregation ----------------
#define DMAX 384
__global__ __launch_bounds__(128)
void row_attn_kernel(const float* __restrict__ qkv,
                     const int* __restrict__ off,
                     const int* __restrict__ eid,
                     const int* __restrict__ col_index,
                     const int* __restrict__ to_col_index,
                     const float* __restrict__ pab,
                     const float* __restrict__ dist,
                     const float* __restrict__ pos,
                     const float* __restrict__ col_pos,
                     const float* __restrict__ Wvec,
                     const float* __restrict__ bvec,
                     __nv_bfloat16* __restrict__ agg) {
    int r = blockIdx.x;
    int tid = threadIdx.x;          // 128
    int lane = tid & 31;
    int w = tid >> 5;               // warp 0..3
    int beg = off[r];
    int deg = off[r + 1] - beg;

    __shared__ float s_q[C];
    __shared__ float s_den[H];
    __shared__ float s_px[DMAX][H];
    __shared__ float s_mt[DMAX][4];

    for (int i = tid; i < C / 4; i += 128)
        ((float4*)s_q)[i] = ((const float4*)(qkv + (size_t)r * NQKV))[i];
    if (tid < H) s_den[tid] = 0.0f;
    __syncthreads();

    float px0 = pos[r * 3 + 0], px1 = pos[r * 3 + 1], px2 = pos[r * 3 + 2];

    // ---- pass 1: scores, den, cache pexp/meta ----
    for (int i0 = w; i0 < deg; i0 += 4) {
        int e = eid[beg + i0];
        int ci = col_index[e];
        const float* kr = qkv + (size_t)ci * NQKV + C;
        float sc[H];
        #pragma unroll
        for (int h = 0; h < H; h++) {
            float d0 = s_q[h * DH + lane]      - kr[h * DH + lane];
            float d1 = s_q[h * DH + 32 + lane] - kr[h * DH + 32 + lane];
            float s = d0 * d0 + d1 * d1;
            #pragma unroll
            for (int o = 16; o > 0; o >>= 1)
                s += __shfl_xor_sync(0xffffffffu, s, o);
            sc[h] = s;
        }
        if (lane < H) {
            float val = __expf(-sc[lane] * 0.125f + pab[(size_t)e * H + lane]);
            atomicAdd(&s_den[lane], val);
            if (i0 < DMAX) s_px[i0][lane] = val;
        }
        if (lane == 8 && i0 < DMAX) {
            int tci = to_col_index[e];
            float dinv = 1.0f / dist[e];
            s_mt[i0][0] = __int_as_float(ci);
            s_mt[i0][1] = (col_pos[tci * 3 + 0] - px0) * dinv;
            s_mt[i0][2] = (col_pos[tci * 3 + 1] - px1) * dinv;
            s_mt[i0][3] = (col_pos[tci * 3 + 2] - px2) * dinv;
        }
    }
    __syncthreads();
    if (tid < H) {
        float d = s_den[tid];
        s_den[tid] = (d == 0.0f) ? 1.0f : 1.0f / d;
    }
    __syncthreads();

    // ---- pass 2: channel-parallel aggregation, 4-edge software pipeline ----
    int c0 = tid * 4;
    int hh = c0 >> 6;
    float4 wv0 = *(const float4*)(Wvec + c0);
    float4 wv1 = *(const float4*)(Wvec + C + c0);
    float4 wv2 = *(const float4*)(Wvec + 2 * C + c0);
    float4 bv  = *(const float4*)(bvec + c0);
    float dinvh = s_den[hh];

    float a0 = 0.0f, a1 = 0.0f, a2 = 0.0f, a3 = 0.0f;
    int ncache = deg < DMAX ? deg : DMAX;
    int i = 0;
    for (; i + 4 <= ncache; i += 4) {
        // gather metadata for 4 edges (smem, cheap)
        int   ci[4];
        float rx[4], ry[4], rz[4], al[4];
        #pragma unroll
        for (int j = 0; j < 4; j++) {
            ci[j] = __float_as_int(s_mt[i + j][0]);
            rx[j] = s_mt[i + j][1];
            ry[j] = s_mt[i + j][2];
            rz[j] = s_mt[i + j][3];
            al[j] = s_px[i + j][hh] * dinvh;
        }
        // 4 independent global gathers (MLP=4)
        float4 v4[4];
        #pragma unroll
        for (int j = 0; j < 4; j++)
            v4[j] = *(const float4*)(qkv + (size_t)ci[j] * NQKV + 2 * C + c0);
        // accumulate in original edge order (bit-identical to serial loop)
        #pragma unroll
        for (int j = 0; j < 4; j++) {
            a0 += al[j] * (v4[j].x + rx[j] * wv0.x + ry[j] * wv1.x + rz[j] * wv2.x + bv.x);
            a1 += al[j] * (v4[j].y + rx[j] * wv0.y + ry[j] * wv1.y + rz[j] * wv2.y + bv.y);
            a2 += al[j] * (v4[j].z + rx[j] * wv0.z + ry[j] * wv1.z + rz[j] * wv2.z + bv.z);
            a3 += al[j] * (v4[j].w + rx[j] * wv0.w + ry[j] * wv1.w + rz[j] * wv2.w + bv.w);
        }
    }
    for (; i < ncache; i++) {
        int cii = __float_as_int(s_mt[i][0]);
        float rxx = s_mt[i][1], ryy = s_mt[i][2], rzz = s_mt[i][3];
        float all = s_px[i][hh] * dinvh;
        float4 v4 = *(const float4*)(qkv + (size_t)cii * NQKV + 2 * C + c0);
        a0 += all * (v4.x + rxx * wv0.x + ryy * wv1.x + rzz * wv2.x + bv.x);
        a1 += all * (v4.y + rxx * wv0.y + ryy * wv1.y + rzz * wv2.y + bv.y);
        a2 += all * (v4.z + rxx * wv0.z + ryy * wv1.z + rzz * wv2.z + bv.z);
        a3 += all * (v4.w + rxx * wv0.w + ryy * wv1.w + rzz * wv2.w + bv.w);
    }
    // overflow fallback (deg > DMAX): recompute scores in chunks of 16
    for (int base = DMAX; base < deg; base += 16) {
        int n = min(16, deg - base);
        __syncthreads();
        for (int j = w; j < n; j += 4) {
            int e = eid[beg + base + j];
            int ci = col_index[e];
            const float* kr = qkv + (size_t)ci * NQKV + C;
            float sc[H];
            #pragma unroll
            for (int h = 0; h < H; h++) {
                float d0 = s_q[h * DH + lane]      - kr[h * DH + lane];
                float d1 = s_q[h * DH + 32 + lane] - kr[h * DH + 32 + lane];
                float s = d0 * d0 + d1 * d1;
                #pragma unroll
                for (int o = 16; o > 0; o >>= 1)
                    s += __shfl_xor_sync(0xffffffffu, s, o);
                sc[h] = s;
            }
            if (lane < H)
                s_px[j][lane] = __expf(-sc[lane] * 0.125f + pab[(size_t)e * H + lane]);
            if (lane == 8) {
                int tci = to_col_index[e];
                float dinv = 1.0f / dist[e];
                s_mt[j][0] = __int_as_float(ci);
                s_mt[j][1] = (col_pos[tci * 3 + 0] - px0) * dinv;
                s_mt[j][2] = (col_pos[tci * 3 + 1] - px1) * dinv;
                s_mt[j][3] = (col_pos[tci * 3 + 2] - px2) * dinv;
            }
        }
        __syncthreads();
        for (int ii = 0; ii < n; ii++) {
            int cii = __float_as_int(s_mt[ii][0]);
            float rxx = s_mt[ii][1], ryy = s_mt[ii][2], rzz = s_mt[ii][3];
            float all = s_px[ii][hh] * dinvh;
            float4 v4 = *(const float4*)(qkv + (size_t)cii * NQKV + 2 * C + c0);
            a0 += all * (v4.x + rxx * wv0.x + ryy * wv1.x + rzz * wv2.x + bv.x);
            a1 += all * (v4.y + rxx * wv0.y + ryy * wv1.y + rzz * wv2.y + bv.y);
            a2 += all * (v4.z + rxx * wv0.z + ryy * wv1.z + rzz * wv2.z + bv.z);
            a3 += all * (v4.w + rxx * wv0.w + ryy * wv1.w + rzz * wv2.w + bv.w);
        }
    }

    __nv_bfloat162 o0 = __floats2bfloat162_rn(a0, a1);
    __nv_bfloat162 o1 = __floats2bfloat162_rn(a2, a3);
    __nv_bfloat162* ar = (__nv_bfloat162*)(agg + (size_t)r * C);
    ar[tid * 2]     = o0;
    ar[tid * 2 + 1] = o1;
}

// ---------------- launcher ----------------
extern "C" void kernel_launch(void* const* d_in, const int* in_sizes, int n_in,
                              void* d_out, int out_size) {
    const float* x        = (const float*)d_in[0];
    const int*   row_idx  = (const int*)  d_in[1];
    const int*   col_idx  = (const int*)  d_in[2];
    const int*   tcol_idx = (const int*)  d_in[3];
    const float* pab      = (const float*)d_in[5];
    const float* dist     = (const float*)d_in[6];
    const float* pos      = (const float*)d_in[7];
    const float* col_pos  = (const float*)d_in[8];
    const float* ln1_g    = (const float*)d_in[9];
    const float* ln1_b    = (const float*)d_in[10];
    const float* ln2_g    = (const float*)d_in[11];
    const float* ln2_b    = (const float*)d_in[12];
    const float* Wq       = (const float*)d_in[13];
    const float* bq       = (const float*)d_in[14];
    const float* Wk       = (const float*)d_in[15];
    const float* bk       = (const float*)d_in[16];
    const float* Wv       = (const float*)d_in[17];
    const float* bv       = (const float*)d_in[18];
    const float* Wvec     = (const float*)d_in[19];
    const float* bvec     = (const float*)d_in[20];
    const float* Wo       = (const float*)d_in[21];
    const float* bo       = (const float*)d_in[22];
    const float* W1       = (const float*)d_in[23];
    const float* b1       = (const float*)d_in[24];
    const float* W2       = (const float*)d_in[25];
    const float* b2       = (const float*)d_in[26];
    float* out = (float*)d_out;

    static __nv_bfloat16 *zp = nullptr, *aggp, *z2p, *hidp,
                         *wqkvp, *wop, *w1p, *w2p;
    static float *qkvp, *x1p, *bqkvp;
    static int *cntp, *offp, *curp, *eidp;
    if (!zp) {
        cudaGetSymbolAddress((void**)&zp,    g_z);
        cudaGetSymbolAddress((void**)&qkvp,  g_qkv);
        cudaGetSymbolAddress((void**)&aggp,  g_agg);
        cudaGetSymbolAddress((void**)&x1p,   g_x1);
        cudaGetSymbolAddress((void**)&z2p,   g_z2);
        cudaGetSymbolAddress((void**)&hidp,  g_hid);
        cudaGetSymbolAddress((void**)&wqkvp, g_wqkv);
        cudaGetSymbolAddress((void**)&bqkvp, g_bqkv);
        cudaGetSymbolAddress((void**)&wop,   g_wo);
        cudaGetSymbolAddress((void**)&w1p,   g_w1);
        cudaGetSymbolAddress((void**)&w2p,   g_w2);
        cudaGetSymbolAddress((void**)&cntp,  g_cnt);
        cudaGetSymbolAddress((void**)&offp,  g_off);
        cudaGetSymbolAddress((void**)&curp,  g_cur);
        cudaGetSymbolAddress((void**)&eidp,  g_eid);
        cudaFuncSetAttribute(tgemm_kernel<0>,
            cudaFuncAttributeMaxDynamicSharedMemorySize, SMEM_BYTES);
        cudaFuncSetAttribute(tgemm_kernel<1>,
            cudaFuncAttributeMaxDynamicSharedMemorySize, SMEM_BYTES);
        cudaFuncSetAttribute(tgemm_kernel<2>,
            cudaFuncAttributeMaxDynamicSharedMemorySize, SMEM_BYTES);
    }

    // CSR build
    zero_cnt_kernel<<<(L + 255) / 256, 256>>>(cntp);
    hist_kernel<<<(E + 255) / 256, 256>>>(row_idx, cntp);
    scan_kernel<<<1, 1024>>>(cntp, offp, curp);
    scatter_kernel<<<(E + 255) / 256, 256>>>(row_idx, curp, eidp);

    // weight prep (transposes + bias pack, one launch)
    transpose_all_kernel<<<dim3(32, 32, 6), dim3(32, 8)>>>(
        Wq, Wk, Wv, Wo, W1, W2, bq, bk, bv, wqkvp, wop, w1p, w2p, bqkvp);

    // LN1 -> bf16
    ln_kernel<<<L, 128>>>(x, ln1_g, ln1_b, zp);

    // fused QKV projection (bf16 MMA, fp32 out)
    dim3 gqkv(NQKV / BN, L / BM);
    tgemm_kernel<0><<<gqkv, 256, SMEM_BYTES>>>(zp, wqkvp, bqkvp, nullptr, qkvp,
                                               L, NQKV, C);

    // fused edge score + softmax + aggregation -> bf16 agg
    row_attn_kernel<<<L, 128>>>(qkvp, offp, eidp, col_idx, tcol_idx,
                                pab, dist, pos, col_pos, Wvec, bvec, aggp);

    // output projection + residual -> fp32 x1
    dim3 g512(C / BN, L / BM);
    tgemm_kernel<2><<<g512, 256, SMEM_BYTES>>>(aggp, wop, bo, x, x1p, L, C, C);

    // LN2 -> bf16
    ln_kernel<<<L, 128>>>(x1p, ln2_g, ln2_b, z2p);

    // FFN up + gelu -> bf16 hid
    dim3 g1024(HID / BN, L / BM);
    tgemm_kernel<1><<<g1024, 256, SMEM_BYTES>>>(z2p, w1p, b1, nullptr,
                                                (float*)hidp, L, HID, C);

    // FFN down + residual -> fp32 out
    tgemm_kernel<2><<<g512, 256, SMEM_BYTES>>>(hidp, w2p, b2, x1p, out,
                                               L, C, HID);
}

// round 10
// speedup vs baseline: 4.4979x; 1.0466x over previous
#include <cuda_runtime.h>
#include <cuda_bf16.h>
#include <math.h>
#include <stdint.h>

// Problem constants
#define L   16384
#define E   131072
#define SP  20000
#define C   512
#define H   8
#define DH  64
#define HID 1024
#define NQKV 1536

// ---------------- scratch (device globals: allocation-free) ----------------
__device__ __nv_bfloat16 g_z[(size_t)L * C];
__device__ float         g_qkv[(size_t)L * NQKV];
__device__ __nv_bfloat16 g_vb[(size_t)L * C];     // bf16 copy of v
__device__ __nv_bfloat16 g_agg[(size_t)L * C];
__device__ float         g_x1[(size_t)L * C];
__device__ __nv_bfloat16 g_z2[(size_t)L * C];
__device__ __nv_bfloat16 g_hid[(size_t)L * HID];
// transposed bf16 weights: [N][K]
__device__ __nv_bfloat16 g_wqkv[(size_t)NQKV * C];
__device__ float         g_bqkv[NQKV];
__device__ __nv_bfloat16 g_wo[(size_t)C * C];
__device__ __nv_bfloat16 g_w1[(size_t)HID * C];
__device__ __nv_bfloat16 g_w2[(size_t)C * HID];
// CSR
__device__ int g_cnt[L];
__device__ int g_off[L + 1];
__device__ int g_cur[L];
__device__ int g_eid[E];

// ---------------- helpers ----------------
__device__ __forceinline__ float gelu_tanh(float x) {
    const float k0 = 0.7978845608028654f;
    const float k1 = 0.044715f;
    float x3 = x * x * x;
    return 0.5f * x * (1.0f + tanhf(k0 * (x + k1 * x3)));
}

__device__ __forceinline__ void mma_bf16(float* d, const uint32_t* a,
                                         const uint32_t* b) {
    asm volatile(
        "mma.sync.aligned.m16n8k16.row.col.f32.bf16.bf16.f32 "
        "{%0,%1,%2,%3}, {%4,%5,%6,%7}, {%8,%9}, {%0,%1,%2,%3};\n"
        : "+f"(d[0]), "+f"(d[1]), "+f"(d[2]), "+f"(d[3])
        : "r"(a[0]), "r"(a[1]), "r"(a[2]), "r"(a[3]),
          "r"(b[0]), "r"(b[1]));
}

__device__ __forceinline__ void ldsm_x4(uint32_t* r, uint32_t addr) {
    asm volatile(
        "ldmatrix.sync.aligned.m8n8.x4.shared.b16 {%0,%1,%2,%3}, [%4];\n"
        : "=r"(r[0]), "=r"(r[1]), "=r"(r[2]), "=r"(r[3]) : "r"(addr));
}

__device__ __forceinline__ void cp16(uint32_t dst, const void* src) {
    asm volatile("cp.async.cg.shared.global [%0], [%1], 16;\n"
                 :: "r"(dst), "l"(src));
}
__device__ __forceinline__ void cp_commit() {
    asm volatile("cp.async.commit_group;\n");
}
template <int N>
__device__ __forceinline__ void cp_wait() {
    asm volatile("cp.async.wait_group %0;\n" :: "n"(N));
}
__device__ __forceinline__ uint32_t smem_u32(const void* p) {
    uint32_t a;
    asm("{ .reg .u64 t; cvta.to.shared.u64 t, %1; cvt.u32.u64 %0, t; }"
        : "=r"(a) : "l"(p));
    return a;
}

// swizzled byte offset of 16B chunk c (0..3) in logical row r (64B rows,
// packed 2 per 128B physical row)
__device__ __forceinline__ uint32_t sw_off(int r, int c) {
    return (uint32_t)((r >> 1) * 128 + ((((c + 4 * (r & 1))) ^ ((r >> 1) & 7)) << 4));
}

// ---------------- weight prep: all 6 transposes + bias pack ---------------
__global__ void transpose_all_kernel(const float* __restrict__ Wq,
                                     const float* __restrict__ Wk,
                                     const float* __restrict__ Wv,
                                     const float* __restrict__ Wo,
                                     const float* __restrict__ W1,
                                     const float* __restrict__ W2,
                                     const float* __restrict__ bq,
                                     const float* __restrict__ bk,
                                     const float* __restrict__ bv,
                                     __nv_bfloat16* __restrict__ wqkv,
                                     __nv_bfloat16* __restrict__ wo,
                                     __nv_bfloat16* __restrict__ w1,
                                     __nv_bfloat16* __restrict__ w2,
                                     float* __restrict__ bqkv) {
    int z = blockIdx.z;
    if (z == 0) {
        int bid = blockIdx.y * gridDim.x + blockIdx.x;
        int i = bid * 256 + threadIdx.y * 32 + threadIdx.x;
        if (i < C) {
            bqkv[i]         = bq[i];
            bqkv[C + i]     = bk[i];
            bqkv[2 * C + i] = bv[i];
        }
    }
    const float* src;
    __nv_bfloat16* dst;
    int Kd, Nd;
    if (z == 0)      { src = Wq; dst = wqkv;                     Kd = C;   Nd = C; }
    else if (z == 1) { src = Wk; dst = wqkv + (size_t)C * C;     Kd = C;   Nd = C; }
    else if (z == 2) { src = Wv; dst = wqkv + (size_t)2 * C * C; Kd = C;   Nd = C; }
    else if (z == 3) { src = Wo; dst = wo;                       Kd = C;   Nd = C; }
    else if (z == 4) { src = W1; dst = w1;                       Kd = C;   Nd = HID; }
    else             { src = W2; dst = w2;                       Kd = HID; Nd = C; }
    int kb = blockIdx.y * 32, nb = blockIdx.x * 32;
    if (kb >= Kd || nb >= Nd) return;
    __shared__ float tile[32][33];
    int tx = threadIdx.x, ty = threadIdx.y;   // 32x8
    #pragma unroll
    for (int i = ty; i < 32; i += 8)
        tile[i][tx] = src[(size_t)(kb + i) * Nd + nb + tx];
    __syncthreads();
    #pragma unroll
    for (int i = ty; i < 32; i += 8)
        dst[(size_t)(nb + i) * Kd + kb + tx] = __float2bfloat16_rn(tile[tx][i]);
}

// ---------------- LayerNorm (bf16 output) ----------------
__global__ void ln_kernel(const float* __restrict__ x,
                          const float* __restrict__ g,
                          const float* __restrict__ b,
                          __nv_bfloat16* __restrict__ z) {
    int row = blockIdx.x;
    int t = threadIdx.x;                 // 0..127
    const float* xr = x + (size_t)row * C;
    float4 v4 = *(const float4*)(xr + t * 4);
    float s  = v4.x + v4.y + v4.z + v4.w;
    float ss = v4.x * v4.x + v4.y * v4.y + v4.z * v4.z + v4.w * v4.w;
    #pragma unroll
    for (int o = 16; o > 0; o >>= 1) {
        s  += __shfl_xor_sync(0xffffffffu, s, o);
        ss += __shfl_xor_sync(0xffffffffu, ss, o);
    }
    __shared__ float sh[4], sh2[4];
    int w = t >> 5;
    if ((t & 31) == 0) { sh[w] = s; sh2[w] = ss; }
    __syncthreads();
    float sum  = sh[0] + sh[1] + sh[2] + sh[3];
    float sum2 = sh2[0] + sh2[1] + sh2[2] + sh2[3];
    float mean = sum * (1.0f / C);
    float var  = sum2 * (1.0f / C) - mean * mean;
    float inv  = rsqrtf(var + 1e-5f);
    float4 g4 = *(const float4*)(g + t * 4);
    float4 b4 = *(const float4*)(b + t * 4);
    __nv_bfloat162 p0 = __floats2bfloat162_rn(
        (v4.x - mean) * inv * g4.x + b4.x, (v4.y - mean) * inv * g4.y + b4.y);
    __nv_bfloat162 p1 = __floats2bfloat162_rn(
        (v4.z - mean) * inv * g4.z + b4.z, (v4.w - mean) * inv * g4.w + b4.w);
    __nv_bfloat162* zr = (__nv_bfloat162*)(z + (size_t)row * C);
    zr[t * 2]     = p0;
    zr[t * 2 + 1] = p1;
}

// ---------------- bf16 tensor-core GEMM ----------------
// EPI: 1 bias+gelu->bf16, 2 bias+residual->fp32, 3 bias->fp32 + bf16 v copy
#define BM  128
#define BN  128
#define BK  32
#define STAGES 4
#define STAGE_BYTES 8192
#define SMEM_BYTES (STAGES * 2 * STAGE_BYTES)   // 65536

template <int EPI>
__global__ __launch_bounds__(256, 2)
void tgemm_kernel(const __nv_bfloat16* __restrict__ A,
                  const __nv_bfloat16* __restrict__ B,
                  const float* __restrict__ bias, const float* __restrict__ res,
                  float* __restrict__ Cmat, __nv_bfloat16* __restrict__ vb,
                  int M, int N, int K) {
    extern __shared__ float smemf[];
    const uint32_t sA = smem_u32(smemf);
    const uint32_t sB = sA + STAGES * STAGE_BYTES;

    const int tid    = threadIdx.x;
    const int lane   = tid & 31;
    const int wid    = tid >> 5;
    const int warp_m = wid & 3;
    const int warp_n = wid >> 2;

    const int brow = blockIdx.y * BM;
    const int bcol = blockIdx.x * BN;

    float acc[2][8][4];
    #pragma unroll
    for (int i = 0; i < 2; i++)
        #pragma unroll
        for (int j = 0; j < 8; j++)
            #pragma unroll
            for (int c = 0; c < 4; c++) acc[i][j][c] = 0.0f;

    const int lr = tid >> 1;
    const int c0 = (tid & 1) * 2;
    const __nv_bfloat16* A0 = A + (size_t)(brow + lr) * K + c0 * 8;
    const __nv_bfloat16* B0 = B + (size_t)(bcol + lr) * K + c0 * 8;
    const uint32_t dA0 = sA + sw_off(lr, c0);
    const uint32_t dA1 = sA + sw_off(lr, c0 + 1);
    const uint32_t dB0 = sB + sw_off(lr, c0);
    const uint32_t dB1 = sB + sw_off(lr, c0 + 1);

    const int m8    = lane >> 3;
    const int rowin = lane & 7;
    int rA[2], cAh = m8 >> 1;
    rA[0] = warp_m * 32 + (m8 & 1) * 8 + rowin;
    rA[1] = rA[0] + 16;
    int rB[4], cBh = m8 & 1;
    #pragma unroll
    for (int np = 0; np < 4; np++)
        rB[np] = warp_n * 64 + np * 16 + (m8 >> 1) * 8 + rowin;

    const int kIters = K / BK;

    #pragma unroll
    for (int s = 0; s < STAGES - 1; s++) {
        int k0 = s * BK;
        uint32_t so = (uint32_t)s * STAGE_BYTES;
        cp16(dA0 + so, A0 + k0);
        cp16(dA1 + so, A0 + k0 + 8);
        cp16(dB0 + so, B0 + k0);
        cp16(dB1 + so, B0 + k0 + 8);
        cp_commit();
    }

    int buf = 0;
    int nbuf = STAGES - 1;
    for (int s = 0; s < kIters; s++) {
        cp_wait<STAGES - 2>();
        __syncthreads();

        if (s + STAGES - 1 < kIters) {
            int k0 = (s + STAGES - 1) * BK;
            uint32_t so = (uint32_t)nbuf * STAGE_BYTES;
            cp16(dA0 + so, A0 + k0);
            cp16(dA1 + so, A0 + k0 + 8);
            cp16(dB0 + so, B0 + k0);
            cp16(dB1 + so, B0 + k0 + 8);
        }
        cp_commit();

        const uint32_t aBuf = sA + (uint32_t)buf * STAGE_BYTES;
        const uint32_t bBuf = sB + (uint32_t)buf * STAGE_BYTES;
        #pragma unroll
        for (int ks = 0; ks < 2; ks++) {
            uint32_t af[2][4];
            #pragma unroll
            for (int mt = 0; mt < 2; mt++)
                ldsm_x4(af[mt], aBuf + sw_off(rA[mt], 2 * ks + cAh));
            #pragma unroll
            for (int np = 0; np < 4; np++) {
                uint32_t bf[4];
                ldsm_x4(bf, bBuf + sw_off(rB[np], 2 * ks + cBh));
                mma_bf16(acc[0][2 * np],     af[0], bf);
                mma_bf16(acc[1][2 * np],     af[1], bf);
                mma_bf16(acc[0][2 * np + 1], af[0], bf + 2);
                mma_bf16(acc[1][2 * np + 1], af[1], bf + 2);
            }
        }
        buf = (buf + 1 == STAGES) ? 0 : buf + 1;
        nbuf = (nbuf + 1 == STAGES) ? 0 : nbuf + 1;
    }

    const int grp = lane >> 2;
    const int t4  = lane & 3;
    #pragma unroll
    for (int mt = 0; mt < 2; mt++) {
        int row = brow + warp_m * 32 + mt * 16 + grp;
        #pragma unroll
        for (int nt = 0; nt < 8; nt++) {
            int col = bcol + warp_n * 64 + nt * 8 + 2 * t4;
            float b0 = bias[col], b1 = bias[col + 1];
            float v0 = acc[mt][nt][0] + b0;
            float v1 = acc[mt][nt][1] + b1;
            float v2 = acc[mt][nt][2] + b0;
            float v3 = acc[mt][nt][3] + b1;
            if (EPI == 1) {
                __nv_bfloat16* O = (__nv_bfloat16*)Cmat;
                __nv_bfloat162 o0 = __floats2bfloat162_rn(gelu_tanh(v0),
                                                          gelu_tanh(v1));
                __nv_bfloat162 o1 = __floats2bfloat162_rn(gelu_tanh(v2),
                                                          gelu_tanh(v3));
                *(__nv_bfloat162*)&O[(size_t)row * N + col]       = o0;
                *(__nv_bfloat162*)&O[(size_t)(row + 8) * N + col] = o1;
            } else {
                if (EPI == 2) {
                    v0 += res[(size_t)row * N + col];
                    v1 += res[(size_t)row * N + col + 1];
                    v2 += res[(size_t)(row + 8) * N + col];
                    v3 += res[(size_t)(row + 8) * N + col + 1];
                }
                float2 o0 = { v0, v1 };
                float2 o1 = { v2, v3 };
                *(float2*)&Cmat[(size_t)row * N + col]       = o0;
                *(float2*)&Cmat[(size_t)(row + 8) * N + col] = o1;
                if (EPI == 3 && col >= 2 * C) {
                    int vc = col - 2 * C;
                    __nv_bfloat162 p0 = __floats2bfloat162_rn(v0, v1);
                    __nv_bfloat162 p1 = __floats2bfloat162_rn(v2, v3);
                    *(__nv_bfloat162*)&vb[(size_t)row * C + vc]       = p0;
                    *(__nv_bfloat162*)&vb[(size_t)(row + 8) * C + vc] = p1;
                }
            }
        }
    }
}

// ---------------- CSR build ----------------
__global__ void zero_cnt_kernel(int* __restrict__ cnt) {
    int i = blockIdx.x * blockDim.x + threadIdx.x;
    if (i < L) cnt[i] = 0;
}
__global__ void hist_kernel(const int* __restrict__ row, int* __restrict__ cnt) {
    int e = blockIdx.x * blockDim.x + threadIdx.x;
    if (e < E) atomicAdd(&cnt[row[e]], 1);
}
__global__ void scan_kernel(const int* __restrict__ cnt, int* __restrict__ off,
                            int* __restrict__ cur) {
    __shared__ int ws[32];
    int tid = threadIdx.x;
    int base = tid * 16;
    int loc[16];
    int s = 0;
    #pragma unroll
    for (int i = 0; i < 16; i++) { loc[i] = s; s += cnt[base + i]; }
    int lane = tid & 31, w = tid >> 5;
    int v = s;
    #pragma unroll
    for (int o = 1; o < 32; o <<= 1) {
        int t = __shfl_up_sync(0xffffffffu, v, o);
        if (lane >= o) v += t;
    }
    if (lane == 31) ws[w] = v;
    __syncthreads();
    if (w == 0) {
        int t = ws[lane];
        #pragma unroll
        for (int o = 1; o < 32; o <<= 1) {
            int u = __shfl_up_sync(0xffffffffu, t, o);
            if (lane >= o) t += u;
        }
        ws[lane] = t;
    }
    __syncthreads();
    int excl = v - s + (w > 0 ? ws[w - 1] : 0);
    #pragma unroll
    for (int i = 0; i < 16; i++) {
        off[base + i] = excl + loc[i];
        cur[base + i] = excl + loc[i];
    }
    if (tid == 1023) off[L] = excl + s;
}
__global__ void scatter_kernel(const int* __restrict__ row,
                               int* __restrict__ cur, int* __restrict__ eid) {
    int e = blockIdx.x * blockDim.x + threadIdx.x;
    if (e < E) {
        int p = atomicAdd(&cur[row[e]], 1);
        eid[p] = e;
    }
}

// ---------------- fused edge score + softmax + aggregation ----------------
#define DMAX 64
__global__ __launch_bounds__(128)
void row_attn_kernel(const float* __restrict__ qkv,
                     const __nv_bfloat16* __restrict__ vb,
                     const int* __restrict__ off,
                     const int* __restrict__ eid,
                     const int* __restrict__ col_index,
                     const int* __restrict__ to_col_index,
                     const float* __restrict__ pab,
                     const float* __restrict__ dist,
                     const float* __restrict__ pos,
                     const float* __restrict__ col_pos,
                     const float* __restrict__ Wvec,
                     const float* __restrict__ bvec,
                     __nv_bfloat16* __restrict__ agg) {
    int r = blockIdx.x;
    int tid = threadIdx.x;          // 128
    int lane = tid & 31;
    int w = tid >> 5;               // warp 0..3
    int beg = off[r];
    int deg = off[r + 1] - beg;

    __shared__ float s_q[C];
    __shared__ float s_den[H];
    __shared__ float s_px[DMAX][H];
    __shared__ float s_mt[DMAX][4];

    for (int i = tid; i < C / 4; i += 128)
        ((float4*)s_q)[i] = ((const float4*)(qkv + (size_t)r * NQKV))[i];
    if (tid < H) s_den[tid] = 0.0f;
    __syncthreads();

    float px0 = pos[r * 3 + 0], px1 = pos[r * 3 + 1], px2 = pos[r * 3 + 2];

    // ---- pass 1: scores, den, cache pexp/meta ----
    for (int i0 = w; i0 < deg; i0 += 4) {
        int e = eid[beg + i0];
        int ci = col_index[e];
        const float* kr = qkv + (size_t)ci * NQKV + C;
        float sc[H];
        #pragma unroll
        for (int h = 0; h < H; h++) {
            float d0 = s_q[h * DH + lane]      - kr[h * DH + lane];
            float d1 = s_q[h * DH + 32 + lane] - kr[h * DH + 32 + lane];
            float s = d0 * d0 + d1 * d1;
            #pragma unroll
            for (int o = 16; o > 0; o >>= 1)
                s += __shfl_xor_sync(0xffffffffu, s, o);
            sc[h] = s;
        }
        if (lane < H) {
            float val = __expf(-sc[lane] * 0.125f + pab[(size_t)e * H + lane]);
            atomicAdd(&s_den[lane], val);
            if (i0 < DMAX) s_px[i0][lane] = val;
        }
        if (lane == 8 && i0 < DMAX) {
            int tci = to_col_index[e];
            float dinv = 1.0f / dist[e];
            s_mt[i0][0] = __int_as_float(ci);
            s_mt[i0][1] = (col_pos[tci * 3 + 0] - px0) * dinv;
            s_mt[i0][2] = (col_pos[tci * 3 + 1] - px1) * dinv;
            s_mt[i0][3] = (col_pos[tci * 3 + 2] - px2) * dinv;
        }
    }
    __syncthreads();
    if (tid < H) {
        float d = s_den[tid];
        s_den[tid] = (d == 0.0f) ? 1.0f : 1.0f / d;
    }
    __syncthreads();

    // ---- pass 2: channel-parallel aggregation, 4-edge pipeline, bf16 v ----
    int c0 = tid * 4;
    int hh = c0 >> 6;
    float4 wv0 = *(const float4*)(Wvec + c0);
    float4 wv1 = *(const float4*)(Wvec + C + c0);
    float4 wv2 = *(const float4*)(Wvec + 2 * C + c0);
    float4 bv  = *(const float4*)(bvec + c0);
    float dinvh = s_den[hh];

    float a0 = 0.0f, a1 = 0.0f, a2 = 0.0f, a3 = 0.0f;
    int ncache = deg < DMAX ? deg : DMAX;
    int i = 0;
    for (; i + 4 <= ncache; i += 4) {
        int   ci[4];
        float rx[4], ry[4], rz[4], al[4];
        #pragma unroll
        for (int j = 0; j < 4; j++) {
            ci[j] = __float_as_int(s_mt[i + j][0]);
            rx[j] = s_mt[i + j][1];
            ry[j] = s_mt[i + j][2];
            rz[j] = s_mt[i + j][3];
            al[j] = s_px[i + j][hh] * dinvh;
        }
        uint2 raw[4];
        #pragma unroll
        for (int j = 0; j < 4; j++)
            raw[j] = *(const uint2*)(vb + (size_t)ci[j] * C + c0);
        #pragma unroll
        for (int j = 0; j < 4; j++) {
            float2 f0 = __bfloat1622float2(*(__nv_bfloat162*)&raw[j].x);
            float2 f1 = __bfloat1622float2(*(__nv_bfloat162*)&raw[j].y);
            a0 += al[j] * (f0.x + rx[j] * wv0.x + ry[j] * wv1.x + rz[j] * wv2.x + bv.x);
            a1 += al[j] * (f0.y + rx[j] * wv0.y + ry[j] * wv1.y + rz[j] * wv2.y + bv.y);
            a2 += al[j] * (f1.x + rx[j] * wv0.z + ry[j] * wv1.z + rz[j] * wv2.z + bv.z);
            a3 += al[j] * (f1.y + rx[j] * wv0.w + ry[j] * wv1.w + rz[j] * wv2.w + bv.w);
        }
    }
    for (; i < ncache; i++) {
        int cii = __float_as_int(s_mt[i][0]);
        float rxx = s_mt[i][1], ryy = s_mt[i][2], rzz = s_mt[i][3];
        float all = s_px[i][hh] * dinvh;
        uint2 raw = *(const uint2*)(vb + (size_t)cii * C + c0);
        float2 f0 = __bfloat1622float2(*(__nv_bfloat162*)&raw.x);
        float2 f1 = __bfloat1622float2(*(__nv_bfloat162*)&raw.y);
        a0 += all * (f0.x + rxx * wv0.x + ryy * wv1.x + rzz * wv2.x + bv.x);
        a1 += all * (f0.y + rxx * wv0.y + ryy * wv1.y + rzz * wv2.y + bv.y);
        a2 += all * (f1.x + rxx * wv0.z + ryy * wv1.z + rzz * wv2.z + bv.z);
        a3 += all * (f1.y + rxx * wv0.w + ryy * wv1.w + rzz * wv2.w + bv.w);
    }
    // overflow fallback (deg > DMAX): recompute scores in chunks of 16
    for (int base = DMAX; base < deg; base += 16) {
        int n = min(16, deg - base);
        __syncthreads();
        for (int j = w; j < n; j += 4) {
            int e = eid[beg + base + j];
            int ci = col_index[e];
            const float* kr = qkv + (size_t)ci * NQKV + C;
            float sc[H];
            #pragma unroll
            for (int h = 0; h < H; h++) {
                float d0 = s_q[h * DH + lane]      - kr[h * DH + lane];
                float d1 = s_q[h * DH + 32 + lane] - kr[h * DH + 32 + lane];
                float s = d0 * d0 + d1 * d1;
                #pragma unroll
                for (int o = 16; o > 0; o >>= 1)
                    s += __shfl_xor_sync(0xffffffffu, s, o);
                sc[h] = s;
            }
            if (lane < H)
                s_px[j][lane] = __expf(-sc[lane] * 0.125f + pab[(size_t)e * H + lane]);
            if (lane == 8) {
                int tci = to_col_index[e];
                float dinv = 1.0f / dist[e];
                s_mt[j][0] = __int_as_float(ci);
                s_mt[j][1] = (col_pos[tci * 3 + 0] - px0) * dinv;
                s_mt[j][2] = (col_pos[tci * 3 + 1] - px1) * dinv;
                s_mt[j][3] = (col_pos[tci * 3 + 2] - px2) * dinv;
            }
        }
        __syncthreads();
        for (int ii = 0; ii < n; ii++) {
            int cii = __float_as_int(s_mt[ii][0]);
            float rxx = s_mt[ii][1], ryy = s_mt[ii][2], rzz = s_mt[ii][3];
            float all = s_px[ii][hh] * dinvh;
            uint2 raw = *(const uint2*)(vb + (size_t)cii * C + c0);
            float2 f0 = __bfloat1622float2(*(__nv_bfloat162*)&raw.x);
            float2 f1 = __bfloat1622float2(*(__nv_bfloat162*)&raw.y);
            a0 += all * (f0.x + rxx * wv0.x + ryy * wv1.x + rzz * wv2.x + bv.x);
            a1 += all * (f0.y + rxx * wv0.y + ryy * wv1.y + rzz * wv2.y + bv.y);
            a2 += all * (f1.x + rxx * wv0.z + ryy * wv1.z + rzz * wv2.z + bv.z);
            a3 += all * (f1.y + rxx * wv0.w + ryy * wv1.w + rzz * wv2.w + bv.w);
        }
    }

    __nv_bfloat162 o0 = __floats2bfloat162_rn(a0, a1);
    __nv_bfloat162 o1 = __floats2bfloat162_rn(a2, a3);
    __nv_bfloat162* ar = (__nv_bfloat162*)(agg + (size_t)r * C);
    ar[tid * 2]     = o0;
    ar[tid * 2 + 1] = o1;
}

// ---------------- launcher ----------------
extern "C" void kernel_launch(void* const* d_in, const int* in_sizes, int n_in,
                              void* d_out, int out_size) {
    const float* x        = (const float*)d_in[0];
    const int*   row_idx  = (const int*)  d_in[1];
    const int*   col_idx  = (const int*)  d_in[2];
    const int*   tcol_idx = (const int*)  d_in[3];
    const float* pab      = (const float*)d_in[5];
    const float* dist     = (const float*)d_in[6];
    const float* pos      = (const float*)d_in[7];
    const float* col_pos  = (const float*)d_in[8];
    const float* ln1_g    = (const float*)d_in[9];
    const float* ln1_b    = (const float*)d_in[10];
    const float* ln2_g    = (const float*)d_in[11];
    const float* ln2_b    = (const float*)d_in[12];
    const float* Wq       = (const float*)d_in[13];
    const float* bq       = (const float*)d_in[14];
    const float* Wk       = (const float*)d_in[15];
    const float* bk       = (const float*)d_in[16];
    const float* Wv       = (const float*)d_in[17];
    const float* bv       = (const float*)d_in[18];
    const float* Wvec     = (const float*)d_in[19];
    const float* bvec     = (const float*)d_in[20];
    const float* Wo       = (const float*)d_in[21];
    const float* bo       = (const float*)d_in[22];
    const float* W1       = (const float*)d_in[23];
    const float* b1       = (const float*)d_in[24];
    const float* W2       = (const float*)d_in[25];
    const float* b2       = (const float*)d_in[26];
    float* out = (float*)d_out;

    static __nv_bfloat16 *zp = nullptr, *vbp, *aggp, *z2p, *hidp,
                         *wqkvp, *wop, *w1p, *w2p;
    static float *qkvp, *x1p, *bqkvp;
    static int *cntp, *offp, *curp, *eidp;
    static cudaStream_t side = nullptr;
    static cudaEvent_t evFork, evJoin;
    if (!zp) {
        cudaGetSymbolAddress((void**)&zp,    g_z);
        cudaGetSymbolAddress((void**)&qkvp,  g_qkv);
        cudaGetSymbolAddress((void**)&vbp,   g_vb);
        cudaGetSymbolAddress((void**)&aggp,  g_agg);
        cudaGetSymbolAddress((void**)&x1p,   g_x1);
        cudaGetSymbolAddress((void**)&z2p,   g_z2);
        cudaGetSymbolAddress((void**)&hidp,  g_hid);
        cudaGetSymbolAddress((void**)&wqkvp, g_wqkv);
        cudaGetSymbolAddress((void**)&bqkvp, g_bqkv);
        cudaGetSymbolAddress((void**)&wop,   g_wo);
        cudaGetSymbolAddress((void**)&w1p,   g_w1);
        cudaGetSymbolAddress((void**)&w2p,   g_w2);
        cudaGetSymbolAddress((void**)&cntp,  g_cnt);
        cudaGetSymbolAddress((void**)&offp,  g_off);
        cudaGetSymbolAddress((void**)&curp,  g_cur);
        cudaGetSymbolAddress((void**)&eidp,  g_eid);
        cudaFuncSetAttribute(tgemm_kernel<1>,
            cudaFuncAttributeMaxDynamicSharedMemorySize, SMEM_BYTES);
        cudaFuncSetAttribute(tgemm_kernel<2>,
            cudaFuncAttributeMaxDynamicSharedMemorySize, SMEM_BYTES);
        cudaFuncSetAttribute(tgemm_kernel<3>,
            cudaFuncAttributeMaxDynamicSharedMemorySize, SMEM_BYTES);
        cudaStreamCreateWithFlags(&side, cudaStreamNonBlocking);
        cudaEventCreateWithFlags(&evFork, cudaEventDisableTiming);
        cudaEventCreateWithFlags(&evJoin, cudaEventDisableTiming);
    }

    // ---- fork: CSR build on side stream (only feeds row_attn) ----
    cudaEventRecord(evFork, 0);
    cudaStreamWaitEvent(side, evFork, 0);
    zero_cnt_kernel<<<(L + 255) / 256, 256, 0, side>>>(cntp);
    hist_kernel<<<(E + 255) / 256, 256, 0, side>>>(row_idx, cntp);
    scan_kernel<<<1, 1024, 0, side>>>(cntp, offp, curp);
    scatter_kernel<<<(E + 255) / 256, 256, 0, side>>>(row_idx, curp, eidp);
    cudaEventRecord(evJoin, side);

    // ---- main chain ----
    transpose_all_kernel<<<dim3(32, 32, 6), dim3(32, 8)>>>(
        Wq, Wk, Wv, Wo, W1, W2, bq, bk, bv, wqkvp, wop, w1p, w2p, bqkvp);
    ln_kernel<<<L, 128>>>(x, ln1_g, ln1_b, zp);

    dim3 gqkv(NQKV / BN, L / BM);
    tgemm_kernel<3><<<gqkv, 256, SMEM_BYTES>>>(zp, wqkvp, bqkvp, nullptr,
                                               qkvp, vbp, L, NQKV, C);

    // join CSR before row_attn
    cudaStreamWaitEvent(0, evJoin, 0);
    row_attn_kernel<<<L, 128>>>(qkvp, vbp, offp, eidp, col_idx, tcol_idx,
                                pab, dist, pos, col_pos, Wvec, bvec, aggp);

    dim3 g512(C / BN, L / BM);
    tgemm_kernel<2><<<g512, 256, SMEM_BYTES>>>(aggp, wop, bo, x, x1p, nullptr,
                                               L, C, C);

    ln_kernel<<<L, 128>>>(x1p, ln2_g, ln2_b, z2p);

    dim3 g1024(HID / BN, L / BM);
    tgemm_kernel<1><<<g1024, 256, SMEM_BYTES>>>(z2p, w1p, b1, nullptr,
                                                (float*)hidp, nullptr,
                                                L, HID, C);

    tgemm_kernel<2><<<g512, 256, SMEM_BYTES>>>(hidp, w2p, b2, x1p, out,
                                               nullptr, L, C, HID);
}

// round 11
// speedup vs baseline: 4.6123x; 1.0254x over previous
#include <cuda_runtime.h>
#include <cuda_bf16.h>
#include <math.h>
#include <stdint.h>

// Problem constants
#define L   16384
#define E   131072
#define SP  20000
#define C   512
#define H   8
#define DH  64
#define HID 1024
#define NQKV 1536

// ---------------- scratch (device globals: allocation-free) ----------------
__device__ __nv_bfloat16 g_z[(size_t)L * C];
__device__ float         g_qkv[(size_t)L * NQKV];
__device__ __nv_bfloat16 g_kb[(size_t)L * C];     // bf16 copy of k
__device__ __nv_bfloat16 g_vb[(size_t)L * C];     // bf16 copy of v
__device__ __nv_bfloat16 g_agg[(size_t)L * C];
__device__ float         g_x1[(size_t)L * C];
__device__ __nv_bfloat16 g_z2[(size_t)L * C];
__device__ __nv_bfloat16 g_hid[(size_t)L * HID];
// transposed bf16 weights: [N][K]
__device__ __nv_bfloat16 g_wqkv[(size_t)NQKV * C];
__device__ float         g_bqkv[NQKV];
__device__ __nv_bfloat16 g_wo[(size_t)C * C];
__device__ __nv_bfloat16 g_w1[(size_t)HID * C];
__device__ __nv_bfloat16 g_w2[(size_t)C * HID];
// CSR
__device__ int g_cnt[L];
__device__ int g_off[L + 1];
__device__ int g_cur[L];
__device__ int g_eid[E];

// ---------------- helpers ----------------
__device__ __forceinline__ float gelu_tanh(float x) {
    const float k0 = 0.7978845608028654f;
    const float k1 = 0.044715f;
    float x3 = x * x * x;
    return 0.5f * x * (1.0f + tanhf(k0 * (x + k1 * x3)));
}

__device__ __forceinline__ void mma_bf16(float* d, const uint32_t* a,
                                         const uint32_t* b) {
    asm volatile(
        "mma.sync.aligned.m16n8k16.row.col.f32.bf16.bf16.f32 "
        "{%0,%1,%2,%3}, {%4,%5,%6,%7}, {%8,%9}, {%0,%1,%2,%3};\n"
        : "+f"(d[0]), "+f"(d[1]), "+f"(d[2]), "+f"(d[3])
        : "r"(a[0]), "r"(a[1]), "r"(a[2]), "r"(a[3]),
          "r"(b[0]), "r"(b[1]));
}

__device__ __forceinline__ void ldsm_x4(uint32_t* r, uint32_t addr) {
    asm volatile(
        "ldmatrix.sync.aligned.m8n8.x4.shared.b16 {%0,%1,%2,%3}, [%4];\n"
        : "=r"(r[0]), "=r"(r[1]), "=r"(r[2]), "=r"(r[3]) : "r"(addr));
}

__device__ __forceinline__ void cp16(uint32_t dst, const void* src) {
    asm volatile("cp.async.cg.shared.global [%0], [%1], 16;\n"
                 :: "r"(dst), "l"(src));
}
__device__ __forceinline__ void cp_commit() {
    asm volatile("cp.async.commit_group;\n");
}
template <int N>
__device__ __forceinline__ void cp_wait() {
    asm volatile("cp.async.wait_group %0;\n" :: "n"(N));
}
__device__ __forceinline__ uint32_t smem_u32(const void* p) {
    uint32_t a;
    asm("{ .reg .u64 t; cvta.to.shared.u64 t, %1; cvt.u32.u64 %0, t; }"
        : "=r"(a) : "l"(p));
    return a;
}

// swizzled byte offset of 16B chunk c (0..3) in logical row r (64B rows,
// packed 2 per 128B physical row)
__device__ __forceinline__ uint32_t sw_off(int r, int c) {
    return (uint32_t)((r >> 1) * 128 + ((((c + 4 * (r & 1))) ^ ((r >> 1) & 7)) << 4));
}

// ---------------- weight prep: all 6 transposes + bias pack ---------------
__global__ void transpose_all_kernel(const float* __restrict__ Wq,
                                     const float* __restrict__ Wk,
                                     const float* __restrict__ Wv,
                                     const float* __restrict__ Wo,
                                     const float* __restrict__ W1,
                                     const float* __restrict__ W2,
                                     const float* __restrict__ bq,
                                     const float* __restrict__ bk,
                                     const float* __restrict__ bv,
                                     __nv_bfloat16* __restrict__ wqkv,
                                     __nv_bfloat16* __restrict__ wo,
                                     __nv_bfloat16* __restrict__ w1,
                                     __nv_bfloat16* __restrict__ w2,
                                     float* __restrict__ bqkv) {
    int z = blockIdx.z;
    if (z == 0) {
        int bid = blockIdx.y * gridDim.x + blockIdx.x;
        int i = bid * 256 + threadIdx.y * 32 + threadIdx.x;
        if (i < C) {
            bqkv[i]         = bq[i];
            bqkv[C + i]     = bk[i];
            bqkv[2 * C + i] = bv[i];
        }
    }
    const float* src;
    __nv_bfloat16* dst;
    int Kd, Nd;
    if (z == 0)      { src = Wq; dst = wqkv;                     Kd = C;   Nd = C; }
    else if (z == 1) { src = Wk; dst = wqkv + (size_t)C * C;     Kd = C;   Nd = C; }
    else if (z == 2) { src = Wv; dst = wqkv + (size_t)2 * C * C; Kd = C;   Nd = C; }
    else if (z == 3) { src = Wo; dst = wo;                       Kd = C;   Nd = C; }
    else if (z == 4) { src = W1; dst = w1;                       Kd = C;   Nd = HID; }
    else             { src = W2; dst = w2;                       Kd = HID; Nd = C; }
    int kb = blockIdx.y * 32, nb = blockIdx.x * 32;
    if (kb >= Kd || nb >= Nd) return;
    __shared__ float tile[32][33];
    int tx = threadIdx.x, ty = threadIdx.y;   // 32x8
    #pragma unroll
    for (int i = ty; i < 32; i += 8)
        tile[i][tx] = src[(size_t)(kb + i) * Nd + nb + tx];
    __syncthreads();
    #pragma unroll
    for (int i = ty; i < 32; i += 8)
        dst[(size_t)(nb + i) * Kd + kb + tx] = __float2bfloat16_rn(tile[tx][i]);
}

// ---------------- LayerNorm (bf16 output) ----------------
__global__ void ln_kernel(const float* __restrict__ x,
                          const float* __restrict__ g,
                          const float* __restrict__ b,
                          __nv_bfloat16* __restrict__ z) {
    int row = blockIdx.x;
    int t = threadIdx.x;                 // 0..127
    const float* xr = x + (size_t)row * C;
    float4 v4 = *(const float4*)(xr + t * 4);
    float s  = v4.x + v4.y + v4.z + v4.w;
    float ss = v4.x * v4.x + v4.y * v4.y + v4.z * v4.z + v4.w * v4.w;
    #pragma unroll
    for (int o = 16; o > 0; o >>= 1) {
        s  += __shfl_xor_sync(0xffffffffu, s, o);
        ss += __shfl_xor_sync(0xffffffffu, ss, o);
    }
    __shared__ float sh[4], sh2[4];
    int w = t >> 5;
    if ((t & 31) == 0) { sh[w] = s; sh2[w] = ss; }
    __syncthreads();
    float sum  = sh[0] + sh[1] + sh[2] + sh[3];
    float sum2 = sh2[0] + sh2[1] + sh2[2] + sh2[3];
    float mean = sum * (1.0f / C);
    float var  = sum2 * (1.0f / C) - mean * mean;
    float inv  = rsqrtf(var + 1e-5f);
    float4 g4 = *(const float4*)(g + t * 4);
    float4 b4 = *(const float4*)(b + t * 4);
    __nv_bfloat162 p0 = __floats2bfloat162_rn(
        (v4.x - mean) * inv * g4.x + b4.x, (v4.y - mean) * inv * g4.y + b4.y);
    __nv_bfloat162 p1 = __floats2bfloat162_rn(
        (v4.z - mean) * inv * g4.z + b4.z, (v4.w - mean) * inv * g4.w + b4.w);
    __nv_bfloat162* zr = (__nv_bfloat162*)(z + (size_t)row * C);
    zr[t * 2]     = p0;
    zr[t * 2 + 1] = p1;
}

// ---------------- bf16 tensor-core GEMM ----------------
// EPI: 1 bias+gelu->bf16, 2 bias+residual->fp32,
//      3 bias->fp32 + bf16 k/v side-copies
#define BM  128
#define BN  128
#define BK  32
#define STAGES 4
#define STAGE_BYTES 8192
#define SMEM_BYTES (STAGES * 2 * STAGE_BYTES)   // 65536

template <int EPI>
__global__ __launch_bounds__(256, 2)
void tgemm_kernel(const __nv_bfloat16* __restrict__ A,
                  const __nv_bfloat16* __restrict__ B,
                  const float* __restrict__ bias, const float* __restrict__ res,
                  float* __restrict__ Cmat,
                  __nv_bfloat16* __restrict__ kb,
                  __nv_bfloat16* __restrict__ vb,
                  int M, int N, int K) {
    extern __shared__ float smemf[];
    const uint32_t sA = smem_u32(smemf);
    const uint32_t sB = sA + STAGES * STAGE_BYTES;

    const int tid    = threadIdx.x;
    const int lane   = tid & 31;
    const int wid    = tid >> 5;
    const int warp_m = wid & 3;
    const int warp_n = wid >> 2;

    const int brow = blockIdx.y * BM;
    const int bcol = blockIdx.x * BN;

    float acc[2][8][4];
    #pragma unroll
    for (int i = 0; i < 2; i++)
        #pragma unroll
        for (int j = 0; j < 8; j++)
            #pragma unroll
            for (int c = 0; c < 4; c++) acc[i][j][c] = 0.0f;

    const int lr = tid >> 1;
    const int c0 = (tid & 1) * 2;
    const __nv_bfloat16* A0 = A + (size_t)(brow + lr) * K + c0 * 8;
    const __nv_bfloat16* B0 = B + (size_t)(bcol + lr) * K + c0 * 8;
    const uint32_t dA0 = sA + sw_off(lr, c0);
    const uint32_t dA1 = sA + sw_off(lr, c0 + 1);
    const uint32_t dB0 = sB + sw_off(lr, c0);
    const uint32_t dB1 = sB + sw_off(lr, c0 + 1);

    const int m8    = lane >> 3;
    const int rowin = lane & 7;
    int rA[2], cAh = m8 >> 1;
    rA[0] = warp_m * 32 + (m8 & 1) * 8 + rowin;
    rA[1] = rA[0] + 16;
    int rB[4], cBh = m8 & 1;
    #pragma unroll
    for (int np = 0; np < 4; np++)
        rB[np] = warp_n * 64 + np * 16 + (m8 >> 1) * 8 + rowin;

    const int kIters = K / BK;

    #pragma unroll
    for (int s = 0; s < STAGES - 1; s++) {
        int k0 = s * BK;
        uint32_t so = (uint32_t)s * STAGE_BYTES;
        cp16(dA0 + so, A0 + k0);
        cp16(dA1 + so, A0 + k0 + 8);
        cp16(dB0 + so, B0 + k0);
        cp16(dB1 + so, B0 + k0 + 8);
        cp_commit();
    }

    int buf = 0;
    int nbuf = STAGES - 1;
    for (int s = 0; s < kIters; s++) {
        cp_wait<STAGES - 2>();
        __syncthreads();

        if (s + STAGES - 1 < kIters) {
            int k0 = (s + STAGES - 1) * BK;
            uint32_t so = (uint32_t)nbuf * STAGE_BYTES;
            cp16(dA0 + so, A0 + k0);
            cp16(dA1 + so, A0 + k0 + 8);
            cp16(dB0 + so, B0 + k0);
            cp16(dB1 + so, B0 + k0 + 8);
        }
        cp_commit();

        const uint32_t aBuf = sA + (uint32_t)buf * STAGE_BYTES;
        const uint32_t bBuf = sB + (uint32_t)buf * STAGE_BYTES;
        #pragma unroll
        for (int ks = 0; ks < 2; ks++) {
            uint32_t af[2][4];
            #pragma unroll
            for (int mt = 0; mt < 2; mt++)
                ldsm_x4(af[mt], aBuf + sw_off(rA[mt], 2 * ks + cAh));
            #pragma unroll
            for (int np = 0; np < 4; np++) {
                uint32_t bf[4];
                ldsm_x4(bf, bBuf + sw_off(rB[np], 2 * ks + cBh));
                mma_bf16(acc[0][2 * np],     af[0], bf);
                mma_bf16(acc[1][2 * np],     af[1], bf);
                mma_bf16(acc[0][2 * np + 1], af[0], bf + 2);
                mma_bf16(acc[1][2 * np + 1], af[1], bf + 2);
            }
        }
        buf = (buf + 1 == STAGES) ? 0 : buf + 1;
        nbuf = (nbuf + 1 == STAGES) ? 0 : nbuf + 1;
    }

    const int grp = lane >> 2;
    const int t4  = lane & 3;
    #pragma unroll
    for (int mt = 0; mt < 2; mt++) {
        int row = brow + warp_m * 32 + mt * 16 + grp;
        #pragma unroll
        for (int nt = 0; nt < 8; nt++) {
            int col = bcol + warp_n * 64 + nt * 8 + 2 * t4;
            float b0 = bias[col], b1 = bias[col + 1];
            float v0 = acc[mt][nt][0] + b0;
            float v1 = acc[mt][nt][1] + b1;
            float v2 = acc[mt][nt][2] + b0;
            float v3 = acc[mt][nt][3] + b1;
            if (EPI == 1) {
                __nv_bfloat16* O = (__nv_bfloat16*)Cmat;
                __nv_bfloat162 o0 = __floats2bfloat162_rn(gelu_tanh(v0),
                                                          gelu_tanh(v1));
                __nv_bfloat162 o1 = __floats2bfloat162_rn(gelu_tanh(v2),
                                                          gelu_tanh(v3));
                *(__nv_bfloat162*)&O[(size_t)row * N + col]       = o0;
                *(__nv_bfloat162*)&O[(size_t)(row + 8) * N + col] = o1;
            } else {
                if (EPI == 2) {
                    v0 += res[(size_t)row * N + col];
                    v1 += res[(size_t)row * N + col + 1];
                    v2 += res[(size_t)(row + 8) * N + col];
                    v3 += res[(size_t)(row + 8) * N + col + 1];
                }
                float2 o0 = { v0, v1 };
                float2 o1 = { v2, v3 };
                *(float2*)&Cmat[(size_t)row * N + col]       = o0;
                *(float2*)&Cmat[(size_t)(row + 8) * N + col] = o1;
                if (EPI == 3 && col >= C) {
                    __nv_bfloat162 p0 = __floats2bfloat162_rn(v0, v1);
                    __nv_bfloat162 p1 = __floats2bfloat162_rn(v2, v3);
                    if (col >= 2 * C) {
                        int vc = col - 2 * C;
                        *(__nv_bfloat162*)&vb[(size_t)row * C + vc]       = p0;
                        *(__nv_bfloat162*)&vb[(size_t)(row + 8) * C + vc] = p1;
                    } else {
                        int kc = col - C;
                        *(__nv_bfloat162*)&kb[(size_t)row * C + kc]       = p0;
                        *(__nv_bfloat162*)&kb[(size_t)(row + 8) * C + kc] = p1;
                    }
                }
            }
        }
    }
}

// ---------------- CSR build ----------------
__global__ void zero_cnt_kernel(int* __restrict__ cnt) {
    int i = blockIdx.x * blockDim.x + threadIdx.x;
    if (i < L) cnt[i] = 0;
}
__global__ void hist_kernel(const int* __restrict__ row, int* __restrict__ cnt) {
    int e = blockIdx.x * blockDim.x + threadIdx.x;
    if (e < E) atomicAdd(&cnt[row[e]], 1);
}
__global__ void scan_kernel(const int* __restrict__ cnt, int* __restrict__ off,
                            int* __restrict__ cur) {
    __shared__ int ws[32];
    int tid = threadIdx.x;
    int base = tid * 16;
    int loc[16];
    int s = 0;
    #pragma unroll
    for (int i = 0; i < 16; i++) { loc[i] = s; s += cnt[base + i]; }
    int lane = tid & 31, w = tid >> 5;
    int v = s;
    #pragma unroll
    for (int o = 1; o < 32; o <<= 1) {
        int t = __shfl_up_sync(0xffffffffu, v, o);
        if (lane >= o) v += t;
    }
    if (lane == 31) ws[w] = v;
    __syncthreads();
    if (w == 0) {
        int t = ws[lane];
        #pragma unroll
        for (int o = 1; o < 32; o <<= 1) {
            int u = __shfl_up_sync(0xffffffffu, t, o);
            if (lane >= o) t += u;
        }
        ws[lane] = t;
    }
    __syncthreads();
    int excl = v - s + (w > 0 ? ws[w - 1] : 0);
    #pragma unroll
    for (int i = 0; i < 16; i++) {
        off[base + i] = excl + loc[i];
        cur[base + i] = excl + loc[i];
    }
    if (tid == 1023) off[L] = excl + s;
}
__global__ void scatter_kernel(const int* __restrict__ row,
                               int* __restrict__ cur, int* __restrict__ eid) {
    int e = blockIdx.x * blockDim.x + threadIdx.x;
    if (e < E) {
        int p = atomicAdd(&cur[row[e]], 1);
        eid[p] = e;
    }
}

// ---------------- fused edge score + softmax + aggregation ----------------
#define DMAX 64
__global__ __launch_bounds__(128)
void row_attn_kernel(const float* __restrict__ qkv,
                     const __nv_bfloat16* __restrict__ kb,
                     const __nv_bfloat16* __restrict__ vb,
                     const int* __restrict__ off,
                     const int* __restrict__ eid,
                     const int* __restrict__ col_index,
                     const int* __restrict__ to_col_index,
                     const float* __restrict__ pab,
                     const float* __restrict__ dist,
                     const float* __restrict__ pos,
                     const float* __restrict__ col_pos,
                     const float* __restrict__ Wvec,
                     const float* __restrict__ bvec,
                     __nv_bfloat16* __restrict__ agg) {
    int r = blockIdx.x;
    int tid = threadIdx.x;          // 128
    int lane = tid & 31;
    int w = tid >> 5;               // warp 0..3
    int beg = off[r];
    int deg = off[r + 1] - beg;

    __shared__ float s_q[C];
    __shared__ float s_den[H];
    __shared__ float s_px[DMAX][H];
    __shared__ float s_mt[DMAX][4];

    for (int i = tid; i < C / 4; i += 128)
        ((float4*)s_q)[i] = ((const float4*)(qkv + (size_t)r * NQKV))[i];
    if (tid < H) s_den[tid] = 0.0f;
    __syncthreads();

    float px0 = pos[r * 3 + 0], px1 = pos[r * 3 + 1], px2 = pos[r * 3 + 2];

    // ---- pass 1: scores from bf16 k; den; cache pexp/meta ----
    for (int i0 = w; i0 < deg; i0 += 4) {
        int e = eid[beg + i0];
        int ci = col_index[e];
        const __nv_bfloat162* kr =
            (const __nv_bfloat162*)(kb + (size_t)ci * C);
        float sc[H];
        #pragma unroll
        for (int h = 0; h < H; h++) {
            float2 kf = __bfloat1622float2(kr[h * 32 + lane]);
            float d0 = s_q[h * DH + 2 * lane]     - kf.x;
            float d1 = s_q[h * DH + 2 * lane + 1] - kf.y;
            float s = d0 * d0 + d1 * d1;
            #pragma unroll
            for (int o = 16; o > 0; o >>= 1)
                s += __shfl_xor_sync(0xffffffffu, s, o);
            sc[h] = s;
        }
        if (lane < H) {
            float val = __expf(-sc[lane] * 0.125f + pab[(size_t)e * H + lane]);
            atomicAdd(&s_den[lane], val);
            if (i0 < DMAX) s_px[i0][lane] = val;
        }
        if (lane == 8 && i0 < DMAX) {
            int tci = to_col_index[e];
            float dinv = 1.0f / dist[e];
            s_mt[i0][0] = __int_as_float(ci);
            s_mt[i0][1] = (col_pos[tci * 3 + 0] - px0) * dinv;
            s_mt[i0][2] = (col_pos[tci * 3 + 1] - px1) * dinv;
            s_mt[i0][3] = (col_pos[tci * 3 + 2] - px2) * dinv;
        }
    }
    __syncthreads();
    if (tid < H) {
        float d = s_den[tid];
        s_den[tid] = (d == 0.0f) ? 1.0f : 1.0f / d;
    }
    __syncthreads();

    // ---- pass 2: channel-parallel aggregation, 4-edge pipeline, bf16 v ----
    int c0 = tid * 4;
    int hh = c0 >> 6;
    float4 wv0 = *(const float4*)(Wvec + c0);
    float4 wv1 = *(const float4*)(Wvec + C + c0);
    float4 wv2 = *(const float4*)(Wvec + 2 * C + c0);
    float4 bv  = *(const float4*)(bvec + c0);
    float dinvh = s_den[hh];

    float a0 = 0.0f, a1 = 0.0f, a2 = 0.0f, a3 = 0.0f;
    int ncache = deg < DMAX ? deg : DMAX;
    int i = 0;
    for (; i + 4 <= ncache; i += 4) {
        int   ci[4];
        float rx[4], ry[4], rz[4], al[4];
        #pragma unroll
        for (int j = 0; j < 4; j++) {
            ci[j] = __float_as_int(s_mt[i + j][0]);
            rx[j] = s_mt[i + j][1];
            ry[j] = s_mt[i + j][2];
            rz[j] = s_mt[i + j][3];
            al[j] = s_px[i + j][hh] * dinvh;
        }
        uint2 raw[4];
        #pragma unroll
        for (int j = 0; j < 4; j++)
            raw[j] = *(const uint2*)(vb + (size_t)ci[j] * C + c0);
        #pragma unroll
        for (int j = 0; j < 4; j++) {
            float2 f0 = __bfloat1622float2(*(__nv_bfloat162*)&raw[j].x);
            float2 f1 = __bfloat1622float2(*(__nv_bfloat162*)&raw[j].y);
            a0 += al[j] * (f0.x + rx[j] * wv0.x + ry[j] * wv1.x + rz[j] * wv2.x + bv.x);
            a1 += al[j] * (f0.y + rx[j] * wv0.y + ry[j] * wv1.y + rz[j] * wv2.y + bv.y);
            a2 += al[j] * (f1.x + rx[j] * wv0.z + ry[j] * wv1.z + rz[j] * wv2.z + bv.z);
            a3 += al[j] * (f1.y + rx[j] * wv0.w + ry[j] * wv1.w + rz[j] * wv2.w + bv.w);
        }
    }
    for (; i < ncache; i++) {
        int cii = __float_as_int(s_mt[i][0]);
        float rxx = s_mt[i][1], ryy = s_mt[i][2], rzz = s_mt[i][3];
        float all = s_px[i][hh] * dinvh;
        uint2 raw = *(const uint2*)(vb + (size_t)cii * C + c0);
        float2 f0 = __bfloat1622float2(*(__nv_bfloat162*)&raw.x);
        float2 f1 = __bfloat1622float2(*(__nv_bfloat162*)&raw.y);
        a0 += all * (f0.x + rxx * wv0.x + ryy * wv1.x + rzz * wv2.x + bv.x);
        a1 += all * (f0.y + rxx * wv0.y + ryy * wv1.y + rzz * wv2.y + bv.y);
        a2 += all * (f1.x + rxx * wv0.z + ryy * wv1.z + rzz * wv2.z + bv.z);
        a3 += all * (f1.y + rxx * wv0.w + ryy * wv1.w + rzz * wv2.w + bv.w);
    }
    // overflow fallback (deg > DMAX): recompute scores in chunks of 16
    for (int base = DMAX; base < deg; base += 16) {
        int n = min(16, deg - base);
        __syncthreads();
        for (int j = w; j < n; j += 4) {
            int e = eid[beg + base + j];
            int ci = col_index[e];
            const __nv_bfloat162* kr =
                (const __nv_bfloat162*)(kb + (size_t)ci * C);
            float sc[H];
            #pragma unroll
            for (int h = 0; h < H; h++) {
                float2 kf = __bfloat1622float2(kr[h * 32 + lane]);
                float d0 = s_q[h * DH + 2 * lane]     - kf.x;
                float d1 = s_q[h * DH + 2 * lane + 1] - kf.y;
                float s = d0 * d0 + d1 * d1;
                #pragma unroll
                for (int o = 16; o > 0; o >>= 1)
                    s += __shfl_xor_sync(0xffffffffu, s, o);
                sc[h] = s;
            }
            if (lane < H)
                s_px[j][lane] = __expf(-sc[lane] * 0.125f + pab[(size_t)e * H + lane]);
            if (lane == 8) {
                int tci = to_col_index[e];
                float dinv = 1.0f / dist[e];
                s_mt[j][0] = __int_as_float(ci);
                s_mt[j][1] = (col_pos[tci * 3 + 0] - px0) * dinv;
                s_mt[j][2] = (col_pos[tci * 3 + 1] - px1) * dinv;
                s_mt[j][3] = (col_pos[tci * 3 + 2] - px2) * dinv;
            }
        }
        __syncthreads();
        for (int ii = 0; ii < n; ii++) {
            int cii = __float_as_int(s_mt[ii][0]);
            float rxx = s_mt[ii][1], ryy = s_mt[ii][2], rzz = s_mt[ii][3];
            float all = s_px[ii][hh] * dinvh;
            uint2 raw = *(const uint2*)(vb + (size_t)cii * C + c0);
            float2 f0 = __bfloat1622float2(*(__nv_bfloat162*)&raw.x);
            float2 f1 = __bfloat1622float2(*(__nv_bfloat162*)&raw.y);
            a0 += all * (f0.x + rxx * wv0.x + ryy * wv1.x + rzz * wv2.x + bv.x);
            a1 += all * (f0.y + rxx * wv0.y + ryy * wv1.y + rzz * wv2.y + bv.y);
            a2 += all * (f1.x + rxx * wv0.z + ryy * wv1.z + rzz * wv2.z + bv.z);
            a3 += all * (f1.y + rxx * wv0.w + ryy * wv1.w + rzz * wv2.w + bv.w);
        }
    }

    __nv_bfloat162 o0 = __floats2bfloat162_rn(a0, a1);
    __nv_bfloat162 o1 = __floats2bfloat162_rn(a2, a3);
    __nv_bfloat162* ar = (__nv_bfloat162*)(agg + (size_t)r * C);
    ar[tid * 2]     = o0;
    ar[tid * 2 + 1] = o1;
}

// ---------------- launcher ----------------
extern "C" void kernel_launch(void* const* d_in, const int* in_sizes, int n_in,
                              void* d_out, int out_size) {
    const float* x        = (const float*)d_in[0];
    const int*   row_idx  = (const int*)  d_in[1];
    const int*   col_idx  = (const int*)  d_in[2];
    const int*   tcol_idx = (const int*)  d_in[3];
    const float* pab      = (const float*)d_in[5];
    const float* dist     = (const float*)d_in[6];
    const float* pos      = (const float*)d_in[7];
    const float* col_pos  = (const float*)d_in[8];
    const float* ln1_g    = (const float*)d_in[9];
    const float* ln1_b    = (const float*)d_in[10];
    const float* ln2_g    = (const float*)d_in[11];
    const float* ln2_b    = (const float*)d_in[12];
    const float* Wq       = (const float*)d_in[13];
    const float* bq       = (const float*)d_in[14];
    const float* Wk       = (const float*)d_in[15];
    const float* bk       = (const float*)d_in[16];
    const float* Wv       = (const float*)d_in[17];
    const float* bv       = (const float*)d_in[18];
    const float* Wvec     = (const float*)d_in[19];
    const float* bvec     = (const float*)d_in[20];
    const float* Wo       = (const float*)d_in[21];
    const float* bo       = (const float*)d_in[22];
    const float* W1       = (const float*)d_in[23];
    const float* b1       = (const float*)d_in[24];
    const float* W2       = (const float*)d_in[25];
    const float* b2       = (const float*)d_in[26];
    float* out = (float*)d_out;

    static __nv_bfloat16 *zp = nullptr, *kbp, *vbp, *aggp, *z2p, *hidp,
                         *wqkvp, *wop, *w1p, *w2p;
    static float *qkvp, *x1p, *bqkvp;
    static int *cntp, *offp, *curp, *eidp;
    static cudaStream_t side = nullptr, side2 = nullptr;
    static cudaEvent_t evFork, evJoin, evLn;
    if (!zp) {
        cudaGetSymbolAddress((void**)&zp,    g_z);
        cudaGetSymbolAddress((void**)&qkvp,  g_qkv);
        cudaGetSymbolAddress((void**)&kbp,   g_kb);
        cudaGetSymbolAddress((void**)&vbp,   g_vb);
        cudaGetSymbolAddress((void**)&aggp,  g_agg);
        cudaGetSymbolAddress((void**)&x1p,   g_x1);
        cudaGetSymbolAddress((void**)&z2p,   g_z2);
        cudaGetSymbolAddress((void**)&hidp,  g_hid);
        cudaGetSymbolAddress((void**)&wqkvp, g_wqkv);
        cudaGetSymbolAddress((void**)&bqkvp, g_bqkv);
        cudaGetSymbolAddress((void**)&wop,   g_wo);
        cudaGetSymbolAddress((void**)&w1p,   g_w1);
        cudaGetSymbolAddress((void**)&w2p,   g_w2);
        cudaGetSymbolAddress((void**)&cntp,  g_cnt);
        cudaGetSymbolAddress((void**)&offp,  g_off);
        cudaGetSymbolAddress((void**)&curp,  g_cur);
        cudaGetSymbolAddress((void**)&eidp,  g_eid);
        cudaFuncSetAttribute(tgemm_kernel<1>,
            cudaFuncAttributeMaxDynamicSharedMemorySize, SMEM_BYTES);
        cudaFuncSetAttribute(tgemm_kernel<2>,
            cudaFuncAttributeMaxDynamicSharedMemorySize, SMEM_BYTES);
        cudaFuncSetAttribute(tgemm_kernel<3>,
            cudaFuncAttributeMaxDynamicSharedMemorySize, SMEM_BYTES);
        cudaStreamCreateWithFlags(&side, cudaStreamNonBlocking);
        cudaStreamCreateWithFlags(&side2, cudaStreamNonBlocking);
        cudaEventCreateWithFlags(&evFork, cudaEventDisableTiming);
        cudaEventCreateWithFlags(&evJoin, cudaEventDisableTiming);
        cudaEventCreateWithFlags(&evLn,   cudaEventDisableTiming);
    }

    // ---- fork ----
    cudaEventRecord(evFork, 0);
    cudaStreamWaitEvent(side, evFork, 0);
    cudaStreamWaitEvent(side2, evFork, 0);

    // side: CSR build (only feeds row_attn)
    zero_cnt_kernel<<<(L + 255) / 256, 256, 0, side>>>(cntp);
    hist_kernel<<<(E + 255) / 256, 256, 0, side>>>(row_idx, cntp);
    scan_kernel<<<1, 1024, 0, side>>>(cntp, offp, curp);
    scatter_kernel<<<(E + 255) / 256, 256, 0, side>>>(row_idx, curp, eidp);
    cudaEventRecord(evJoin, side);

    // side2: LN1 (needs x only)
    ln_kernel<<<L, 128, 0, side2>>>(x, ln1_g, ln1_b, zp);
    cudaEventRecord(evLn, side2);

    // main: weight transposes (concurrent with LN1)
    transpose_all_kernel<<<dim3(32, 32, 6), dim3(32, 8)>>>(
        Wq, Wk, Wv, Wo, W1, W2, bq, bk, bv, wqkvp, wop, w1p, w2p, bqkvp);

    // QKV needs z (LN1) + transposed weights
    cudaStreamWaitEvent(0, evLn, 0);
    dim3 gqkv(NQKV / BN, L / BM);
    tgemm_kernel<3><<<gqkv, 256, SMEM_BYTES>>>(zp, wqkvp, bqkvp, nullptr,
                                               qkvp, kbp, vbp, L, NQKV, C);

    // join CSR before row_attn
    cudaStreamWaitEvent(0, evJoin, 0);
    row_attn_kernel<<<L, 128>>>(qkvp, kbp, vbp, offp, eidp, col_idx, tcol_idx,
                                pab, dist, pos, col_pos, Wvec, bvec, aggp);

    dim3 g512(C / BN, L / BM);
    tgemm_kernel<2><<<g512, 256, SMEM_BYTES>>>(aggp, wop, bo, x, x1p,
                                               nullptr, nullptr, L, C, C);

    ln_kernel<<<L, 128>>>(x1p, ln2_g, ln2_b, z2p);

    dim3 g1024(HID / BN, L / BM);
    tgemm_kernel<1><<<g1024, 256, SMEM_BYTES>>>(z2p, w1p, b1, nullptr,
                                                (float*)hidp, nullptr, nullptr,
                                                L, HID, C);

    tgemm_kernel<2><<<g512, 256, SMEM_BYTES>>>(hidp, w2p, b2, x1p, out,
                                               nullptr, nullptr, L, C, HID);
}

// round 12
// speedup vs baseline: 4.8211x; 1.0453x over previous
#include <cuda_runtime.h>
#include <cuda_bf16.h>
#include <math.h>
#include <stdint.h>

// Problem constants
#define L   16384
#define E   131072
#define SP  20000
#define C   512
#define H   8
#define DH  64
#define HID 1024
#define NQKV 1536

// ---------------- scratch (device globals: allocation-free) ----------------
__device__ __nv_bfloat16 g_z[(size_t)L * C];
__device__ __nv_bfloat16 g_qb[(size_t)L * C];     // bf16 q
__device__ __nv_bfloat16 g_kb[(size_t)L * C];     // bf16 k
__device__ __nv_bfloat16 g_vb[(size_t)L * C];     // bf16 v
__device__ __nv_bfloat16 g_agg[(size_t)L * C];
__device__ float         g_x1[(size_t)L * C];
__device__ __nv_bfloat16 g_z2[(size_t)L * C];
__device__ __nv_bfloat16 g_hid[(size_t)L * HID];
// transposed bf16 weights: [N][K]
__device__ __nv_bfloat16 g_wqkv[(size_t)NQKV * C];
__device__ float         g_bqkv[NQKV];
__device__ __nv_bfloat16 g_wo[(size_t)C * C];
__device__ __nv_bfloat16 g_w1[(size_t)HID * C];
__device__ __nv_bfloat16 g_w2[(size_t)C * HID];
// CSR
__device__ int g_cnt[L];
__device__ int g_off[L + 1];
__device__ int g_cur[L];
__device__ int g_eid[E];

// ---------------- helpers ----------------
__device__ __forceinline__ float gelu_tanh(float x) {
    const float k0 = 0.7978845608028654f;
    const float k1 = 0.044715f;
    float x3 = x * x * x;
    return 0.5f * x * (1.0f + tanhf(k0 * (x + k1 * x3)));
}

__device__ __forceinline__ void mma_bf16(float* d, const uint32_t* a,
                                         const uint32_t* b) {
    asm volatile(
        "mma.sync.aligned.m16n8k16.row.col.f32.bf16.bf16.f32 "
        "{%0,%1,%2,%3}, {%4,%5,%6,%7}, {%8,%9}, {%0,%1,%2,%3};\n"
        : "+f"(d[0]), "+f"(d[1]), "+f"(d[2]), "+f"(d[3])
        : "r"(a[0]), "r"(a[1]), "r"(a[2]), "r"(a[3]),
          "r"(b[0]), "r"(b[1]));
}

__device__ __forceinline__ void ldsm_x4(uint32_t* r, uint32_t addr) {
    asm volatile(
        "ldmatrix.sync.aligned.m8n8.x4.shared.b16 {%0,%1,%2,%3}, [%4];\n"
        : "=r"(r[0]), "=r"(r[1]), "=r"(r[2]), "=r"(r[3]) : "r"(addr));
}

__device__ __forceinline__ void cp16(uint32_t dst, const void* src) {
    asm volatile("cp.async.cg.shared.global [%0], [%1], 16;\n"
                 :: "r"(dst), "l"(src));
}
__device__ __forceinline__ void cp_commit() {
    asm volatile("cp.async.commit_group;\n");
}
template <int N>
__device__ __forceinline__ void cp_wait() {
    asm volatile("cp.async.wait_group %0;\n" :: "n"(N));
}
__device__ __forceinline__ uint32_t smem_u32(const void* p) {
    uint32_t a;
    asm("{ .reg .u64 t; cvta.to.shared.u64 t, %1; cvt.u32.u64 %0, t; }"
        : "=r"(a) : "l"(p));
    return a;
}

// unpack uint4 (8 bf16) into 8 floats
__device__ __forceinline__ void unpack8(const uint4& u, float* f) {
    float2 t;
    t = __bfloat1622float2(*(const __nv_bfloat162*)&u.x); f[0] = t.x; f[1] = t.y;
    t = __bfloat1622float2(*(const __nv_bfloat162*)&u.y); f[2] = t.x; f[3] = t.y;
    t = __bfloat1622float2(*(const __nv_bfloat162*)&u.z); f[4] = t.x; f[5] = t.y;
    t = __bfloat1622float2(*(const __nv_bfloat162*)&u.w); f[6] = t.x; f[7] = t.y;
}

// swizzled byte offset of 16B chunk c (0..3) in logical row r (64B rows,
// packed 2 per 128B physical row)
__device__ __forceinline__ uint32_t sw_off(int r, int c) {
    return (uint32_t)((r >> 1) * 128 + ((((c + 4 * (r & 1))) ^ ((r >> 1) & 7)) << 4));
}

// ---------------- weight prep: all 6 transposes + bias pack ---------------
__global__ void transpose_all_kernel(const float* __restrict__ Wq,
                                     const float* __restrict__ Wk,
                                     const float* __restrict__ Wv,
                                     const float* __restrict__ Wo,
                                     const float* __restrict__ W1,
                                     const float* __restrict__ W2,
                                     const float* __restrict__ bq,
                                     const float* __restrict__ bk,
                                     const float* __restrict__ bv,
                                     __nv_bfloat16* __restrict__ wqkv,
                                     __nv_bfloat16* __restrict__ wo,
                                     __nv_bfloat16* __restrict__ w1,
                                     __nv_bfloat16* __restrict__ w2,
                                     float* __restrict__ bqkv) {
    int z = blockIdx.z;
    if (z == 0) {
        int bid = blockIdx.y * gridDim.x + blockIdx.x;
        int i = bid * 256 + threadIdx.y * 32 + threadIdx.x;
        if (i < C) {
            bqkv[i]         = bq[i];
            bqkv[C + i]     = bk[i];
            bqkv[2 * C + i] = bv[i];
        }
    }
    const float* src;
    __nv_bfloat16* dst;
    int Kd, Nd;
    if (z == 0)      { src = Wq; dst = wqkv;                     Kd = C;   Nd = C; }
    else if (z == 1) { src = Wk; dst = wqkv + (size_t)C * C;     Kd = C;   Nd = C; }
    else if (z == 2) { src = Wv; dst = wqkv + (size_t)2 * C * C; Kd = C;   Nd = C; }
    else if (z == 3) { src = Wo; dst = wo;                       Kd = C;   Nd = C; }
    else if (z == 4) { src = W1; dst = w1;                       Kd = C;   Nd = HID; }
    else             { src = W2; dst = w2;                       Kd = HID; Nd = C; }
    int kb = blockIdx.y * 32, nb = blockIdx.x * 32;
    if (kb >= Kd || nb >= Nd) return;
    __shared__ float tile[32][33];
    int tx = threadIdx.x, ty = threadIdx.y;   // 32x8
    #pragma unroll
    for (int i = ty; i < 32; i += 8)
        tile[i][tx] = src[(size_t)(kb + i) * Nd + nb + tx];
    __syncthreads();
    #pragma unroll
    for (int i = ty; i < 32; i += 8)
        dst[(size_t)(nb + i) * Kd + kb + tx] = __float2bfloat16_rn(tile[tx][i]);
}

// ---------------- LayerNorm (bf16 output) ----------------
__global__ void ln_kernel(const float* __restrict__ x,
                          const float* __restrict__ g,
                          const float* __restrict__ b,
                          __nv_bfloat16* __restrict__ z) {
    int row = blockIdx.x;
    int t = threadIdx.x;                 // 0..127
    const float* xr = x + (size_t)row * C;
    float4 v4 = *(const float4*)(xr + t * 4);
    float s  = v4.x + v4.y + v4.z + v4.w;
    float ss = v4.x * v4.x + v4.y * v4.y + v4.z * v4.z + v4.w * v4.w;
    #pragma unroll
    for (int o = 16; o > 0; o >>= 1) {
        s  += __shfl_xor_sync(0xffffffffu, s, o);
        ss += __shfl_xor_sync(0xffffffffu, ss, o);
    }
    __shared__ float sh[4], sh2[4];
    int w = t >> 5;
    if ((t & 31) == 0) { sh[w] = s; sh2[w] = ss; }
    __syncthreads();
    float sum  = sh[0] + sh[1] + sh[2] + sh[3];
    float sum2 = sh2[0] + sh2[1] + sh2[2] + sh2[3];
    float mean = sum * (1.0f / C);
    float var  = sum2 * (1.0f / C) - mean * mean;
    float inv  = rsqrtf(var + 1e-5f);
    float4 g4 = *(const float4*)(g + t * 4);
    float4 b4 = *(const float4*)(b + t * 4);
    __nv_bfloat162 p0 = __floats2bfloat162_rn(
        (v4.x - mean) * inv * g4.x + b4.x, (v4.y - mean) * inv * g4.y + b4.y);
    __nv_bfloat162 p1 = __floats2bfloat162_rn(
        (v4.z - mean) * inv * g4.z + b4.z, (v4.w - mean) * inv * g4.w + b4.w);
    __nv_bfloat162* zr = (__nv_bfloat162*)(z + (size_t)row * C);
    zr[t * 2]     = p0;
    zr[t * 2 + 1] = p1;
}

// ---------------- bf16 tensor-core GEMM ----------------
// EPI: 1 bias+gelu->bf16, 2 bias+residual->fp32,
//      3 bias->bf16 q/k/v planes (no fp32 output)
#define BM  128
#define BN  128
#define BK  32
#define STAGES 4
#define STAGE_BYTES 8192
#define SMEM_BYTES (STAGES * 2 * STAGE_BYTES)   // 65536

template <int EPI>
__global__ __launch_bounds__(256, 2)
void tgemm_kernel(const __nv_bfloat16* __restrict__ A,
                  const __nv_bfloat16* __restrict__ B,
                  const float* __restrict__ bias, const float* __restrict__ res,
                  float* __restrict__ Cmat,
                  __nv_bfloat16* __restrict__ qb,
                  __nv_bfloat16* __restrict__ kb,
                  __nv_bfloat16* __restrict__ vb,
                  int M, int N, int K) {
    extern __shared__ float smemf[];
    const uint32_t sA = smem_u32(smemf);
    const uint32_t sB = sA + STAGES * STAGE_BYTES;

    const int tid    = threadIdx.x;
    const int lane   = tid & 31;
    const int wid    = tid >> 5;
    const int warp_m = wid & 3;
    const int warp_n = wid >> 2;

    const int brow = blockIdx.y * BM;
    const int bcol = blockIdx.x * BN;

    float acc[2][8][4];
    #pragma unroll
    for (int i = 0; i < 2; i++)
        #pragma unroll
        for (int j = 0; j < 8; j++)
            #pragma unroll
            for (int c = 0; c < 4; c++) acc[i][j][c] = 0.0f;

    const int lr = tid >> 1;
    const int c0 = (tid & 1) * 2;
    const __nv_bfloat16* A0 = A + (size_t)(brow + lr) * K + c0 * 8;
    const __nv_bfloat16* B0 = B + (size_t)(bcol + lr) * K + c0 * 8;
    const uint32_t dA0 = sA + sw_off(lr, c0);
    const uint32_t dA1 = sA + sw_off(lr, c0 + 1);
    const uint32_t dB0 = sB + sw_off(lr, c0);
    const uint32_t dB1 = sB + sw_off(lr, c0 + 1);

    const int m8    = lane >> 3;
    const int rowin = lane & 7;
    int rA[2], cAh = m8 >> 1;
    rA[0] = warp_m * 32 + (m8 & 1) * 8 + rowin;
    rA[1] = rA[0] + 16;
    int rB[4], cBh = m8 & 1;
    #pragma unroll
    for (int np = 0; np < 4; np++)
        rB[np] = warp_n * 64 + np * 16 + (m8 >> 1) * 8 + rowin;

    const int kIters = K / BK;

    #pragma unroll
    for (int s = 0; s < STAGES - 1; s++) {
        int k0 = s * BK;
        uint32_t so = (uint32_t)s * STAGE_BYTES;
        cp16(dA0 + so, A0 + k0);
        cp16(dA1 + so, A0 + k0 + 8);
        cp16(dB0 + so, B0 + k0);
        cp16(dB1 + so, B0 + k0 + 8);
        cp_commit();
    }

    int buf = 0;
    int nbuf = STAGES - 1;
    for (int s = 0; s < kIters; s++) {
        cp_wait<STAGES - 2>();
        __syncthreads();

        if (s + STAGES - 1 < kIters) {
            int k0 = (s + STAGES - 1) * BK;
            uint32_t so = (uint32_t)nbuf * STAGE_BYTES;
            cp16(dA0 + so, A0 + k0);
            cp16(dA1 + so, A0 + k0 + 8);
            cp16(dB0 + so, B0 + k0);
            cp16(dB1 + so, B0 + k0 + 8);
        }
        cp_commit();

        const uint32_t aBuf = sA + (uint32_t)buf * STAGE_BYTES;
        const uint32_t bBuf = sB + (uint32_t)buf * STAGE_BYTES;
        #pragma unroll
        for (int ks = 0; ks < 2; ks++) {
            uint32_t af[2][4];
            #pragma unroll
            for (int mt = 0; mt < 2; mt++)
                ldsm_x4(af[mt], aBuf + sw_off(rA[mt], 2 * ks + cAh));
            #pragma unroll
            for (int np = 0; np < 4; np++) {
                uint32_t bf[4];
                ldsm_x4(bf, bBuf + sw_off(rB[np], 2 * ks + cBh));
                mma_bf16(acc[0][2 * np],     af[0], bf);
                mma_bf16(acc[1][2 * np],     af[1], bf);
                mma_bf16(acc[0][2 * np + 1], af[0], bf + 2);
                mma_bf16(acc[1][2 * np + 1], af[1], bf + 2);
            }
        }
        buf = (buf + 1 == STAGES) ? 0 : buf + 1;
        nbuf = (nbuf + 1 == STAGES) ? 0 : nbuf + 1;
    }

    const int grp = lane >> 2;
    const int t4  = lane & 3;
    #pragma unroll
    for (int mt = 0; mt < 2; mt++) {
        int row = brow + warp_m * 32 + mt * 16 + grp;
        #pragma unroll
        for (int nt = 0; nt < 8; nt++) {
            int col = bcol + warp_n * 64 + nt * 8 + 2 * t4;
            float b0 = bias[col], b1 = bias[col + 1];
            float v0 = acc[mt][nt][0] + b0;
            float v1 = acc[mt][nt][1] + b1;
            float v2 = acc[mt][nt][2] + b0;
            float v3 = acc[mt][nt][3] + b1;
            if (EPI == 1) {
                __nv_bfloat16* O = (__nv_bfloat16*)Cmat;
                __nv_bfloat162 o0 = __floats2bfloat162_rn(gelu_tanh(v0),
                                                          gelu_tanh(v1));
                __nv_bfloat162 o1 = __floats2bfloat162_rn(gelu_tanh(v2),
                                                          gelu_tanh(v3));
                *(__nv_bfloat162*)&O[(size_t)row * N + col]       = o0;
                *(__nv_bfloat162*)&O[(size_t)(row + 8) * N + col] = o1;
            } else if (EPI == 3) {
                __nv_bfloat162 p0 = __floats2bfloat162_rn(v0, v1);
                __nv_bfloat162 p1 = __floats2bfloat162_rn(v2, v3);
                __nv_bfloat16* dst;
                int cc;
                if (col < C)          { dst = qb; cc = col; }
                else if (col < 2 * C) { dst = kb; cc = col - C; }
                else                  { dst = vb; cc = col - 2 * C; }
                *(__nv_bfloat162*)&dst[(size_t)row * C + cc]       = p0;
                *(__nv_bfloat162*)&dst[(size_t)(row + 8) * C + cc] = p1;
            } else {
                if (EPI == 2) {
                    v0 += res[(size_t)row * N + col];
                    v1 += res[(size_t)row * N + col + 1];
                    v2 += res[(size_t)(row + 8) * N + col];
                    v3 += res[(size_t)(row + 8) * N + col + 1];
                }
                float2 o0 = { v0, v1 };
                float2 o1 = { v2, v3 };
                *(float2*)&Cmat[(size_t)row * N + col]       = o0;
                *(float2*)&Cmat[(size_t)(row + 8) * N + col] = o1;
            }
        }
    }
}

// ---------------- CSR build ----------------
__global__ void zero_cnt_kernel(int* __restrict__ cnt) {
    int i = blockIdx.x * blockDim.x + threadIdx.x;
    if (i < L) cnt[i] = 0;
}
__global__ void hist_kernel(const int* __restrict__ row, int* __restrict__ cnt) {
    int e = blockIdx.x * blockDim.x + threadIdx.x;
    if (e < E) atomicAdd(&cnt[row[e]], 1);
}
__global__ void scan_kernel(const int* __restrict__ cnt, int* __restrict__ off,
                            int* __restrict__ cur) {
    __shared__ int ws[32];
    int tid = threadIdx.x;
    int base = tid * 16;
    int loc[16];
    int s = 0;
    #pragma unroll
    for (int i = 0; i < 16; i++) { loc[i] = s; s += cnt[base + i]; }
    int lane = tid & 31, w = tid >> 5;
    int v = s;
    #pragma unroll
    for (int o = 1; o < 32; o <<= 1) {
        int t = __shfl_up_sync(0xffffffffu, v, o);
        if (lane >= o) v += t;
    }
    if (lane == 31) ws[w] = v;
    __syncthreads();
    if (w == 0) {
        int t = ws[lane];
        #pragma unroll
        for (int o = 1; o < 32; o <<= 1) {
            int u = __shfl_up_sync(0xffffffffu, t, o);
            if (lane >= o) t += u;
        }
        ws[lane] = t;
    }
    __syncthreads();
    int excl = v - s + (w > 0 ? ws[w - 1] : 0);
    #pragma unroll
    for (int i = 0; i < 16; i++) {
        off[base + i] = excl + loc[i];
        cur[base + i] = excl + loc[i];
    }
    if (tid == 1023) off[L] = excl + s;
}
__global__ void scatter_kernel(const int* __restrict__ row,
                               int* __restrict__ cur, int* __restrict__ eid) {
    int e = blockIdx.x * blockDim.x + threadIdx.x;
    if (e < E) {
        int p = atomicAdd(&cur[row[e]], 1);
        eid[p] = e;
    }
}

// ---------------- fused edge score + softmax + aggregation ----------------
// Pass 1: 4 lanes per head, 16 elems/lane, vectorized bf16 k loads,
//         2-shuffle reduction. q fragment held in registers.
#define DMAX 64
__global__ __launch_bounds__(128)
void row_attn_kernel(const __nv_bfloat16* __restrict__ qb,
                     const __nv_bfloat16* __restrict__ kb,
                     const __nv_bfloat16* __restrict__ vb,
                     const int* __restrict__ off,
                     const int* __restrict__ eid,
                     const int* __restrict__ col_index,
                     const int* __restrict__ to_col_index,
                     const float* __restrict__ pab,
                     const float* __restrict__ dist,
                     const float* __restrict__ pos,
                     const float* __restrict__ col_pos,
                     const float* __restrict__ Wvec,
                     const float* __restrict__ bvec,
                     __nv_bfloat16* __restrict__ agg) {
    int r = blockIdx.x;
    int tid = threadIdx.x;          // 128
    int lane = tid & 31;
    int w = tid >> 5;               // warp 0..3
    int beg = off[r];
    int deg = off[r + 1] - beg;

    __shared__ float s_den[H];
    __shared__ float s_px[DMAX][H];
    __shared__ float s_mt[DMAX][4];

    if (tid < H) s_den[tid] = 0.0f;
    __syncthreads();

    // q fragment: lane handles head lane>>2, 16 elems at offset lane*16
    float qf[16];
    {
        const uint4* qrow = (const uint4*)(qb + (size_t)r * C);
        uint4 u0 = qrow[lane * 2];
        uint4 u1 = qrow[lane * 2 + 1];
        unpack8(u0, qf);
        unpack8(u1, qf + 8);
    }

    float px0 = pos[r * 3 + 0], px1 = pos[r * 3 + 1], px2 = pos[r * 3 + 2];
    const int myh = lane >> 2;

    // ---- pass 1: scores; den; cache pexp/meta ----
    for (int i0 = w; i0 < deg; i0 += 4) {
        int e = eid[beg + i0];
        int ci = col_index[e];
        const uint4* krow = (const uint4*)(kb + (size_t)ci * C);
        uint4 k0 = krow[lane * 2];
        uint4 k1 = krow[lane * 2 + 1];
        float kf[16];
        unpack8(k0, kf);
        unpack8(k1, kf + 8);
        float s = 0.0f;
        #pragma unroll
        for (int j = 0; j < 16; j++) {
            float d = qf[j] - kf[j];
            s += d * d;
        }
        s += __shfl_xor_sync(0xffffffffu, s, 1);
        s += __shfl_xor_sync(0xffffffffu, s, 2);
        if ((lane & 3) == 0) {
            float val = __expf(-s * 0.125f + pab[(size_t)e * H + myh]);
            atomicAdd(&s_den[myh], val);
            if (i0 < DMAX) s_px[i0][myh] = val;
        }
        if (lane == 1 && i0 < DMAX) {
            int tci = to_col_index[e];
            float dinv = 1.0f / dist[e];
            s_mt[i0][0] = __int_as_float(ci);
            s_mt[i0][1] = (col_pos[tci * 3 + 0] - px0) * dinv;
            s_mt[i0][2] = (col_pos[tci * 3 + 1] - px1) * dinv;
            s_mt[i0][3] = (col_pos[tci * 3 + 2] - px2) * dinv;
        }
    }
    __syncthreads();
    if (tid < H) {
        float d = s_den[tid];
        s_den[tid] = (d == 0.0f) ? 1.0f : 1.0f / d;
    }
    __syncthreads();

    // ---- pass 2: channel-parallel aggregation, 4-edge pipeline, bf16 v ----
    int c0 = tid * 4;
    int hh = c0 >> 6;
    float4 wv0 = *(const float4*)(Wvec + c0);
    float4 wv1 = *(const float4*)(Wvec + C + c0);
    float4 wv2 = *(const float4*)(Wvec + 2 * C + c0);
    float4 bv  = *(const float4*)(bvec + c0);
    float dinvh = s_den[hh];

    float a0 = 0.0f, a1 = 0.0f, a2 = 0.0f, a3 = 0.0f;
    int ncache = deg < DMAX ? deg : DMAX;
    int i = 0;
    for (; i + 4 <= ncache; i += 4) {
        int   ci[4];
        float rx[4], ry[4], rz[4], al[4];
        #pragma unroll
        for (int j = 0; j < 4; j++) {
            ci[j] = __float_as_int(s_mt[i + j][0]);
            rx[j] = s_mt[i + j][1];
            ry[j] = s_mt[i + j][2];
            rz[j] = s_mt[i + j][3];
            al[j] = s_px[i + j][hh] * dinvh;
        }
        uint2 raw[4];
        #pragma unroll
        for (int j = 0; j < 4; j++)
            raw[j] = *(const uint2*)(vb + (size_t)ci[j] * C + c0);
        #pragma unroll
        for (int j = 0; j < 4; j++) {
            float2 f0 = __bfloat1622float2(*(__nv_bfloat162*)&raw[j].x);
            float2 f1 = __bfloat1622float2(*(__nv_bfloat162*)&raw[j].y);
            a0 += al[j] * (f0.x + rx[j] * wv0.x + ry[j] * wv1.x + rz[j] * wv2.x + bv.x);
            a1 += al[j] * (f0.y + rx[j] * wv0.y + ry[j] * wv1.y + rz[j] * wv2.y + bv.y);
            a2 += al[j] * (f1.x + rx[j] * wv0.z + ry[j] * wv1.z + rz[j] * wv2.z + bv.z);
            a3 += al[j] * (f1.y + rx[j] * wv0.w + ry[j] * wv1.w + rz[j] * wv2.w + bv.w);
        }
    }
    for (; i < ncache; i++) {
        int cii = __float_as_int(s_mt[i][0]);
        float rxx = s_mt[i][1], ryy = s_mt[i][2], rzz = s_mt[i][3];
        float all = s_px[i][hh] * dinvh;
        uint2 raw = *(const uint2*)(vb + (size_t)cii * C + c0);
        float2 f0 = __bfloat1622float2(*(__nv_bfloat162*)&raw.x);
        float2 f1 = __bfloat1622float2(*(__nv_bfloat162*)&raw.y);
        a0 += all * (f0.x + rxx * wv0.x + ryy * wv1.x + rzz * wv2.x + bv.x);
        a1 += all * (f0.y + rxx * wv0.y + ryy * wv1.y + rzz * wv2.y + bv.y);
        a2 += all * (f1.x + rxx * wv0.z + ryy * wv1.z + rzz * wv2.z + bv.z);
        a3 += all * (f1.y + rxx * wv0.w + ryy * wv1.w + rzz * wv2.w + bv.w);
    }
    // overflow fallback (deg > DMAX): recompute scores in chunks of 16
    for (int base = DMAX; base < deg; base += 16) {
        int n = min(16, deg - base);
        __syncthreads();
        for (int j = w; j < n; j += 4) {
            int e = eid[beg + base + j];
            int ci = col_index[e];
            const uint4* krow = (const uint4*)(kb + (size_t)ci * C);
            uint4 k0 = krow[lane * 2];
            uint4 k1 = krow[lane * 2 + 1];
            float kf[16];
            unpack8(k0, kf);
            unpack8(k1, kf + 8);
            float s = 0.0f;
            #pragma unroll
            for (int jj = 0; jj < 16; jj++) {
                float d = qf[jj] - kf[jj];
                s += d * d;
            }
            s += __shfl_xor_sync(0xffffffffu, s, 1);
            s += __shfl_xor_sync(0xffffffffu, s, 2);
            if ((lane & 3) == 0)
                s_px[j][myh] = __expf(-s * 0.125f + pab[(size_t)e * H + myh]);
            if (lane == 1) {
                int tci = to_col_index[e];
                float dinv = 1.0f / dist[e];
                s_mt[j][0] = __int_as_float(ci);
                s_mt[j][1] = (col_pos[tci * 3 + 0] - px0) * dinv;
                s_mt[j][2] = (col_pos[tci * 3 + 1] - px1) * dinv;
                s_mt[j][3] = (col_pos[tci * 3 + 2] - px2) * dinv;
            }
        }
        __syncthreads();
        for (int ii = 0; ii < n; ii++) {
            int cii = __float_as_int(s_mt[ii][0]);
            float rxx = s_mt[ii][1], ryy = s_mt[ii][2], rzz = s_mt[ii][3];
            float all = s_px[ii][hh] * dinvh;
            uint2 raw = *(const uint2*)(vb + (size_t)cii * C + c0);
            float2 f0 = __bfloat1622float2(*(__nv_bfloat162*)&raw.x);
            float2 f1 = __bfloat1622float2(*(__nv_bfloat162*)&raw.y);
            a0 += all * (f0.x + rxx * wv0.x + ryy * wv1.x + rzz * wv2.x + bv.x);
            a1 += all * (f0.y + rxx * wv0.y + ryy * wv1.y + rzz * wv2.y + bv.y);
            a2 += all * (f1.x + rxx * wv0.z + ryy * wv1.z + rzz * wv2.z + bv.z);
            a3 += all * (f1.y + rxx * wv0.w + ryy * wv1.w + rzz * wv2.w + bv.w);
        }
    }

    __nv_bfloat162 o0 = __floats2bfloat162_rn(a0, a1);
    __nv_bfloat162 o1 = __floats2bfloat162_rn(a2, a3);
    __nv_bfloat162* ar = (__nv_bfloat162*)(agg + (size_t)r * C);
    ar[tid * 2]     = o0;
    ar[tid * 2 + 1] = o1;
}

// ---------------- launcher ----------------
extern "C" void kernel_launch(void* const* d_in, const int* in_sizes, int n_in,
                              void* d_out, int out_size) {
    const float* x        = (const float*)d_in[0];
    const int*   row_idx  = (const int*)  d_in[1];
    const int*   col_idx  = (const int*)  d_in[2];
    const int*   tcol_idx = (const int*)  d_in[3];
    const float* pab      = (const float*)d_in[5];
    const float* dist     = (const float*)d_in[6];
    const float* pos      = (const float*)d_in[7];
    const float* col_pos  = (const float*)d_in[8];
    const float* ln1_g    = (const float*)d_in[9];
    const float* ln1_b    = (const float*)d_in[10];
    const float* ln2_g    = (const float*)d_in[11];
    const float* ln2_b    = (const float*)d_in[12];
    const float* Wq       = (const float*)d_in[13];
    const float* bq       = (const float*)d_in[14];
    const float* Wk       = (const float*)d_in[15];
    const float* bk       = (const float*)d_in[16];
    const float* Wv       = (const float*)d_in[17];
    const float* bv       = (const float*)d_in[18];
    const float* Wvec     = (const float*)d_in[19];
    const float* bvec     = (const float*)d_in[20];
    const float* Wo       = (const float*)d_in[21];
    const float* bo       = (const float*)d_in[22];
    const float* W1       = (const float*)d_in[23];
    const float* b1       = (const float*)d_in[24];
    const float* W2       = (const float*)d_in[25];
    const float* b2       = (const float*)d_in[26];
    float* out = (float*)d_out;

    static __nv_bfloat16 *zp = nullptr, *qbp, *kbp, *vbp, *aggp, *z2p, *hidp,
                         *wqkvp, *wop, *w1p, *w2p;
    static float *x1p, *bqkvp;
    static int *cntp, *offp, *curp, *eidp;
    static cudaStream_t side = nullptr, side2 = nullptr;
    static cudaEvent_t evFork, evJoin, evLn;
    if (!zp) {
        cudaGetSymbolAddress((void**)&zp,    g_z);
        cudaGetSymbolAddress((void**)&qbp,   g_qb);
        cudaGetSymbolAddress((void**)&kbp,   g_kb);
        cudaGetSymbolAddress((void**)&vbp,   g_vb);
        cudaGetSymbolAddress((void**)&aggp,  g_agg);
        cudaGetSymbolAddress((void**)&x1p,   g_x1);
        cudaGetSymbolAddress((void**)&z2p,   g_z2);
        cudaGetSymbolAddress((void**)&hidp,  g_hid);
        cudaGetSymbolAddress((void**)&wqkvp, g_wqkv);
        cudaGetSymbolAddress((void**)&bqkvp, g_bqkv);
        cudaGetSymbolAddress((void**)&wop,   g_wo);
        cudaGetSymbolAddress((void**)&w1p,   g_w1);
        cudaGetSymbolAddress((void**)&w2p,   g_w2);
        cudaGetSymbolAddress((void**)&cntp,  g_cnt);
        cudaGetSymbolAddress((void**)&offp,  g_off);
        cudaGetSymbolAddress((void**)&curp,  g_cur);
        cudaGetSymbolAddress((void**)&eidp,  g_eid);
        cudaFuncSetAttribute(tgemm_kernel<1>,
            cudaFuncAttributeMaxDynamicSharedMemorySize, SMEM_BYTES);
        cudaFuncSetAttribute(tgemm_kernel<2>,
            cudaFuncAttributeMaxDynamicSharedMemorySize, SMEM_BYTES);
        cudaFuncSetAttribute(tgemm_kernel<3>,
            cudaFuncAttributeMaxDynamicSharedMemorySize, SMEM_BYTES);
        cudaStreamCreateWithFlags(&side, cudaStreamNonBlocking);
        cudaStreamCreateWithFlags(&side2, cudaStreamNonBlocking);
        cudaEventCreateWithFlags(&evFork, cudaEventDisableTiming);
        cudaEventCreateWithFlags(&evJoin, cudaEventDisableTiming);
        cudaEventCreateWithFlags(&evLn,   cudaEventDisableTiming);
    }

    // ---- fork ----
    cudaEventRecord(evFork, 0);
    cudaStreamWaitEvent(side, evFork, 0);
    cudaStreamWaitEvent(side2, evFork, 0);

    // side: CSR build (only feeds row_attn)
    zero_cnt_kernel<<<(L + 255) / 256, 256, 0, side>>>(cntp);
    hist_kernel<<<(E + 255) / 256, 256, 0, side>>>(row_idx, cntp);
    scan_kernel<<<1, 1024, 0, side>>>(cntp, offp, curp);
    scatter_kernel<<<(E + 255) / 256, 256, 0, side>>>(row_idx, curp, eidp);
    cudaEventRecord(evJoin, side);

    // side2: LN1 (needs x only)
    ln_kernel<<<L, 128, 0, side2>>>(x, ln1_g, ln1_b, zp);
    cudaEventRecord(evLn, side2);

    // main: weight transposes (concurrent with LN1)
    transpose_all_kernel<<<dim3(32, 32, 6), dim3(32, 8)>>>(
        Wq, Wk, Wv, Wo, W1, W2, bq, bk, bv, wqkvp, wop, w1p, w2p, bqkvp);

    // QKV needs z (LN1) + transposed weights; writes bf16 q/k/v planes only
    cudaStreamWaitEvent(0, evLn, 0);
    dim3 gqkv(NQKV / BN, L / BM);
    tgemm_kernel<3><<<gqkv, 256, SMEM_BYTES>>>(zp, wqkvp, bqkvp, nullptr,
                                               nullptr, qbp, kbp, vbp,
                                               L, NQKV, C);

    // join CSR before row_attn
    cudaStreamWaitEvent(0, evJoin, 0);
    row_attn_kernel<<<L, 128>>>(qbp, kbp, vbp, offp, eidp, col_idx, tcol_idx,
                                pab, dist, pos, col_pos, Wvec, bvec, aggp);

    dim3 g512(C / BN, L / BM);
    tgemm_kernel<2><<<g512, 256, SMEM_BYTES>>>(aggp, wop, bo, x, x1p,
                                               nullptr, nullptr, nullptr,
                                               L, C, C);

    ln_kernel<<<L, 128>>>(x1p, ln2_g, ln2_b, z2p);

    dim3 g1024(HID / BN, L / BM);
    tgemm_kernel<1><<<g1024, 256, SMEM_BYTES>>>(z2p, w1p, b1, nullptr,
                                                (float*)hidp,
                                                nullptr, nullptr, nullptr,
                                                L, HID, C);

    tgemm_kernel<2><<<g512, 256, SMEM_BYTES>>>(hidp, w2p, b2, x1p, out,
                                               nullptr, nullptr, nullptr,
                                               L, C, HID);
}